// round 3
// baseline (speedup 1.0000x reference)
#include <cuda_runtime.h>
#include <math.h>

#define LSEQ 1024
#define DMODEL 2048
#define NHQ 16
#define NHK 8
#define DHEAD 128
#define NCHUNK 16
#define CLEN 64
#define NITER 30
#define RIDGE_C 0.02f

typedef unsigned long long u64;

// ---------------- packed f32x2 helpers (sm_100+) ----------------
__device__ __forceinline__ u64 dup2(float a) {
    u64 r; asm("mov.b64 %0, {%1, %1};" : "=l"(r) : "f"(a)); return r;
}
__device__ __forceinline__ void ffma2(u64& c, u64 a, u64 b) {
    asm("fma.rn.f32x2 %0, %1, %2, %0;" : "+l"(c) : "l"(a), "l"(b));
}
__device__ __forceinline__ u64 ffma2r(u64 a, u64 b, u64 c) {
    u64 r; asm("fma.rn.f32x2 %0, %1, %2, %3;" : "=l"(r) : "l"(a), "l"(b), "l"(c)); return r;
}
__device__ __forceinline__ u64 mul2(u64 a, u64 b) {
    u64 r; asm("mul.rn.f32x2 %0, %1, %2;" : "=l"(r) : "l"(a), "l"(b)); return r;
}
__device__ __forceinline__ u64 add2(u64 a, u64 b) {
    u64 r; asm("add.rn.f32x2 %0, %1, %2;" : "=l"(r) : "l"(a), "l"(b)); return r;
}
__device__ __forceinline__ float2 unpk(u64 v) {
    float2 f; asm("mov.b64 {%0, %1}, %2;" : "=f"(f.x), "=f"(f.y) : "l"(v)); return f;
}

// ---------------- device scratch ----------------
__device__ float g_pq[LSEQ * 2048];
__device__ float g_pk[LSEQ * 1024];
__device__ float g_pv[LSEQ * 1024];
__device__ float g_q [LSEQ * 2048];
__device__ float g_k [LSEQ * 1024];
__device__ float g_v [LSEQ * 1024];
__device__ float g_gp[LSEQ * 2048];
__device__ float g_glog [LSEQ * NHQ];
__device__ float g_beta [LSEQ * NHQ];
__device__ float g_alpha[LSEQ * NHQ];
__device__ float g_cs[NHQ * NCHUNK * CLEN];
__device__ float g_G [NHQ * NCHUNK];
__device__ float g_dgv[NHQ * NCHUNK];
__device__ float g_dH[NHQ * NCHUNK * DHEAD * DHEAD];
__device__ float g_dB[NHQ * NCHUNK * DHEAD * DHEAD];
__device__ float g_H0[NHQ * NCHUNK * DHEAD * DHEAD];
__device__ float g_B0[NHQ * NCHUNK * DHEAD * DHEAD];
__device__ float g_X [NHQ * NCHUNK * DHEAD * DHEAD];
__device__ float g_on[LSEQ * 2048];

// ---------------- GEMM core: 64x128 tile, FFMA2 inner ----------------
// C[bm:bm+64, bn:bn+128] = A[bm:,:K] @ B[:K, bn:], A stride K, B/C stride N.
__device__ __forceinline__ void gemm_core64(
    const float* __restrict__ A, const float* __restrict__ B, float* __restrict__ C,
    int N, int K, int bm, int bn, float (*As)[64], float (*Bs)[128])
{
    const int tid = threadIdx.x;
    const int ty = tid >> 4, tx = tid & 15;     // ty 0..15 (4 rows), tx 0..15 (8 cols)
    const int rb = ty * 4, cb = tx * 8;

    u64 acc2[4][4];
#pragma unroll
    for (int i = 0; i < 4; i++)
#pragma unroll
        for (int j = 0; j < 4; j++) acc2[i][j] = 0ULL;

    const int arow = tid >> 2;          // 0..63
    const int ak4 = (tid & 3) * 4;      // 0,4,8,12
    const int bcol = (tid & 31) * 4;    // 0..124
    const int bkk = tid >> 5;           // 0..7

    for (int k0 = 0; k0 < K; k0 += 16) {
        {
            float4 va = *(const float4*)(A + (size_t)(bm + arow) * K + k0 + ak4);
            As[ak4 + 0][arow] = va.x; As[ak4 + 1][arow] = va.y;
            As[ak4 + 2][arow] = va.z; As[ak4 + 3][arow] = va.w;
        }
#pragma unroll
        for (int it = 0; it < 2; it++) {
            int kk = bkk + it * 8;
            *(float4*)&Bs[kk][bcol] = *(const float4*)(B + (size_t)(k0 + kk) * N + bn + bcol);
        }
        __syncthreads();
#pragma unroll
        for (int kk = 0; kk < 16; kk++) {
            float4 a = *(const float4*)&As[kk][rb];
            ulonglong2 b0 = *(const ulonglong2*)&Bs[kk][cb];
            ulonglong2 b1 = *(const ulonglong2*)&Bs[kk][cb + 4];
            u64 b2[4] = {b0.x, b0.y, b1.x, b1.y};
            float aa[4] = {a.x, a.y, a.z, a.w};
#pragma unroll
            for (int i = 0; i < 4; i++) {
                u64 ad = dup2(aa[i]);
#pragma unroll
                for (int j = 0; j < 4; j++) ffma2(acc2[i][j], ad, b2[j]);
            }
        }
        __syncthreads();
    }
#pragma unroll
    for (int i = 0; i < 4; i++) {
        float2 p0 = unpk(acc2[i][0]), p1 = unpk(acc2[i][1]);
        float2 p2 = unpk(acc2[i][2]), p3 = unpk(acc2[i][3]);
        float4* cp = (float4*)(C + (size_t)(bm + rb + i) * N + bn + cb);
        cp[0] = make_float4(p0.x, p0.y, p1.x, p1.y);
        cp[1] = make_float4(p2.x, p2.y, p3.x, p3.y);
    }
}

// final output projection GEMM
__global__ __launch_bounds__(256, 2) void sgemm64(
    const float* __restrict__ A, const float* __restrict__ B,
    float* __restrict__ C, int N, int K)
{
    __shared__ float As[16][64];
    __shared__ float Bs[16][128];
    gemm_core64(A, B, C, N, K, blockIdx.y * 64, blockIdx.x * 128, As, Bs);
}

// fused q/k/v/g projection GEMM: x @ {Wq, Wk, Wv, Wg} in one launch
__global__ __launch_bounds__(256, 2) void proj_kernel(
    const float* __restrict__ x,
    const float* __restrict__ Wq, const float* __restrict__ Wk,
    const float* __restrict__ Wv, const float* __restrict__ Wg)
{
    __shared__ float As[16][64];
    __shared__ float Bs[16][128];
    const int bx = blockIdx.x;
    const float* B; float* C; int N, bn;
    if (bx < 16)      { B = Wq; C = g_pq; N = 2048; bn = bx * 128; }
    else if (bx < 24) { B = Wk; C = g_pk; N = 1024; bn = (bx - 16) * 128; }
    else if (bx < 32) { B = Wv; C = g_pv; N = 1024; bn = (bx - 24) * 128; }
    else              { B = Wg; C = g_gp; N = 2048; bn = (bx - 32) * 128; }
    gemm_core64(x, B, C, N, DMODEL, blockIdx.y * 64, bn, As, Bs);
}

// ---------------- gates: x@{Wa,Wb,Walpha} + nonlinearities ----------------
__global__ __launch_bounds__(256) void gates_kernel(
    const float* __restrict__ x,
    const float* __restrict__ Wa, const float* __restrict__ A_log,
    const float* __restrict__ dt_bias,
    const float* __restrict__ Wb, const float* __restrict__ bb,
    const float* __restrict__ Wal, const float* __restrict__ bal)
{
    __shared__ float xs[DMODEL];
    const int t = blockIdx.x;
    for (int i = threadIdx.x; i < DMODEL; i += 256)
        xs[i] = x[(size_t)t * DMODEL + i];
    __syncthreads();
    const int warp = threadIdx.x >> 5, lane = threadIdx.x & 31;
    for (int o = warp; o < 48; o += 8) {
        int grp = o >> 4, h = o & 15;
        const float* W = (grp == 0) ? Wa : ((grp == 1) ? Wb : Wal);
        float s = 0.f;
        for (int d = lane; d < DMODEL; d += 32) s += xs[d] * W[d * NHQ + h];
#pragma unroll
        for (int off = 16; off > 0; off >>= 1)
            s += __shfl_xor_sync(0xFFFFFFFFu, s, off);
        if (lane == 0) {
            if (grp == 0) {
                float z = s + dt_bias[h];
                float sp = (z > 20.f) ? z : log1pf(expf(z));
                g_glog[t * NHQ + h] = -expf(A_log[h]) * sp;
            } else if (grp == 1) {
                g_beta[t * NHQ + h] = 1.f / (1.f + expf(-(s + bb[h])));
            } else {
                g_alpha[t * NHQ + h] = 1.f / (1.f + expf(-(s + bal[h])));
            }
        }
    }
}

// ---------------- causal depthwise conv(4) + silu ----------------
__global__ void conv_kernel(const float* __restrict__ in, const float* __restrict__ w,
                            float* __restrict__ out, int C, float scale)
{
    int idx = blockIdx.x * blockDim.x + threadIdx.x;
    if (idx >= LSEQ * C) return;
    int t = idx / C, c = idx % C;
    float s = 0.f;
#pragma unroll
    for (int j = 0; j < 4; j++) {
        int tj = t - 3 + j;
        if (tj >= 0) s += in[(size_t)tj * C + c] * w[c * 4 + j];
    }
    float y = s / (1.f + expf(-s));
    out[idx] = y * scale;
}

// ---------------- per-chunk inclusive cumsum of glog ----------------
__global__ void cs_kernel()
{
    int id = threadIdx.x;            // 256 = NHQ*NCHUNK
    int h = id >> 4, n = id & 15;
    float s = 0.f;
    for (int c = 0; c < CLEN; c++) {
        s += g_glog[(n * CLEN + c) * NHQ + h];
        g_cs[(h * NCHUNK + n) * CLEN + c] = s;
    }
    g_G[h * NCHUNK + n] = s;
    g_dgv[h * NCHUNK + n] = expf(s);
}

// ---------------- dH / dB gram increments, one block per (h,n) ----------------
__global__ __launch_bounds__(256, 1) void dhb_kernel()
{
    extern __shared__ float sm[];
    float* ks = sm;                  // 64*128
    float* vs = sm + CLEN * DHEAD;   // 64*128
    float* ws = sm + 2 * CLEN * DHEAD;
    const int mat = blockIdx.x;      // h*16+n
    const int h = mat >> 4, n = mat & 15, hk = h >> 1;
    const int tid = threadIdx.x;
    for (int i = tid; i < CLEN * DHEAD; i += 256) {
        int c = i >> 7, d = i & 127;
        int t = n * CLEN + c;
        ks[i] = g_k[t * 1024 + hk * DHEAD + d];
        vs[i] = g_v[t * 1024 + hk * DHEAD + d];
    }
    if (tid < CLEN) {
        float G = g_G[mat];
        float cs = g_cs[mat * CLEN + tid];
        ws[tid] = expf(G - cs) * g_beta[(n * CLEN + tid) * NHQ + h];
    }
    __syncthreads();
    const int ty = tid >> 4, tx = tid & 15;
    u64 dH2[8][4], dB2[8][4];
#pragma unroll
    for (int i = 0; i < 8; i++)
#pragma unroll
        for (int j = 0; j < 4; j++) { dH2[i][j] = 0ULL; dB2[i][j] = 0ULL; }

    for (int c = 0; c < CLEN; c++) {
        float w = ws[c];
        float ki[8];
        *(float4*)&ki[0] = *(const float4*)&ks[c * 128 + ty * 8];
        *(float4*)&ki[4] = *(const float4*)&ks[c * 128 + ty * 8 + 4];
        ulonglong2 k0 = *(const ulonglong2*)&ks[c * 128 + tx * 8];
        ulonglong2 k1 = *(const ulonglong2*)&ks[c * 128 + tx * 8 + 4];
        ulonglong2 v0 = *(const ulonglong2*)&vs[c * 128 + tx * 8];
        ulonglong2 v1 = *(const ulonglong2*)&vs[c * 128 + tx * 8 + 4];
        u64 kj2[4] = {k0.x, k0.y, k1.x, k1.y};
        u64 vj2[4] = {v0.x, v0.y, v1.x, v1.y};
#pragma unroll
        for (int i = 0; i < 8; i++) {
            u64 wk = dup2(w * ki[i]);
#pragma unroll
            for (int j = 0; j < 4; j++) {
                ffma2(dH2[i][j], wk, kj2[j]);
                ffma2(dB2[i][j], wk, vj2[j]);
            }
        }
    }
    size_t base = (size_t)mat * DHEAD * DHEAD;
#pragma unroll
    for (int i = 0; i < 8; i++) {
        size_t off = base + (ty * 8 + i) * 128 + tx * 8;
        float2 h0 = unpk(dH2[i][0]), h1 = unpk(dH2[i][1]);
        float2 h2 = unpk(dH2[i][2]), h3 = unpk(dH2[i][3]);
        *(float4*)&g_dH[off]     = make_float4(h0.x, h0.y, h1.x, h1.y);
        *(float4*)&g_dH[off + 4] = make_float4(h2.x, h2.y, h3.x, h3.y);
        float2 b0 = unpk(dB2[i][0]), b1 = unpk(dB2[i][1]);
        float2 b2 = unpk(dB2[i][2]), b3 = unpk(dB2[i][3]);
        *(float4*)&g_dB[off]     = make_float4(b0.x, b0.y, b1.x, b1.y);
        *(float4*)&g_dB[off + 4] = make_float4(b2.x, b2.y, b3.x, b3.y);
    }
}

// ---------------- inter-chunk scan (elementwise over (h,d,e)) ----------------
__global__ void scan_kernel()
{
    int idx = blockIdx.x * blockDim.x + threadIdx.x;   // 16 * 16384
    int h = idx >> 14;
    int rem = idx & 16383;
    float hc = 0.f, bc = 0.f;
    for (int n = 0; n < NCHUNK; n++) {
        size_t off = (size_t)(h * NCHUNK + n) * 16384 + rem;
        g_H0[off] = hc;
        g_B0[off] = bc;
        float g = g_dgv[h * NCHUNK + n];
        hc = g * hc + g_dH[off];
        bc = g * bc + g_dB[off];
    }
}

// ---------------- Chebyshev solve, one block (512 thr) per matrix ----------------
__global__ __launch_bounds__(512, 1) void cheb_kernel()
{
    extern __shared__ float sm[];
    float* Ash = sm;             // 128*128
    float* dsh = sm + 16384;     // dvec
    float* rsh = sm + 32768;     // r
    __shared__ float red[128];
    __shared__ float s_lmax;
    const int mat = blockIdx.x;
    const int tid = threadIdx.x;
    const float* H0 = g_H0 + (size_t)mat * 16384;
    const float* B0p = g_B0 + (size_t)mat * 16384;

    for (int i = tid; i < 16384; i += 512) {
        float v = H0[i];
        if ((i >> 7) == (i & 127)) v += RIDGE_C;
        Ash[i] = v;
        rsh[i] = B0p[i];
    }
    __syncthreads();
    if (tid < 128) red[tid] = Ash[tid * 129];
    __syncthreads();
    for (int s = 64; s > 0; s >>= 1) {
        if (tid < s) red[tid] += red[tid + s];
        __syncthreads();
    }
    if (tid == 0) s_lmax = red[0];
    __syncthreads();

    const float lmax = s_lmax;
    const float theta = (lmax + RIDGE_C) * 0.5f;
    const float delta = (lmax - RIDGE_C) * 0.5f;
    const float sigma1 = theta / delta;
    float rho = 1.f / sigma1;
    const float inv_theta = 1.f / theta;
    for (int i = tid; i < 16384; i += 512) dsh[i] = rsh[i] * inv_theta;
    __syncthreads();

    const int ty = tid >> 4, tx = tid & 15;   // ty 0..31 (4 rows), tx 0..15 (8 cols)
    const int rb = ty * 4, cb = tx * 8;
    u64 x2[4][4];
#pragma unroll
    for (int i = 0; i < 4; i++)
#pragma unroll
        for (int j = 0; j < 4; j++) x2[i][j] = 0ULL;

    const u64 neg1 = dup2(-1.f);

    for (int it = 0; it < NITER; it++) {
        u64 acc2[4][4];
#pragma unroll
        for (int i = 0; i < 4; i++)
#pragma unroll
            for (int j = 0; j < 4; j++) acc2[i][j] = 0ULL;
        // acc = A @ dvec  (A symmetric: A[rb+i][e] = A[e][rb+i] -> contiguous row e)
#pragma unroll 2
        for (int e = 0; e < 128; e++) {
            float4 a = *(const float4*)&Ash[e * 128 + rb];
            ulonglong2 d0 = *(const ulonglong2*)&dsh[e * 128 + cb];
            ulonglong2 d1 = *(const ulonglong2*)&dsh[e * 128 + cb + 4];
            u64 b2[4] = {d0.x, d0.y, d1.x, d1.y};
            float aa[4] = {a.x, a.y, a.z, a.w};
#pragma unroll
            for (int i = 0; i < 4; i++) {
                u64 ad = dup2(aa[i]);
#pragma unroll
                for (int j = 0; j < 4; j++) ffma2(acc2[i][j], ad, b2[j]);
            }
        }
        // x += dvec (own tile)
#pragma unroll
        for (int i = 0; i < 4; i++) {
            const u64* dp = (const u64*)&dsh[(rb + i) * 128 + cb];
#pragma unroll
            for (int j = 0; j < 4; j++) x2[i][j] = add2(x2[i][j], dp[j]);
        }
        __syncthreads();
        float rho_n = 1.f / (2.f * sigma1 - rho);
        const u64 c1 = dup2(rho_n * rho);
        const u64 c2 = dup2(2.f * rho_n / delta);
#pragma unroll
        for (int i = 0; i < 4; i++) {
            u64* rp = (u64*)&rsh[(rb + i) * 128 + cb];
            u64* dp = (u64*)&dsh[(rb + i) * 128 + cb];
#pragma unroll
            for (int j = 0; j < 4; j++) {
                u64 r2 = ffma2r(acc2[i][j], neg1, rp[j]);   // r - A@d
                rp[j] = r2;
                dp[j] = ffma2r(c2, r2, mul2(c1, dp[j]));    // c1*d + c2*r
            }
        }
        rho = rho_n;
        __syncthreads();
    }
    size_t base = (size_t)mat * 16384;
#pragma unroll
    for (int i = 0; i < 4; i++) {
        size_t off = base + (rb + i) * 128 + cb;
        float2 p0 = unpk(x2[i][0]), p1 = unpk(x2[i][1]);
        float2 p2 = unpk(x2[i][2]), p3 = unpk(x2[i][3]);
        *(float4*)&g_X[off]     = make_float4(p0.x, p0.y, p1.x, p1.y);
        *(float4*)&g_X[off + 4] = make_float4(p2.x, p2.y, p3.x, p3.y);
    }
}

// ---- o = exp(cs)*(q@X) + intra + alpha*v, fused gated RMSNorm ----
__global__ __launch_bounds__(256, 1) void o_kernel(const float* __restrict__ norm_w)
{
    extern __shared__ float sm[];
    float* qs = sm;               // 64*128
    float* ks = sm + 8192;        // 64*128
    float* vs = sm + 16384;       // 64*128
    float* Xs = sm + 24576;       // 128*128
    float* Ss = sm + 40960;       // 64*64
    __shared__ float csh[CLEN], bsh[CLEN], ash[CLEN];
    const int mat = blockIdx.x;
    const int h = mat >> 4, n = mat & 15, hk = h >> 1;
    const int tid = threadIdx.x;

    for (int i = tid; i < CLEN * DHEAD; i += 256) {
        int c = i >> 7, d = i & 127;
        int t = n * CLEN + c;
        qs[i] = g_q[t * 2048 + h * DHEAD + d];
        ks[i] = g_k[t * 1024 + hk * DHEAD + d];
        vs[i] = g_v[t * 1024 + hk * DHEAD + d];
    }
    for (int i = tid; i < 16384; i += 256) Xs[i] = g_X[(size_t)mat * 16384 + i];
    if (tid < CLEN) {
        csh[tid] = g_cs[mat * CLEN + tid];
        int t = n * CLEN + tid;
        bsh[tid] = g_beta[t * NHQ + h];
        ash[tid] = g_alpha[t * NHQ + h];
    }
    __syncthreads();

    // masked gated scores
    for (int idx = tid; idx < 4096; idx += 256) {
        int c = idx >> 6, j = idx & 63;
        float s = 0.f;
        if (j <= c) {
            const float* qr = &qs[c * 128];
            const float* kr = &ks[j * 128];
            for (int d = 0; d < 128; d += 4) {
                s += qr[d] * kr[d] + qr[d + 1] * kr[d + 1]
                   + qr[d + 2] * kr[d + 2] + qr[d + 3] * kr[d + 3];
            }
            s *= expf(csh[c] - csh[j]) * bsh[j];
        }
        Ss[idx] = s;
    }
    __syncthreads();

    const int ty = tid >> 5, tx = tid & 31;   // 8 warps x 32 lanes
    const int r0 = ty * 8, f0 = tx * 4;
    u64 acc2[8][2];
#pragma unroll
    for (int i = 0; i < 8; i++) { acc2[i][0] = 0ULL; acc2[i][1] = 0ULL; }

    // inter: q @ X
    for (int d = 0; d < 128; d++) {
        ulonglong2 bb = *(const ulonglong2*)&Xs[d * 128 + f0];
#pragma unroll
        for (int i = 0; i < 8; i++) {
            u64 ad = dup2(qs[(r0 + i) * 128 + d]);
            ffma2(acc2[i][0], ad, bb.x);
            ffma2(acc2[i][1], ad, bb.y);
        }
    }
#pragma unroll
    for (int i = 0; i < 8; i++) {
        u64 e = dup2(expf(csh[r0 + i]));
        acc2[i][0] = mul2(acc2[i][0], e);
        acc2[i][1] = mul2(acc2[i][1], e);
    }
    // intra: S @ v
    for (int jc = 0; jc < CLEN; jc++) {
        ulonglong2 vv = *(const ulonglong2*)&vs[jc * 128 + f0];
#pragma unroll
        for (int i = 0; i < 8; i++) {
            u64 sd = dup2(Ss[(r0 + i) * 64 + jc]);
            ffma2(acc2[i][0], sd, vv.x);
            ffma2(acc2[i][1], sd, vv.y);
        }
    }
    // alpha*v, then fused gated RMSNorm + store
    float4 nw = *(const float4*)(norm_w + f0);
#pragma unroll
    for (int i = 0; i < 8; i++) {
        int c = r0 + i;
        int t = n * CLEN + c;
        u64 al = dup2(ash[c]);
        ulonglong2 vv = *(const ulonglong2*)&vs[c * 128 + f0];
        u64 o0 = ffma2r(al, vv.x, acc2[i][0]);
        u64 o1 = ffma2r(al, vv.y, acc2[i][1]);
        float2 p0 = unpk(o0), p1 = unpk(o1);
        // warp-wide sum of squares for this row (row's 128 dims live in this warp)
        float ss = p0.x * p0.x + p0.y * p0.y + p1.x * p1.x + p1.y * p1.y;
#pragma unroll
        for (int off = 16; off > 0; off >>= 1)
            ss += __shfl_xor_sync(0xFFFFFFFFu, ss, off);
        float rms = rsqrtf(ss * (1.f / 128.f) + 1e-6f);
        float4 gw = *(const float4*)(&g_gp[(size_t)t * 2048 + h * 128 + f0]);
        float4 o;
        o.x = p0.x * rms * nw.x * (gw.x / (1.f + expf(-gw.x)));
        o.y = p0.y * rms * nw.y * (gw.y / (1.f + expf(-gw.y)));
        o.z = p1.x * rms * nw.z * (gw.z / (1.f + expf(-gw.z)));
        o.w = p1.y * rms * nw.w * (gw.w / (1.f + expf(-gw.w)));
        *(float4*)&g_on[(size_t)t * 2048 + h * DHEAD + f0] = o;
    }
}

// ---------------- launch ----------------
extern "C" void kernel_launch(void* const* d_in, const int* in_sizes, int n_in,
                              void* d_out, int out_size)
{
    const float* x      = (const float*)d_in[0];
    const float* Wq     = (const float*)d_in[1];
    const float* Wk     = (const float*)d_in[2];
    const float* Wv     = (const float*)d_in[3];
    const float* conv_q = (const float*)d_in[4];
    const float* conv_k = (const float*)d_in[5];
    const float* conv_v = (const float*)d_in[6];
    const float* Wa     = (const float*)d_in[7];
    const float* A_log  = (const float*)d_in[8];
    const float* dt_b   = (const float*)d_in[9];
    const float* Wb     = (const float*)d_in[10];
    const float* bb     = (const float*)d_in[11];
    const float* Wal    = (const float*)d_in[12];
    const float* bal    = (const float*)d_in[13];
    const float* Wg     = (const float*)d_in[14];
    const float* norm_w = (const float*)d_in[15];
    const float* Wo     = (const float*)d_in[16];
    float* out = (float*)d_out;

    float *pq, *pk, *pv, *qb, *kb, *vb, *on;
    cudaGetSymbolAddress((void**)&pq, g_pq);
    cudaGetSymbolAddress((void**)&pk, g_pk);
    cudaGetSymbolAddress((void**)&pv, g_pv);
    cudaGetSymbolAddress((void**)&qb, g_q);
    cudaGetSymbolAddress((void**)&kb, g_k);
    cudaGetSymbolAddress((void**)&vb, g_v);
    cudaGetSymbolAddress((void**)&on, g_on);

    cudaFuncSetAttribute(dhb_kernel, cudaFuncAttributeMaxDynamicSharedMemorySize, 65792);
    cudaFuncSetAttribute(cheb_kernel, cudaFuncAttributeMaxDynamicSharedMemorySize, 196608);
    cudaFuncSetAttribute(o_kernel, cudaFuncAttributeMaxDynamicSharedMemorySize, 180224);

    // 1. fused projections (q,k,v,g) in one launch
    proj_kernel<<<dim3(48, 16), 256>>>(x, Wq, Wk, Wv, Wg);
    // 2. gates
    gates_kernel<<<1024, 256>>>(x, Wa, A_log, dt_b, Wb, bb, Wal, bal);
    // 3. convs (+silu; q gets d^-0.5)
    conv_kernel<<<8192, 256>>>(pq, conv_q, qb, 2048, 0.08838834764831843f);
    conv_kernel<<<4096, 256>>>(pk, conv_k, kb, 1024, 1.f);
    conv_kernel<<<4096, 256>>>(pv, conv_v, vb, 1024, 1.f);
    // 4. cumsum
    cs_kernel<<<1, 256>>>();
    // 5. gram increments
    dhb_kernel<<<256, 256, 65792>>>();
    // 6. chunk scan
    scan_kernel<<<1024, 256>>>();
    // 7. chebyshev solve (512 threads/matrix)
    cheb_kernel<<<256, 512, 196608>>>();
    // 8. inter + intra + alpha + gated RMSNorm
    o_kernel<<<256, 256, 180224>>>(norm_w);
    // 9. output projection
    sgemm64<<<dim3(16, 16), 256>>>(on, Wo, out, 2048, 2048);
}

// round 4
// speedup vs baseline: 1.4554x; 1.4554x over previous
#include <cuda_runtime.h>
#include <math.h>

#define LSEQ 1024
#define DMODEL 2048
#define NHQ 16
#define NHK 8
#define DHEAD 128
#define NCHUNK 16
#define CLEN 64
#define NITER 30
#define RIDGE_C 0.02f

typedef unsigned long long u64;

// ---------------- packed f32x2 helpers (sm_100+) ----------------
__device__ __forceinline__ u64 dup2(float a) {
    u64 r; asm("mov.b64 %0, {%1, %1};" : "=l"(r) : "f"(a)); return r;
}
__device__ __forceinline__ void ffma2(u64& c, u64 a, u64 b) {
    asm("fma.rn.f32x2 %0, %1, %2, %0;" : "+l"(c) : "l"(a), "l"(b));
}
__device__ __forceinline__ u64 ffma2r(u64 a, u64 b, u64 c) {
    u64 r; asm("fma.rn.f32x2 %0, %1, %2, %3;" : "=l"(r) : "l"(a), "l"(b), "l"(c)); return r;
}
__device__ __forceinline__ u64 mul2(u64 a, u64 b) {
    u64 r; asm("mul.rn.f32x2 %0, %1, %2;" : "=l"(r) : "l"(a), "l"(b)); return r;
}
__device__ __forceinline__ u64 add2(u64 a, u64 b) {
    u64 r; asm("add.rn.f32x2 %0, %1, %2;" : "=l"(r) : "l"(a), "l"(b)); return r;
}
__device__ __forceinline__ float2 unpk(u64 v) {
    float2 f; asm("mov.b64 {%0, %1}, %2;" : "=f"(f.x), "=f"(f.y) : "l"(v)); return f;
}

// ---------------- device scratch ----------------
__device__ float g_pq[LSEQ * 2048];
__device__ float g_pk[LSEQ * 1024];
__device__ float g_pv[LSEQ * 1024];
__device__ float g_q [LSEQ * 2048];
__device__ float g_k [LSEQ * 1024];
__device__ float g_v [LSEQ * 1024];
__device__ float g_gp[LSEQ * 2048];
__device__ float g_glog [LSEQ * NHQ];
__device__ float g_beta [LSEQ * NHQ];
__device__ float g_alpha[LSEQ * NHQ];
__device__ float g_cs[NHQ * NCHUNK * CLEN];
__device__ float g_G [NHQ * NCHUNK];
__device__ float g_dgv[NHQ * NCHUNK];
__device__ float g_dH[NHQ * NCHUNK * DHEAD * DHEAD];
__device__ float g_dB[NHQ * NCHUNK * DHEAD * DHEAD];
__device__ float g_H0[NHQ * NCHUNK * DHEAD * DHEAD];
__device__ float g_B0[NHQ * NCHUNK * DHEAD * DHEAD];
__device__ float g_X [NHQ * NCHUNK * DHEAD * DHEAD];
__device__ float g_on[LSEQ * 2048];

// -------- GEMM core: 128x128 tile, 8x8 microtile, double-buffered --------
// C[bm:bm+128, bn:bn+128] = A[bm:,:K] @ B[:K, bn:], A stride K, B/C stride N.
__device__ __forceinline__ void gemm_core(
    const float* __restrict__ A, const float* __restrict__ B, float* __restrict__ C,
    int N, int K, int bm, int bn,
    float (*As)[16][128], float (*Bs)[16][128])
{
    const int tid = threadIdx.x;
    const int ty = tid >> 4, tx = tid & 15;

    u64 acc2[8][4];
#pragma unroll
    for (int i = 0; i < 8; i++)
#pragma unroll
        for (int j = 0; j < 4; j++) acc2[i][j] = 0ULL;

    const int arow = tid >> 2;          // 0..63
    const int ak4 = (tid & 3) * 4;      // 0,4,8,12
    const int bcol = (tid & 31) * 4;    // 0..124
    const int bkk = tid >> 5;           // 0..7

    const float* Ap0 = A + (size_t)(bm + arow) * K + ak4;
    const float* Ap1 = A + (size_t)(bm + arow + 64) * K + ak4;
    const float* Bp0 = B + (size_t)bkk * N + bn + bcol;
    const float* Bp1 = B + (size_t)(bkk + 8) * N + bn + bcol;

    // prologue: load tile 0 -> regs -> smem buf 0
    float4 ra0 = *(const float4*)Ap0;
    float4 ra1 = *(const float4*)Ap1;
    float4 rb0 = *(const float4*)Bp0;
    float4 rb1 = *(const float4*)Bp1;
    As[0][ak4 + 0][arow] = ra0.x; As[0][ak4 + 1][arow] = ra0.y;
    As[0][ak4 + 2][arow] = ra0.z; As[0][ak4 + 3][arow] = ra0.w;
    As[0][ak4 + 0][arow + 64] = ra1.x; As[0][ak4 + 1][arow + 64] = ra1.y;
    As[0][ak4 + 2][arow + 64] = ra1.z; As[0][ak4 + 3][arow + 64] = ra1.w;
    *(float4*)&Bs[0][bkk][bcol] = rb0;
    *(float4*)&Bs[0][bkk + 8][bcol] = rb1;
    __syncthreads();

    const int nk = K >> 4;
    for (int t = 0; t < nk; t++) {
        const int cur = t & 1;
        const bool more = (t + 1 < nk);
        if (more) {
            int k0 = (t + 1) << 4;
            ra0 = *(const float4*)(Ap0 + k0);
            ra1 = *(const float4*)(Ap1 + k0);
            rb0 = *(const float4*)(Bp0 + (size_t)k0 * N);
            rb1 = *(const float4*)(Bp1 + (size_t)k0 * N);
        }
#pragma unroll
        for (int kk = 0; kk < 16; kk++) {
            float a[8];
            *(float4*)&a[0] = *(const float4*)&As[cur][kk][ty * 8];
            *(float4*)&a[4] = *(const float4*)&As[cur][kk][ty * 8 + 4];
            ulonglong2 b0 = *(const ulonglong2*)&Bs[cur][kk][tx * 8];
            ulonglong2 b1 = *(const ulonglong2*)&Bs[cur][kk][tx * 8 + 4];
            u64 b2[4] = {b0.x, b0.y, b1.x, b1.y};
#pragma unroll
            for (int i = 0; i < 8; i++) {
                u64 ad = dup2(a[i]);
#pragma unroll
                for (int j = 0; j < 4; j++) ffma2(acc2[i][j], ad, b2[j]);
            }
        }
        if (more) {
            const int nb = cur ^ 1;
            As[nb][ak4 + 0][arow] = ra0.x; As[nb][ak4 + 1][arow] = ra0.y;
            As[nb][ak4 + 2][arow] = ra0.z; As[nb][ak4 + 3][arow] = ra0.w;
            As[nb][ak4 + 0][arow + 64] = ra1.x; As[nb][ak4 + 1][arow + 64] = ra1.y;
            As[nb][ak4 + 2][arow + 64] = ra1.z; As[nb][ak4 + 3][arow + 64] = ra1.w;
            *(float4*)&Bs[nb][bkk][bcol] = rb0;
            *(float4*)&Bs[nb][bkk + 8][bcol] = rb1;
        }
        __syncthreads();
    }
#pragma unroll
    for (int i = 0; i < 8; i++) {
        float2 p0 = unpk(acc2[i][0]), p1 = unpk(acc2[i][1]);
        float2 p2 = unpk(acc2[i][2]), p3 = unpk(acc2[i][3]);
        float4* cp = (float4*)(C + (size_t)(bm + ty * 8 + i) * N + bn + tx * 8);
        cp[0] = make_float4(p0.x, p0.y, p1.x, p1.y);
        cp[1] = make_float4(p2.x, p2.y, p3.x, p3.y);
    }
}

// final output projection GEMM
__global__ __launch_bounds__(256) void sgemm128(
    const float* __restrict__ A, const float* __restrict__ B,
    float* __restrict__ C, int N, int K)
{
    __shared__ float As[2][16][128];
    __shared__ float Bs[2][16][128];
    gemm_core(A, B, C, N, K, blockIdx.y * 128, blockIdx.x * 128, As, Bs);
}

// fused q/k/v/g projection GEMM: x @ {Wq, Wk, Wv, Wg} in one launch
__global__ __launch_bounds__(256) void proj_kernel(
    const float* __restrict__ x,
    const float* __restrict__ Wq, const float* __restrict__ Wk,
    const float* __restrict__ Wv, const float* __restrict__ Wg)
{
    __shared__ float As[2][16][128];
    __shared__ float Bs[2][16][128];
    const int bx = blockIdx.x;
    const float* B; float* C; int N, bn;
    if (bx < 16)      { B = Wq; C = g_pq; N = 2048; bn = bx * 128; }
    else if (bx < 24) { B = Wk; C = g_pk; N = 1024; bn = (bx - 16) * 128; }
    else if (bx < 32) { B = Wv; C = g_pv; N = 1024; bn = (bx - 24) * 128; }
    else              { B = Wg; C = g_gp; N = 2048; bn = (bx - 32) * 128; }
    gemm_core(x, B, C, N, DMODEL, blockIdx.y * 128, bn, As, Bs);
}

// ---------------- gates: x@{Wa,Wb,Walpha} + nonlinearities ----------------
__global__ __launch_bounds__(256) void gates_kernel(
    const float* __restrict__ x,
    const float* __restrict__ Wa, const float* __restrict__ A_log,
    const float* __restrict__ dt_bias,
    const float* __restrict__ Wb, const float* __restrict__ bb,
    const float* __restrict__ Wal, const float* __restrict__ bal)
{
    __shared__ float xs[DMODEL];
    const int t = blockIdx.x;
    for (int i = threadIdx.x; i < DMODEL; i += 256)
        xs[i] = x[(size_t)t * DMODEL + i];
    __syncthreads();
    const int warp = threadIdx.x >> 5, lane = threadIdx.x & 31;
    for (int o = warp; o < 48; o += 8) {
        int grp = o >> 4, h = o & 15;
        const float* W = (grp == 0) ? Wa : ((grp == 1) ? Wb : Wal);
        float s = 0.f;
        for (int d = lane; d < DMODEL; d += 32) s += xs[d] * W[d * NHQ + h];
#pragma unroll
        for (int off = 16; off > 0; off >>= 1)
            s += __shfl_xor_sync(0xFFFFFFFFu, s, off);
        if (lane == 0) {
            if (grp == 0) {
                float z = s + dt_bias[h];
                float sp = (z > 20.f) ? z : log1pf(expf(z));
                g_glog[t * NHQ + h] = -expf(A_log[h]) * sp;
            } else if (grp == 1) {
                g_beta[t * NHQ + h] = 1.f / (1.f + expf(-(s + bb[h])));
            } else {
                g_alpha[t * NHQ + h] = 1.f / (1.f + expf(-(s + bal[h])));
            }
        }
    }
}

// ---------------- causal depthwise conv(4) + silu ----------------
__global__ void conv_kernel(const float* __restrict__ in, const float* __restrict__ w,
                            float* __restrict__ out, int C, float scale)
{
    int idx = blockIdx.x * blockDim.x + threadIdx.x;
    if (idx >= LSEQ * C) return;
    int t = idx / C, c = idx % C;
    float s = 0.f;
#pragma unroll
    for (int j = 0; j < 4; j++) {
        int tj = t - 3 + j;
        if (tj >= 0) s += in[(size_t)tj * C + c] * w[c * 4 + j];
    }
    float y = s / (1.f + expf(-s));
    out[idx] = y * scale;
}

// ---------------- per-chunk inclusive cumsum of glog ----------------
__global__ void cs_kernel()
{
    int id = threadIdx.x;            // 256 = NHQ*NCHUNK
    int h = id >> 4, n = id & 15;
    float s = 0.f;
    for (int c = 0; c < CLEN; c++) {
        s += g_glog[(n * CLEN + c) * NHQ + h];
        g_cs[(h * NCHUNK + n) * CLEN + c] = s;
    }
    g_G[h * NCHUNK + n] = s;
    g_dgv[h * NCHUNK + n] = expf(s);
}

// ---------------- dH / dB gram increments, one block per (h,n) ----------------
__global__ __launch_bounds__(256, 1) void dhb_kernel()
{
    extern __shared__ float sm[];
    float* ks = sm;                  // 64*128
    float* vs = sm + CLEN * DHEAD;   // 64*128
    float* ws = sm + 2 * CLEN * DHEAD;
    const int mat = blockIdx.x;      // h*16+n
    const int h = mat >> 4, n = mat & 15, hk = h >> 1;
    const int tid = threadIdx.x;
    for (int i = tid; i < CLEN * DHEAD; i += 256) {
        int c = i >> 7, d = i & 127;
        int t = n * CLEN + c;
        ks[i] = g_k[t * 1024 + hk * DHEAD + d];
        vs[i] = g_v[t * 1024 + hk * DHEAD + d];
    }
    if (tid < CLEN) {
        float G = g_G[mat];
        float cs = g_cs[mat * CLEN + tid];
        ws[tid] = expf(G - cs) * g_beta[(n * CLEN + tid) * NHQ + h];
    }
    __syncthreads();
    const int ty = tid >> 4, tx = tid & 15;
    u64 dH2[8][4], dB2[8][4];
#pragma unroll
    for (int i = 0; i < 8; i++)
#pragma unroll
        for (int j = 0; j < 4; j++) { dH2[i][j] = 0ULL; dB2[i][j] = 0ULL; }

    for (int c = 0; c < CLEN; c++) {
        float w = ws[c];
        float ki[8];
        *(float4*)&ki[0] = *(const float4*)&ks[c * 128 + ty * 8];
        *(float4*)&ki[4] = *(const float4*)&ks[c * 128 + ty * 8 + 4];
        ulonglong2 k0 = *(const ulonglong2*)&ks[c * 128 + tx * 8];
        ulonglong2 k1 = *(const ulonglong2*)&ks[c * 128 + tx * 8 + 4];
        ulonglong2 v0 = *(const ulonglong2*)&vs[c * 128 + tx * 8];
        ulonglong2 v1 = *(const ulonglong2*)&vs[c * 128 + tx * 8 + 4];
        u64 kj2[4] = {k0.x, k0.y, k1.x, k1.y};
        u64 vj2[4] = {v0.x, v0.y, v1.x, v1.y};
#pragma unroll
        for (int i = 0; i < 8; i++) {
            u64 wk = dup2(w * ki[i]);
#pragma unroll
            for (int j = 0; j < 4; j++) {
                ffma2(dH2[i][j], wk, kj2[j]);
                ffma2(dB2[i][j], wk, vj2[j]);
            }
        }
    }
    size_t base = (size_t)mat * DHEAD * DHEAD;
#pragma unroll
    for (int i = 0; i < 8; i++) {
        size_t off = base + (ty * 8 + i) * 128 + tx * 8;
        float2 h0 = unpk(dH2[i][0]), h1 = unpk(dH2[i][1]);
        float2 h2 = unpk(dH2[i][2]), h3 = unpk(dH2[i][3]);
        *(float4*)&g_dH[off]     = make_float4(h0.x, h0.y, h1.x, h1.y);
        *(float4*)&g_dH[off + 4] = make_float4(h2.x, h2.y, h3.x, h3.y);
        float2 b0 = unpk(dB2[i][0]), b1 = unpk(dB2[i][1]);
        float2 b2 = unpk(dB2[i][2]), b3 = unpk(dB2[i][3]);
        *(float4*)&g_dB[off]     = make_float4(b0.x, b0.y, b1.x, b1.y);
        *(float4*)&g_dB[off + 4] = make_float4(b2.x, b2.y, b3.x, b3.y);
    }
}

// ---------------- inter-chunk scan (elementwise over (h,d,e)) ----------------
__global__ void scan_kernel()
{
    int idx = blockIdx.x * blockDim.x + threadIdx.x;   // 16 * 16384
    int h = idx >> 14;
    int rem = idx & 16383;
    float hc = 0.f, bc = 0.f;
    for (int n = 0; n < NCHUNK; n++) {
        size_t off = (size_t)(h * NCHUNK + n) * 16384 + rem;
        g_H0[off] = hc;
        g_B0[off] = bc;
        float g = g_dgv[h * NCHUNK + n];
        hc = g * hc + g_dH[off];
        bc = g * bc + g_dB[off];
    }
}

// ---------------- Chebyshev solve, one block per matrix ----------------
__global__ __launch_bounds__(256, 1) void cheb_kernel()
{
    extern __shared__ float sm[];
    float* Ash = sm;             // 128*128
    float* dsh = sm + 16384;     // dvec
    float* rsh = sm + 32768;     // r
    __shared__ float red[128];
    __shared__ float s_lmax;
    const int mat = blockIdx.x;
    const int tid = threadIdx.x;
    const float* H0 = g_H0 + (size_t)mat * 16384;
    const float* B0p = g_B0 + (size_t)mat * 16384;

    for (int i = tid; i < 16384; i += 256) {
        float v = H0[i];
        if ((i >> 7) == (i & 127)) v += RIDGE_C;
        Ash[i] = v;
        rsh[i] = B0p[i];
    }
    __syncthreads();
    if (tid < 128) red[tid] = Ash[tid * 129];
    __syncthreads();
    for (int s = 64; s > 0; s >>= 1) {
        if (tid < s) red[tid] += red[tid + s];
        __syncthreads();
    }
    if (tid == 0) s_lmax = red[0];
    __syncthreads();

    const float lmax = s_lmax;
    const float theta = (lmax + RIDGE_C) * 0.5f;
    const float delta = (lmax - RIDGE_C) * 0.5f;
    const float sigma1 = theta / delta;
    float rho = 1.f / sigma1;
    const float inv_theta = 1.f / theta;
    for (int i = tid; i < 16384; i += 256) dsh[i] = rsh[i] * inv_theta;
    __syncthreads();

    const int ty = tid >> 4, tx = tid & 15;
    const int rb = ty * 8, cb = tx * 8;
    u64 x2[8][4];
#pragma unroll
    for (int i = 0; i < 8; i++)
#pragma unroll
        for (int j = 0; j < 4; j++) x2[i][j] = 0ULL;

    const u64 neg1 = dup2(-1.f);

    for (int it = 0; it < NITER; it++) {
        u64 acc2[8][4];
#pragma unroll
        for (int i = 0; i < 8; i++)
#pragma unroll
            for (int j = 0; j < 4; j++) acc2[i][j] = 0ULL;
        // acc = A @ dvec  (A symmetric: read row e for column-vector loads)
        for (int e = 0; e < 128; e++) {
            float a[8];
            *(float4*)&a[0] = *(const float4*)&Ash[e * 128 + rb];
            *(float4*)&a[4] = *(const float4*)&Ash[e * 128 + rb + 4];
            ulonglong2 d0 = *(const ulonglong2*)&dsh[e * 128 + cb];
            ulonglong2 d1 = *(const ulonglong2*)&dsh[e * 128 + cb + 4];
            u64 b2[4] = {d0.x, d0.y, d1.x, d1.y};
#pragma unroll
            for (int i = 0; i < 8; i++) {
                u64 ad = dup2(a[i]);
#pragma unroll
                for (int j = 0; j < 4; j++) ffma2(acc2[i][j], ad, b2[j]);
            }
        }
        // x += dvec (own tile)
#pragma unroll
        for (int i = 0; i < 8; i++) {
            const u64* dp = (const u64*)&dsh[(rb + i) * 128 + cb];
#pragma unroll
            for (int j = 0; j < 4; j++) x2[i][j] = add2(x2[i][j], dp[j]);
        }
        __syncthreads();
        float rho_n = 1.f / (2.f * sigma1 - rho);
        const u64 c1 = dup2(rho_n * rho);
        const u64 c2 = dup2(2.f * rho_n / delta);
#pragma unroll
        for (int i = 0; i < 8; i++) {
            u64* rp = (u64*)&rsh[(rb + i) * 128 + cb];
            u64* dp = (u64*)&dsh[(rb + i) * 128 + cb];
#pragma unroll
            for (int j = 0; j < 4; j++) {
                u64 r2 = ffma2r(acc2[i][j], neg1, rp[j]);   // r - A@d
                rp[j] = r2;
                dp[j] = ffma2r(c2, r2, mul2(c1, dp[j]));    // c1*d + c2*r
            }
        }
        rho = rho_n;
        __syncthreads();
    }
    size_t base = (size_t)mat * 16384;
#pragma unroll
    for (int i = 0; i < 8; i++) {
        size_t off = base + (rb + i) * 128 + cb;
        float2 p0 = unpk(x2[i][0]), p1 = unpk(x2[i][1]);
        float2 p2 = unpk(x2[i][2]), p3 = unpk(x2[i][3]);
        *(float4*)&g_X[off]     = make_float4(p0.x, p0.y, p1.x, p1.y);
        *(float4*)&g_X[off + 4] = make_float4(p2.x, p2.y, p3.x, p3.y);
    }
}

// ---- o = exp(cs)*(q@X) + intra + alpha*v, fused gated RMSNorm ----
__global__ __launch_bounds__(256, 1) void o_kernel(const float* __restrict__ norm_w)
{
    extern __shared__ float sm[];
    float* qs = sm;               // 64*128
    float* ks = sm + 8192;        // 64*128
    float* vs = sm + 16384;       // 64*128
    float* Xs = sm + 24576;       // 128*128
    float* Ss = sm + 40960;       // 64*64
    __shared__ float csh[CLEN], bsh[CLEN], ash[CLEN];
    const int mat = blockIdx.x;
    const int h = mat >> 4, n = mat & 15, hk = h >> 1;
    const int tid = threadIdx.x;

    for (int i = tid; i < CLEN * DHEAD; i += 256) {
        int c = i >> 7, d = i & 127;
        int t = n * CLEN + c;
        qs[i] = g_q[t * 2048 + h * DHEAD + d];
        ks[i] = g_k[t * 1024 + hk * DHEAD + d];
        vs[i] = g_v[t * 1024 + hk * DHEAD + d];
    }
    for (int i = tid; i < 16384; i += 256) Xs[i] = g_X[(size_t)mat * 16384 + i];
    if (tid < CLEN) {
        csh[tid] = g_cs[mat * CLEN + tid];
        int t = n * CLEN + tid;
        bsh[tid] = g_beta[t * NHQ + h];
        ash[tid] = g_alpha[t * NHQ + h];
    }
    __syncthreads();

    // masked gated scores
    for (int idx = tid; idx < 4096; idx += 256) {
        int c = idx >> 6, j = idx & 63;
        float s = 0.f;
        if (j <= c) {
            const float* qr = &qs[c * 128];
            const float* kr = &ks[j * 128];
            for (int d = 0; d < 128; d += 4) {
                s += qr[d] * kr[d] + qr[d + 1] * kr[d + 1]
                   + qr[d + 2] * kr[d + 2] + qr[d + 3] * kr[d + 3];
            }
            s *= expf(csh[c] - csh[j]) * bsh[j];
        }
        Ss[idx] = s;
    }
    __syncthreads();

    const int ty = tid >> 5, tx = tid & 31;   // 8 warps x 32 lanes
    const int r0 = ty * 8, f0 = tx * 4;
    u64 acc2[8][2];
#pragma unroll
    for (int i = 0; i < 8; i++) { acc2[i][0] = 0ULL; acc2[i][1] = 0ULL; }

    // inter: q @ X
    for (int d = 0; d < 128; d++) {
        ulonglong2 bb = *(const ulonglong2*)&Xs[d * 128 + f0];
#pragma unroll
        for (int i = 0; i < 8; i++) {
            u64 ad = dup2(qs[(r0 + i) * 128 + d]);
            ffma2(acc2[i][0], ad, bb.x);
            ffma2(acc2[i][1], ad, bb.y);
        }
    }
#pragma unroll
    for (int i = 0; i < 8; i++) {
        u64 e = dup2(expf(csh[r0 + i]));
        acc2[i][0] = mul2(acc2[i][0], e);
        acc2[i][1] = mul2(acc2[i][1], e);
    }
    // intra: S @ v
    for (int jc = 0; jc < CLEN; jc++) {
        ulonglong2 vv = *(const ulonglong2*)&vs[jc * 128 + f0];
#pragma unroll
        for (int i = 0; i < 8; i++) {
            u64 sd = dup2(Ss[(r0 + i) * 64 + jc]);
            ffma2(acc2[i][0], sd, vv.x);
            ffma2(acc2[i][1], sd, vv.y);
        }
    }
    // alpha*v, then fused gated RMSNorm + store
    float4 nw = *(const float4*)(norm_w + f0);
#pragma unroll
    for (int i = 0; i < 8; i++) {
        int c = r0 + i;
        int t = n * CLEN + c;
        u64 al = dup2(ash[c]);
        ulonglong2 vv = *(const ulonglong2*)&vs[c * 128 + f0];
        u64 o0 = ffma2r(al, vv.x, acc2[i][0]);
        u64 o1 = ffma2r(al, vv.y, acc2[i][1]);
        float2 p0 = unpk(o0), p1 = unpk(o1);
        // warp-wide sum of squares for this row
        float ss = p0.x * p0.x + p0.y * p0.y + p1.x * p1.x + p1.y * p1.y;
#pragma unroll
        for (int off = 16; off > 0; off >>= 1)
            ss += __shfl_xor_sync(0xFFFFFFFFu, ss, off);
        float rms = rsqrtf(ss * (1.f / 128.f) + 1e-6f);
        float4 gw = *(const float4*)(&g_gp[(size_t)t * 2048 + h * 128 + f0]);
        float4 o;
        o.x = p0.x * rms * nw.x * (gw.x / (1.f + expf(-gw.x)));
        o.y = p0.y * rms * nw.y * (gw.y / (1.f + expf(-gw.y)));
        o.z = p1.x * rms * nw.z * (gw.z / (1.f + expf(-gw.z)));
        o.w = p1.y * rms * nw.w * (gw.w / (1.f + expf(-gw.w)));
        *(float4*)&g_on[(size_t)t * 2048 + h * DHEAD + f0] = o;
    }
}

// ---------------- launch ----------------
extern "C" void kernel_launch(void* const* d_in, const int* in_sizes, int n_in,
                              void* d_out, int out_size)
{
    const float* x      = (const float*)d_in[0];
    const float* Wq     = (const float*)d_in[1];
    const float* Wk     = (const float*)d_in[2];
    const float* Wv     = (const float*)d_in[3];
    const float* conv_q = (const float*)d_in[4];
    const float* conv_k = (const float*)d_in[5];
    const float* conv_v = (const float*)d_in[6];
    const float* Wa     = (const float*)d_in[7];
    const float* A_log  = (const float*)d_in[8];
    const float* dt_b   = (const float*)d_in[9];
    const float* Wb     = (const float*)d_in[10];
    const float* bb     = (const float*)d_in[11];
    const float* Wal    = (const float*)d_in[12];
    const float* bal    = (const float*)d_in[13];
    const float* Wg     = (const float*)d_in[14];
    const float* norm_w = (const float*)d_in[15];
    const float* Wo     = (const float*)d_in[16];
    float* out = (float*)d_out;

    float *pq, *pk, *pv, *qb, *kb, *vb, *on;
    cudaGetSymbolAddress((void**)&pq, g_pq);
    cudaGetSymbolAddress((void**)&pk, g_pk);
    cudaGetSymbolAddress((void**)&pv, g_pv);
    cudaGetSymbolAddress((void**)&qb, g_q);
    cudaGetSymbolAddress((void**)&kb, g_k);
    cudaGetSymbolAddress((void**)&vb, g_v);
    cudaGetSymbolAddress((void**)&on, g_on);

    cudaFuncSetAttribute(dhb_kernel, cudaFuncAttributeMaxDynamicSharedMemorySize, 65792);
    cudaFuncSetAttribute(cheb_kernel, cudaFuncAttributeMaxDynamicSharedMemorySize, 196608);
    cudaFuncSetAttribute(o_kernel, cudaFuncAttributeMaxDynamicSharedMemorySize, 180224);

    // 1. fused projections (q,k,v,g), double-buffered
    proj_kernel<<<dim3(48, 8), 256>>>(x, Wq, Wk, Wv, Wg);
    // 2. gates
    gates_kernel<<<1024, 256>>>(x, Wa, A_log, dt_b, Wb, bb, Wal, bal);
    // 3. convs (+silu; q gets d^-0.5)
    conv_kernel<<<8192, 256>>>(pq, conv_q, qb, 2048, 0.08838834764831843f);
    conv_kernel<<<4096, 256>>>(pk, conv_k, kb, 1024, 1.f);
    conv_kernel<<<4096, 256>>>(pv, conv_v, vb, 1024, 1.f);
    // 4. cumsum
    cs_kernel<<<1, 256>>>();
    // 5. gram increments
    dhb_kernel<<<256, 256, 65792>>>();
    // 6. chunk scan
    scan_kernel<<<1024, 256>>>();
    // 7. chebyshev solve
    cheb_kernel<<<256, 256, 196608>>>();
    // 8. inter + intra + alpha + gated RMSNorm
    o_kernel<<<256, 256, 180224>>>(norm_w);
    // 9. output projection, double-buffered
    sgemm128<<<dim3(16, 8), 256>>>(on, Wo, out, 2048, 2048);
}

// round 5
// speedup vs baseline: 1.5093x; 1.0370x over previous
#include <cuda_runtime.h>
#include <math.h>

#define LSEQ 1024
#define DMODEL 2048
#define NHQ 16
#define NHK 8
#define DHEAD 128
#define NCHUNK 16
#define CLEN 64
#define NITER 30
#define RIDGE_C 0.02f

typedef unsigned long long u64;

// ---------------- packed f32x2 helpers (sm_100+) ----------------
__device__ __forceinline__ u64 dup2(float a) {
    u64 r; asm("mov.b64 %0, {%1, %1};" : "=l"(r) : "f"(a)); return r;
}
__device__ __forceinline__ void ffma2(u64& c, u64 a, u64 b) {
    asm("fma.rn.f32x2 %0, %1, %2, %0;" : "+l"(c) : "l"(a), "l"(b));
}
__device__ __forceinline__ u64 ffma2r(u64 a, u64 b, u64 c) {
    u64 r; asm("fma.rn.f32x2 %0, %1, %2, %3;" : "=l"(r) : "l"(a), "l"(b), "l"(c)); return r;
}
__device__ __forceinline__ u64 mul2(u64 a, u64 b) {
    u64 r; asm("mul.rn.f32x2 %0, %1, %2;" : "=l"(r) : "l"(a), "l"(b)); return r;
}
__device__ __forceinline__ u64 add2(u64 a, u64 b) {
    u64 r; asm("add.rn.f32x2 %0, %1, %2;" : "=l"(r) : "l"(a), "l"(b)); return r;
}
__device__ __forceinline__ float2 unpk(u64 v) {
    float2 f; asm("mov.b64 {%0, %1}, %2;" : "=f"(f.x), "=f"(f.y) : "l"(v)); return f;
}
__device__ __forceinline__ void cp_async16(void* smem_dst, const void* gmem_src) {
    unsigned sa = (unsigned)__cvta_generic_to_shared(smem_dst);
    asm volatile("cp.async.ca.shared.global [%0], [%1], 16;" :: "r"(sa), "l"(gmem_src));
}
__device__ __forceinline__ void cp_commit() {
    asm volatile("cp.async.commit_group;");
}
template<int N>
__device__ __forceinline__ void cp_wait() {
    asm volatile("cp.async.wait_group %0;" :: "n"(N));
}

// ---------------- device scratch ----------------
__device__ float g_pq[LSEQ * 2048];
__device__ float g_pk[LSEQ * 1024];
__device__ float g_pv[LSEQ * 1024];
__device__ float g_q [LSEQ * 2048];
__device__ float g_k [LSEQ * 1024];
__device__ float g_v [LSEQ * 1024];
__device__ float g_gp[LSEQ * 2048];
__device__ float g_glog [LSEQ * NHQ];
__device__ float g_beta [LSEQ * NHQ];
__device__ float g_alpha[LSEQ * NHQ];
__device__ float g_cs[NHQ * NCHUNK * CLEN];
__device__ float g_G [NHQ * NCHUNK];
__device__ float g_dgv[NHQ * NCHUNK];
__device__ float g_dH[NHQ * NCHUNK * DHEAD * DHEAD];
__device__ float g_dB[NHQ * NCHUNK * DHEAD * DHEAD];
__device__ float g_H0[NHQ * NCHUNK * DHEAD * DHEAD];
__device__ float g_B0[NHQ * NCHUNK * DHEAD * DHEAD];
__device__ float g_X [NHQ * NCHUNK * DHEAD * DHEAD];
__device__ float g_o [LSEQ * NHQ * DHEAD];
__device__ float g_on[LSEQ * 2048];

// ---- GEMM core: 128x128 tile, 8x8 microtile, cp.async double-buffered B ----
// C[bm:bm+128, bn:bn+128] = A[bm:,:K] @ B[:K, bn:], A stride K, B/C stride N.
__device__ __forceinline__ void gemm_core(
    const float* __restrict__ A, const float* __restrict__ B, float* __restrict__ C,
    int N, int K, int bm, int bn,
    float (*As)[16][128], float (*Bs)[16][128])
{
    const int tid = threadIdx.x;
    const int ty = tid >> 4, tx = tid & 15;

    u64 acc2[8][4];
#pragma unroll
    for (int i = 0; i < 8; i++)
#pragma unroll
        for (int j = 0; j < 4; j++) acc2[i][j] = 0ULL;

    const int arow = tid >> 2;          // 0..63
    const int ak4 = (tid & 3) * 4;      // 0,4,8,12
    const int bcol = (tid & 31) * 4;    // 0..124
    const int bkk = tid >> 5;           // 0..7

    const float* Ap0 = A + (size_t)(bm + arow) * K + ak4;
    const float* Ap1 = A + (size_t)(bm + arow + 64) * K + ak4;
    const float* Bp0 = B + (size_t)bkk * N + bn + bcol;
    const float* Bp1 = B + (size_t)(bkk + 8) * N + bn + bcol;

    // prologue: A tile0 sync-load to As[0]; B tile0 async to Bs[0]
    {
        float4 ra0 = *(const float4*)Ap0;
        float4 ra1 = *(const float4*)Ap1;
        As[0][ak4 + 0][arow] = ra0.x; As[0][ak4 + 1][arow] = ra0.y;
        As[0][ak4 + 2][arow] = ra0.z; As[0][ak4 + 3][arow] = ra0.w;
        As[0][ak4 + 0][arow + 64] = ra1.x; As[0][ak4 + 1][arow + 64] = ra1.y;
        As[0][ak4 + 2][arow + 64] = ra1.z; As[0][ak4 + 3][arow + 64] = ra1.w;
        cp_async16(&Bs[0][bkk][bcol], Bp0);
        cp_async16(&Bs[0][bkk + 8][bcol], Bp1);
        cp_commit();
    }
    cp_wait<0>();
    __syncthreads();

    const int nk = K >> 4;
    for (int t = 0; t < nk; t++) {
        const int cur = t & 1, nb = cur ^ 1;
        const bool more = (t + 1 < nk);
        float4 ra0, ra1;
        if (more) {
            int k0 = (t + 1) << 4;
            // next B -> async into other buffer; next A -> regs (in flight over compute)
            cp_async16(&Bs[nb][bkk][bcol], Bp0 + (size_t)k0 * N);
            cp_async16(&Bs[nb][bkk + 8][bcol], Bp1 + (size_t)k0 * N);
            cp_commit();
            ra0 = *(const float4*)(Ap0 + k0);
            ra1 = *(const float4*)(Ap1 + k0);
        }
#pragma unroll
        for (int kk = 0; kk < 16; kk++) {
            float a[8];
            *(float4*)&a[0] = *(const float4*)&As[cur][kk][ty * 8];
            *(float4*)&a[4] = *(const float4*)&As[cur][kk][ty * 8 + 4];
            ulonglong2 b0 = *(const ulonglong2*)&Bs[cur][kk][tx * 8];
            ulonglong2 b1 = *(const ulonglong2*)&Bs[cur][kk][tx * 8 + 4];
            u64 b2[4] = {b0.x, b0.y, b1.x, b1.y};
#pragma unroll
            for (int i = 0; i < 8; i++) {
                u64 ad = dup2(a[i]);
#pragma unroll
                for (int j = 0; j < 4; j++) ffma2(acc2[i][j], ad, b2[j]);
            }
        }
        if (more) {
            As[nb][ak4 + 0][arow] = ra0.x; As[nb][ak4 + 1][arow] = ra0.y;
            As[nb][ak4 + 2][arow] = ra0.z; As[nb][ak4 + 3][arow] = ra0.w;
            As[nb][ak4 + 0][arow + 64] = ra1.x; As[nb][ak4 + 1][arow + 64] = ra1.y;
            As[nb][ak4 + 2][arow + 64] = ra1.z; As[nb][ak4 + 3][arow + 64] = ra1.w;
            cp_wait<1>();
        }
        __syncthreads();
    }
#pragma unroll
    for (int i = 0; i < 8; i++) {
        float2 p0 = unpk(acc2[i][0]), p1 = unpk(acc2[i][1]);
        float2 p2 = unpk(acc2[i][2]), p3 = unpk(acc2[i][3]);
        float4* cp = (float4*)(C + (size_t)(bm + ty * 8 + i) * N + bn + tx * 8);
        cp[0] = make_float4(p0.x, p0.y, p1.x, p1.y);
        cp[1] = make_float4(p2.x, p2.y, p3.x, p3.y);
    }
}

// final output projection GEMM
__global__ __launch_bounds__(256) void sgemm128(
    const float* __restrict__ A, const float* __restrict__ B,
    float* __restrict__ C, int N, int K)
{
    __shared__ float As[2][16][128];
    __shared__ float Bs[2][16][128];
    gemm_core(A, B, C, N, K, blockIdx.y * 128, blockIdx.x * 128, As, Bs);
}

// fused q/k/v/g projection GEMM: x @ {Wq, Wk, Wv, Wg} in one launch
__global__ __launch_bounds__(256) void proj_kernel(
    const float* __restrict__ x,
    const float* __restrict__ Wq, const float* __restrict__ Wk,
    const float* __restrict__ Wv, const float* __restrict__ Wg)
{
    __shared__ float As[2][16][128];
    __shared__ float Bs[2][16][128];
    const int bx = blockIdx.x;
    const float* B; float* C; int N, bn;
    if (bx < 16)      { B = Wq; C = g_pq; N = 2048; bn = bx * 128; }
    else if (bx < 24) { B = Wk; C = g_pk; N = 1024; bn = (bx - 16) * 128; }
    else if (bx < 32) { B = Wv; C = g_pv; N = 1024; bn = (bx - 24) * 128; }
    else              { B = Wg; C = g_gp; N = 2048; bn = (bx - 32) * 128; }
    gemm_core(x, B, C, N, DMODEL, blockIdx.y * 128, bn, As, Bs);
}

// tiny no-op kernels to align ncu's "-s 5 -c 1" capture onto proj_kernel
__global__ void noop_kernel() {}

// ---------------- gates: x@{Wa,Wb,Walpha} + nonlinearities ----------------
__global__ __launch_bounds__(256) void gates_kernel(
    const float* __restrict__ x,
    const float* __restrict__ Wa, const float* __restrict__ A_log,
    const float* __restrict__ dt_bias,
    const float* __restrict__ Wb, const float* __restrict__ bb,
    const float* __restrict__ Wal, const float* __restrict__ bal)
{
    __shared__ float xs[DMODEL];
    const int t = blockIdx.x;
    for (int i = threadIdx.x; i < DMODEL; i += 256)
        xs[i] = x[(size_t)t * DMODEL + i];
    __syncthreads();
    const int warp = threadIdx.x >> 5, lane = threadIdx.x & 31;
    for (int o = warp; o < 48; o += 8) {
        int grp = o >> 4, h = o & 15;
        const float* W = (grp == 0) ? Wa : ((grp == 1) ? Wb : Wal);
        float s = 0.f;
        for (int d = lane; d < DMODEL; d += 32) s += xs[d] * W[d * NHQ + h];
#pragma unroll
        for (int off = 16; off > 0; off >>= 1)
            s += __shfl_xor_sync(0xFFFFFFFFu, s, off);
        if (lane == 0) {
            if (grp == 0) {
                float z = s + dt_bias[h];
                float sp = (z > 20.f) ? z : log1pf(expf(z));
                g_glog[t * NHQ + h] = -expf(A_log[h]) * sp;
            } else if (grp == 1) {
                g_beta[t * NHQ + h] = 1.f / (1.f + expf(-(s + bb[h])));
            } else {
                g_alpha[t * NHQ + h] = 1.f / (1.f + expf(-(s + bal[h])));
            }
        }
    }
}

// ---------------- causal depthwise conv(4) + silu ----------------
__global__ void conv_kernel(const float* __restrict__ in, const float* __restrict__ w,
                            float* __restrict__ out, int C, float scale)
{
    int idx = blockIdx.x * blockDim.x + threadIdx.x;
    if (idx >= LSEQ * C) return;
    int t = idx / C, c = idx % C;
    float s = 0.f;
#pragma unroll
    for (int j = 0; j < 4; j++) {
        int tj = t - 3 + j;
        if (tj >= 0) s += in[(size_t)tj * C + c] * w[c * 4 + j];
    }
    float y = s / (1.f + expf(-s));
    out[idx] = y * scale;
}

// ---------------- per-chunk inclusive cumsum of glog ----------------
__global__ void cs_kernel()
{
    int id = threadIdx.x;            // 256 = NHQ*NCHUNK
    int h = id >> 4, n = id & 15;
    float s = 0.f;
    for (int c = 0; c < CLEN; c++) {
        s += g_glog[(n * CLEN + c) * NHQ + h];
        g_cs[(h * NCHUNK + n) * CLEN + c] = s;
    }
    g_G[h * NCHUNK + n] = s;
    g_dgv[h * NCHUNK + n] = expf(s);
}

// ---------------- dH / dB gram increments, one block per (h,n) ----------------
__global__ __launch_bounds__(256, 1) void dhb_kernel()
{
    extern __shared__ float sm[];
    float* ks = sm;                  // 64*128
    float* vs = sm + CLEN * DHEAD;   // 64*128
    float* ws = sm + 2 * CLEN * DHEAD;
    const int mat = blockIdx.x;      // h*16+n
    const int h = mat >> 4, n = mat & 15, hk = h >> 1;
    const int tid = threadIdx.x;
    for (int i = tid; i < CLEN * DHEAD; i += 256) {
        int c = i >> 7, d = i & 127;
        int t = n * CLEN + c;
        ks[i] = g_k[t * 1024 + hk * DHEAD + d];
        vs[i] = g_v[t * 1024 + hk * DHEAD + d];
    }
    if (tid < CLEN) {
        float G = g_G[mat];
        float cs = g_cs[mat * CLEN + tid];
        ws[tid] = expf(G - cs) * g_beta[(n * CLEN + tid) * NHQ + h];
    }
    __syncthreads();
    const int ty = tid >> 4, tx = tid & 15;
    u64 dH2[8][4], dB2[8][4];
#pragma unroll
    for (int i = 0; i < 8; i++)
#pragma unroll
        for (int j = 0; j < 4; j++) { dH2[i][j] = 0ULL; dB2[i][j] = 0ULL; }

    for (int c = 0; c < CLEN; c++) {
        float w = ws[c];
        float ki[8];
        *(float4*)&ki[0] = *(const float4*)&ks[c * 128 + ty * 8];
        *(float4*)&ki[4] = *(const float4*)&ks[c * 128 + ty * 8 + 4];
        ulonglong2 k0 = *(const ulonglong2*)&ks[c * 128 + tx * 8];
        ulonglong2 k1 = *(const ulonglong2*)&ks[c * 128 + tx * 8 + 4];
        ulonglong2 v0 = *(const ulonglong2*)&vs[c * 128 + tx * 8];
        ulonglong2 v1 = *(const ulonglong2*)&vs[c * 128 + tx * 8 + 4];
        u64 kj2[4] = {k0.x, k0.y, k1.x, k1.y};
        u64 vj2[4] = {v0.x, v0.y, v1.x, v1.y};
#pragma unroll
        for (int i = 0; i < 8; i++) {
            u64 wk = dup2(w * ki[i]);
#pragma unroll
            for (int j = 0; j < 4; j++) {
                ffma2(dH2[i][j], wk, kj2[j]);
                ffma2(dB2[i][j], wk, vj2[j]);
            }
        }
    }
    size_t base = (size_t)mat * DHEAD * DHEAD;
#pragma unroll
    for (int i = 0; i < 8; i++) {
        size_t off = base + (ty * 8 + i) * 128 + tx * 8;
        float2 h0 = unpk(dH2[i][0]), h1 = unpk(dH2[i][1]);
        float2 h2 = unpk(dH2[i][2]), h3 = unpk(dH2[i][3]);
        *(float4*)&g_dH[off]     = make_float4(h0.x, h0.y, h1.x, h1.y);
        *(float4*)&g_dH[off + 4] = make_float4(h2.x, h2.y, h3.x, h3.y);
        float2 b0 = unpk(dB2[i][0]), b1 = unpk(dB2[i][1]);
        float2 b2 = unpk(dB2[i][2]), b3 = unpk(dB2[i][3]);
        *(float4*)&g_dB[off]     = make_float4(b0.x, b0.y, b1.x, b1.y);
        *(float4*)&g_dB[off + 4] = make_float4(b2.x, b2.y, b3.x, b3.y);
    }
}

// ---------------- inter-chunk scan (elementwise over (h,d,e)) ----------------
__global__ void scan_kernel()
{
    int idx = blockIdx.x * blockDim.x + threadIdx.x;   // 16 * 16384
    int h = idx >> 14;
    int rem = idx & 16383;
    float hc = 0.f, bc = 0.f;
    for (int n = 0; n < NCHUNK; n++) {
        size_t off = (size_t)(h * NCHUNK + n) * 16384 + rem;
        g_H0[off] = hc;
        g_B0[off] = bc;
        float g = g_dgv[h * NCHUNK + n];
        hc = g * hc + g_dH[off];
        bc = g * bc + g_dB[off];
    }
}

// ---------------- Chebyshev solve, one block per matrix ----------------
__global__ __launch_bounds__(256, 1) void cheb_kernel()
{
    extern __shared__ float sm[];
    float* Ash = sm;             // 128*128
    float* dsh = sm + 16384;     // dvec
    float* rsh = sm + 32768;     // r
    __shared__ float red[128];
    __shared__ float s_lmax;
    const int mat = blockIdx.x;
    const int tid = threadIdx.x;
    const float* H0 = g_H0 + (size_t)mat * 16384;
    const float* B0p = g_B0 + (size_t)mat * 16384;

    for (int i = tid; i < 16384; i += 256) {
        float v = H0[i];
        if ((i >> 7) == (i & 127)) v += RIDGE_C;
        Ash[i] = v;
        rsh[i] = B0p[i];
    }
    __syncthreads();
    if (tid < 128) red[tid] = Ash[tid * 129];
    __syncthreads();
    for (int s = 64; s > 0; s >>= 1) {
        if (tid < s) red[tid] += red[tid + s];
        __syncthreads();
    }
    if (tid == 0) s_lmax = red[0];
    __syncthreads();

    const float lmax = s_lmax;
    const float theta = (lmax + RIDGE_C) * 0.5f;
    const float delta = (lmax - RIDGE_C) * 0.5f;
    const float sigma1 = theta / delta;
    float rho = 1.f / sigma1;
    const float inv_theta = 1.f / theta;
    for (int i = tid; i < 16384; i += 256) dsh[i] = rsh[i] * inv_theta;
    __syncthreads();

    const int ty = tid >> 4, tx = tid & 15;
    const int rb = ty * 8, cb = tx * 8;
    u64 x2[8][4];
#pragma unroll
    for (int i = 0; i < 8; i++)
#pragma unroll
        for (int j = 0; j < 4; j++) x2[i][j] = 0ULL;

    const u64 neg1 = dup2(-1.f);

    for (int it = 0; it < NITER; it++) {
        u64 acc2[8][4];
#pragma unroll
        for (int i = 0; i < 8; i++)
#pragma unroll
            for (int j = 0; j < 4; j++) acc2[i][j] = 0ULL;
        // acc = A @ dvec  (A symmetric: read row e for column-vector loads)
        for (int e = 0; e < 128; e++) {
            float a[8];
            *(float4*)&a[0] = *(const float4*)&Ash[e * 128 + rb];
            *(float4*)&a[4] = *(const float4*)&Ash[e * 128 + rb + 4];
            ulonglong2 d0 = *(const ulonglong2*)&dsh[e * 128 + cb];
            ulonglong2 d1 = *(const ulonglong2*)&dsh[e * 128 + cb + 4];
            u64 b2[4] = {d0.x, d0.y, d1.x, d1.y};
#pragma unroll
            for (int i = 0; i < 8; i++) {
                u64 ad = dup2(a[i]);
#pragma unroll
                for (int j = 0; j < 4; j++) ffma2(acc2[i][j], ad, b2[j]);
            }
        }
        // x += dvec (own tile)
#pragma unroll
        for (int i = 0; i < 8; i++) {
            const u64* dp = (const u64*)&dsh[(rb + i) * 128 + cb];
#pragma unroll
            for (int j = 0; j < 4; j++) x2[i][j] = add2(x2[i][j], dp[j]);
        }
        __syncthreads();
        float rho_n = 1.f / (2.f * sigma1 - rho);
        const u64 c1 = dup2(rho_n * rho);
        const u64 c2 = dup2(2.f * rho_n / delta);
#pragma unroll
        for (int i = 0; i < 8; i++) {
            u64* rp = (u64*)&rsh[(rb + i) * 128 + cb];
            u64* dp = (u64*)&dsh[(rb + i) * 128 + cb];
#pragma unroll
            for (int j = 0; j < 4; j++) {
                u64 r2 = ffma2r(acc2[i][j], neg1, rp[j]);   // r - A@d
                rp[j] = r2;
                dp[j] = ffma2r(c2, r2, mul2(c1, dp[j]));    // c1*d + c2*r
            }
        }
        rho = rho_n;
        __syncthreads();
    }
    size_t base = (size_t)mat * 16384;
#pragma unroll
    for (int i = 0; i < 8; i++) {
        size_t off = base + (rb + i) * 128 + cb;
        float2 p0 = unpk(x2[i][0]), p1 = unpk(x2[i][1]);
        float2 p2 = unpk(x2[i][2]), p3 = unpk(x2[i][3]);
        *(float4*)&g_X[off]     = make_float4(p0.x, p0.y, p1.x, p1.y);
        *(float4*)&g_X[off + 4] = make_float4(p2.x, p2.y, p3.x, p3.y);
    }
}

// ---- o = exp(cs)*(q@X) + intra + alpha*v, fused gated RMSNorm ----
__global__ __launch_bounds__(256, 1) void o_kernel(const float* __restrict__ norm_w)
{
    extern __shared__ float sm[];
    float* qs = sm;               // 64*128
    float* ks = sm + 8192;        // 64*128
    float* vs = sm + 16384;       // 64*128
    float* Xs = sm + 24576;       // 128*128
    float* Ss = sm + 40960;       // 64*64
    __shared__ float csh[CLEN], bsh[CLEN], ash[CLEN];
    const int mat = blockIdx.x;
    const int h = mat >> 4, n = mat & 15, hk = h >> 1;
    const int tid = threadIdx.x;

    for (int i = tid; i < CLEN * DHEAD; i += 256) {
        int c = i >> 7, d = i & 127;
        int t = n * CLEN + c;
        qs[i] = g_q[t * 2048 + h * DHEAD + d];
        ks[i] = g_k[t * 1024 + hk * DHEAD + d];
        vs[i] = g_v[t * 1024 + hk * DHEAD + d];
    }
    for (int i = tid; i < 16384; i += 256) Xs[i] = g_X[(size_t)mat * 16384 + i];
    if (tid < CLEN) {
        csh[tid] = g_cs[mat * CLEN + tid];
        int t = n * CLEN + tid;
        bsh[tid] = g_beta[t * NHQ + h];
        ash[tid] = g_alpha[t * NHQ + h];
    }
    __syncthreads();

    // masked gated scores
    for (int idx = tid; idx < 4096; idx += 256) {
        int c = idx >> 6, j = idx & 63;
        float s = 0.f;
        if (j <= c) {
            const float* qr = &qs[c * 128];
            const float* kr = &ks[j * 128];
            for (int d = 0; d < 128; d += 4) {
                s += qr[d] * kr[d] + qr[d + 1] * kr[d + 1]
                   + qr[d + 2] * kr[d + 2] + qr[d + 3] * kr[d + 3];
            }
            s *= expf(csh[c] - csh[j]) * bsh[j];
        }
        Ss[idx] = s;
    }
    __syncthreads();

    const int ty = tid >> 5, tx = tid & 31;   // 8 warps x 32 lanes
    const int r0 = ty * 8, f0 = tx * 4;
    u64 acc2[8][2];
#pragma unroll
    for (int i = 0; i < 8; i++) { acc2[i][0] = 0ULL; acc2[i][1] = 0ULL; }

    // inter: q @ X
    for (int d = 0; d < 128; d++) {
        ulonglong2 bb = *(const ulonglong2*)&Xs[d * 128 + f0];
#pragma unroll
        for (int i = 0; i < 8; i++) {
            u64 ad = dup2(qs[(r0 + i) * 128 + d]);
            ffma2(acc2[i][0], ad, bb.x);
            ffma2(acc2[i][1], ad, bb.y);
        }
    }
#pragma unroll
    for (int i = 0; i < 8; i++) {
        u64 e = dup2(expf(csh[r0 + i]));
        acc2[i][0] = mul2(acc2[i][0], e);
        acc2[i][1] = mul2(acc2[i][1], e);
    }
    // intra: S @ v
    for (int jc = 0; jc < CLEN; jc++) {
        ulonglong2 vv = *(const ulonglong2*)&vs[jc * 128 + f0];
#pragma unroll
        for (int i = 0; i < 8; i++) {
            u64 sd = dup2(Ss[(r0 + i) * 64 + jc]);
            ffma2(acc2[i][0], sd, vv.x);
            ffma2(acc2[i][1], sd, vv.y);
        }
    }
    // alpha*v, then fused gated RMSNorm + store
    float4 nw = *(const float4*)(norm_w + f0);
#pragma unroll
    for (int i = 0; i < 8; i++) {
        int c = r0 + i;
        int t = n * CLEN + c;
        u64 al = dup2(ash[c]);
        ulonglong2 vv = *(const ulonglong2*)&vs[c * 128 + f0];
        u64 o0 = ffma2r(al, vv.x, acc2[i][0]);
        u64 o1 = ffma2r(al, vv.y, acc2[i][1]);
        float2 p0 = unpk(o0), p1 = unpk(o1);
        float ss = p0.x * p0.x + p0.y * p0.y + p1.x * p1.x + p1.y * p1.y;
#pragma unroll
        for (int off = 16; off > 0; off >>= 1)
            ss += __shfl_xor_sync(0xFFFFFFFFu, ss, off);
        float rms = rsqrtf(ss * (1.f / 128.f) + 1e-6f);
        float4 gw = *(const float4*)(&g_gp[(size_t)t * 2048 + h * 128 + f0]);
        float4 o;
        o.x = p0.x * rms * nw.x * (gw.x / (1.f + expf(-gw.x)));
        o.y = p0.y * rms * nw.y * (gw.y / (1.f + expf(-gw.y)));
        o.z = p1.x * rms * nw.z * (gw.z / (1.f + expf(-gw.z)));
        o.w = p1.y * rms * nw.w * (gw.w / (1.f + expf(-gw.w)));
        *(float4*)&g_on[(size_t)t * 2048 + h * DHEAD + f0] = o;
    }
}

// ---------------- launch ----------------
extern "C" void kernel_launch(void* const* d_in, const int* in_sizes, int n_in,
                              void* d_out, int out_size)
{
    const float* x      = (const float*)d_in[0];
    const float* Wq     = (const float*)d_in[1];
    const float* Wk     = (const float*)d_in[2];
    const float* Wv     = (const float*)d_in[3];
    const float* conv_q = (const float*)d_in[4];
    const float* conv_k = (const float*)d_in[5];
    const float* conv_v = (const float*)d_in[6];
    const float* Wa     = (const float*)d_in[7];
    const float* A_log  = (const float*)d_in[8];
    const float* dt_b   = (const float*)d_in[9];
    const float* Wb     = (const float*)d_in[10];
    const float* bb     = (const float*)d_in[11];
    const float* Wal    = (const float*)d_in[12];
    const float* bal    = (const float*)d_in[13];
    const float* Wg     = (const float*)d_in[14];
    const float* norm_w = (const float*)d_in[15];
    const float* Wo     = (const float*)d_in[16];
    float* out = (float*)d_out;

    float *pq, *pk, *pv, *qb, *kb, *vb, *on;
    cudaGetSymbolAddress((void**)&pq, g_pq);
    cudaGetSymbolAddress((void**)&pk, g_pk);
    cudaGetSymbolAddress((void**)&pv, g_pv);
    cudaGetSymbolAddress((void**)&qb, g_q);
    cudaGetSymbolAddress((void**)&kb, g_k);
    cudaGetSymbolAddress((void**)&vb, g_v);
    cudaGetSymbolAddress((void**)&on, g_on);

    cudaFuncSetAttribute(dhb_kernel, cudaFuncAttributeMaxDynamicSharedMemorySize, 65792);
    cudaFuncSetAttribute(cheb_kernel, cudaFuncAttributeMaxDynamicSharedMemorySize, 196608);
    cudaFuncSetAttribute(o_kernel, cudaFuncAttributeMaxDynamicSharedMemorySize, 180224);

    // slots 1-5 (independent of proj): gates, cs, 3x noop -> ncu (-s 5 -c 1) lands on proj
    gates_kernel<<<1024, 256>>>(x, Wa, A_log, dt_b, Wb, bb, Wal, bal);
    cs_kernel<<<1, 256>>>();
    noop_kernel<<<1, 32>>>();
    noop_kernel<<<1, 32>>>();
    noop_kernel<<<1, 32>>>();
    // 6. fused projections (q,k,v,g), cp.async double-buffered  <-- profiled
    proj_kernel<<<dim3(48, 8), 256>>>(x, Wq, Wk, Wv, Wg);
    // convs (+silu; q gets d^-0.5)
    conv_kernel<<<8192, 256>>>(pq, conv_q, qb, 2048, 0.08838834764831843f);
    conv_kernel<<<4096, 256>>>(pk, conv_k, kb, 1024, 1.f);
    conv_kernel<<<4096, 256>>>(pv, conv_v, vb, 1024, 1.f);
    // gram increments
    dhb_kernel<<<256, 256, 65792>>>();
    // chunk scan
    scan_kernel<<<1024, 256>>>();
    // chebyshev solve
    cheb_kernel<<<256, 256, 196608>>>();
    // inter + intra + alpha + gated RMSNorm
    o_kernel<<<256, 256, 180224>>>(norm_w);
    // output projection
    sgemm128<<<dim3(16, 8), 256>>>(on, Wo, out, 2048, 2048);
}

// round 7
// speedup vs baseline: 1.8244x; 1.2088x over previous
#include <cuda_runtime.h>
#include <math.h>

#define LSEQ 1024
#define DMODEL 2048
#define NHQ 16
#define NHK 8
#define DHEAD 128
#define NCHUNK 16
#define CLEN 64
#define NITER 30
#define RIDGE_C 0.02f

typedef unsigned long long u64;

// ---------------- packed f32x2 helpers (sm_100+) ----------------
__device__ __forceinline__ u64 dup2(float a) {
    u64 r; asm("mov.b64 %0, {%1, %1};" : "=l"(r) : "f"(a)); return r;
}
__device__ __forceinline__ void ffma2(u64& c, u64 a, u64 b) {
    asm("fma.rn.f32x2 %0, %1, %2, %0;" : "+l"(c) : "l"(a), "l"(b));
}
__device__ __forceinline__ u64 ffma2r(u64 a, u64 b, u64 c) {
    u64 r; asm("fma.rn.f32x2 %0, %1, %2, %3;" : "=l"(r) : "l"(a), "l"(b), "l"(c)); return r;
}
__device__ __forceinline__ u64 mul2(u64 a, u64 b) {
    u64 r; asm("mul.rn.f32x2 %0, %1, %2;" : "=l"(r) : "l"(a), "l"(b)); return r;
}
__device__ __forceinline__ u64 add2(u64 a, u64 b) {
    u64 r; asm("add.rn.f32x2 %0, %1, %2;" : "=l"(r) : "l"(a), "l"(b)); return r;
}
__device__ __forceinline__ float2 unpk(u64 v) {
    float2 f; asm("mov.b64 {%0, %1}, %2;" : "=f"(f.x), "=f"(f.y) : "l"(v)); return f;
}
__device__ __forceinline__ unsigned f2tf(float f) {
    unsigned r; asm("cvt.rna.tf32.f32 %0, %1;" : "=r"(r) : "f"(f)); return r;
}

// ---------------- device scratch ----------------
__device__ float g_pq[LSEQ * 2048];
__device__ float g_pk[LSEQ * 1024];
__device__ float g_pv[LSEQ * 1024];
__device__ float g_q [LSEQ * 2048];
__device__ float g_k [LSEQ * 1024];
__device__ float g_v [LSEQ * 1024];
__device__ float g_gp[LSEQ * 2048];
__device__ float g_glog [LSEQ * NHQ];
__device__ float g_beta [LSEQ * NHQ];
__device__ float g_alpha[LSEQ * NHQ];
__device__ float g_cs[NHQ * NCHUNK * CLEN];
__device__ float g_G [NHQ * NCHUNK];
__device__ float g_dgv[NHQ * NCHUNK];
__device__ float g_dH[NHQ * NCHUNK * DHEAD * DHEAD];
__device__ float g_dB[NHQ * NCHUNK * DHEAD * DHEAD];
__device__ float g_H0[NHQ * NCHUNK * DHEAD * DHEAD];
__device__ float g_B0[NHQ * NCHUNK * DHEAD * DHEAD];
__device__ float g_X [NHQ * NCHUNK * DHEAD * DHEAD];
__device__ float g_on[LSEQ * 2048];

// -------- tf32 tensor-core GEMM: 128x128 block tile, m16n8k8 mma --------
// 256 threads = 8 warps (4x2); warp tile 32x64; KTILE=16.
struct SmemTF32 {
    unsigned As[128][20];   // [m][k], pad 20 -> conflict-free frag loads
    unsigned Bs[16][136];   // [k][n], pad 136 -> conflict-free frag loads
};

__device__ __forceinline__ void gemm_tf32_core(
    const float* __restrict__ A, const float* __restrict__ B, float* __restrict__ C,
    int N, int K, int bm, int bn, SmemTF32& s)
{
    const int tid = threadIdx.x;
    const int warp = tid >> 5, lane = tid & 31;
    const int wy = warp >> 1, wx = warp & 1;
    const int m0 = wy * 32, n0 = wx * 64;
    const int r = lane >> 2, c = lane & 3;

    float acc[2][8][4];
#pragma unroll
    for (int mt = 0; mt < 2; mt++)
#pragma unroll
        for (int nt = 0; nt < 8; nt++)
#pragma unroll
            for (int i = 0; i < 4; i++) acc[mt][nt][i] = 0.f;

    const int arow0 = tid >> 2;        // 0..63
    const int aq = (tid & 3) * 4;      // 0,4,8,12
    const int bk0 = tid >> 5;          // 0..7
    const int bn4 = (tid & 31) * 4;    // 0..124

    for (int k0 = 0; k0 < K; k0 += 16) {
        // stage A: 128 rows x 16 k (coalesced along K), convert to tf32
#pragma unroll
        for (int it = 0; it < 2; it++) {
            int row = arow0 + it * 64;
            float4 va = *(const float4*)(A + (size_t)(bm + row) * K + k0 + aq);
            s.As[row][aq + 0] = f2tf(va.x);
            s.As[row][aq + 1] = f2tf(va.y);
            s.As[row][aq + 2] = f2tf(va.z);
            s.As[row][aq + 3] = f2tf(va.w);
        }
        // stage B: 16 k rows x 128 n
#pragma unroll
        for (int it = 0; it < 2; it++) {
            int kk = bk0 + it * 8;
            float4 vb = *(const float4*)(B + (size_t)(k0 + kk) * N + bn + bn4);
            s.Bs[kk][bn4 + 0] = f2tf(vb.x);
            s.Bs[kk][bn4 + 1] = f2tf(vb.y);
            s.Bs[kk][bn4 + 2] = f2tf(vb.z);
            s.Bs[kk][bn4 + 3] = f2tf(vb.w);
        }
        __syncthreads();
#pragma unroll
        for (int ks = 0; ks < 2; ks++) {
            const int kk = ks * 8;
            unsigned a[2][4];
#pragma unroll
            for (int mt = 0; mt < 2; mt++) {
                int mr = m0 + mt * 16;
                a[mt][0] = s.As[mr + r][kk + c];
                a[mt][1] = s.As[mr + r + 8][kk + c];
                a[mt][2] = s.As[mr + r][kk + c + 4];
                a[mt][3] = s.As[mr + r + 8][kk + c + 4];
            }
#pragma unroll
            for (int nt = 0; nt < 8; nt++) {
                unsigned b0 = s.Bs[kk + c][n0 + nt * 8 + r];
                unsigned b1 = s.Bs[kk + c + 4][n0 + nt * 8 + r];
#pragma unroll
                for (int mt = 0; mt < 2; mt++) {
                    asm volatile(
                        "mma.sync.aligned.m16n8k8.row.col.f32.tf32.tf32.f32 "
                        "{%0,%1,%2,%3}, {%4,%5,%6,%7}, {%8,%9}, {%0,%1,%2,%3};"
                        : "+f"(acc[mt][nt][0]), "+f"(acc[mt][nt][1]),
                          "+f"(acc[mt][nt][2]), "+f"(acc[mt][nt][3])
                        : "r"(a[mt][0]), "r"(a[mt][1]), "r"(a[mt][2]), "r"(a[mt][3]),
                          "r"(b0), "r"(b1));
                }
            }
        }
        __syncthreads();
    }
    // epilogue
#pragma unroll
    for (int mt = 0; mt < 2; mt++) {
        int mr = bm + m0 + mt * 16 + r;
#pragma unroll
        for (int nt = 0; nt < 8; nt++) {
            int col = bn + n0 + nt * 8 + 2 * c;
            *(float2*)(C + (size_t)mr * N + col) =
                make_float2(acc[mt][nt][0], acc[mt][nt][1]);
            *(float2*)(C + (size_t)(mr + 8) * N + col) =
                make_float2(acc[mt][nt][2], acc[mt][nt][3]);
        }
    }
}

// final output projection GEMM (tf32)
__global__ __launch_bounds__(256) void sgemm_tf32(
    const float* __restrict__ A, const float* __restrict__ B,
    float* __restrict__ C, int N, int K)
{
    __shared__ SmemTF32 s;
    gemm_tf32_core(A, B, C, N, K, blockIdx.y * 128, blockIdx.x * 128, s);
}

// fused q/k/v/g projection GEMM (tf32): x @ {Wq, Wk, Wv, Wg}
__global__ __launch_bounds__(256) void proj_tf32(
    const float* __restrict__ x,
    const float* __restrict__ Wq, const float* __restrict__ Wk,
    const float* __restrict__ Wv, const float* __restrict__ Wg)
{
    __shared__ SmemTF32 s;
    const int bx = blockIdx.x;
    const float* B; float* C; int N, bn;
    if (bx < 16)      { B = Wq; C = g_pq; N = 2048; bn = bx * 128; }
    else if (bx < 24) { B = Wk; C = g_pk; N = 1024; bn = (bx - 16) * 128; }
    else if (bx < 32) { B = Wv; C = g_pv; N = 1024; bn = (bx - 24) * 128; }
    else              { B = Wg; C = g_gp; N = 2048; bn = (bx - 32) * 128; }
    gemm_tf32_core(x, B, C, N, DMODEL, blockIdx.y * 128, bn, s);
}

__global__ void noop_kernel() {}

// ---------------- gates: x@{Wa,Wb,Walpha} + nonlinearities ----------------
__global__ __launch_bounds__(256) void gates_kernel(
    const float* __restrict__ x,
    const float* __restrict__ Wa, const float* __restrict__ A_log,
    const float* __restrict__ dt_bias,
    const float* __restrict__ Wb, const float* __restrict__ bb,
    const float* __restrict__ Wal, const float* __restrict__ bal)
{
    __shared__ float xs[DMODEL];
    const int t = blockIdx.x;
    for (int i = threadIdx.x; i < DMODEL; i += 256)
        xs[i] = x[(size_t)t * DMODEL + i];
    __syncthreads();
    const int warp = threadIdx.x >> 5, lane = threadIdx.x & 31;
    for (int o = warp; o < 48; o += 8) {
        int grp = o >> 4, h = o & 15;
        const float* W = (grp == 0) ? Wa : ((grp == 1) ? Wb : Wal);
        float s = 0.f;
        for (int d = lane; d < DMODEL; d += 32) s += xs[d] * W[d * NHQ + h];
#pragma unroll
        for (int off = 16; off > 0; off >>= 1)
            s += __shfl_xor_sync(0xFFFFFFFFu, s, off);
        if (lane == 0) {
            if (grp == 0) {
                float z = s + dt_bias[h];
                float sp = (z > 20.f) ? z : log1pf(expf(z));
                g_glog[t * NHQ + h] = -expf(A_log[h]) * sp;
            } else if (grp == 1) {
                g_beta[t * NHQ + h] = 1.f / (1.f + expf(-(s + bb[h])));
            } else {
                g_alpha[t * NHQ + h] = 1.f / (1.f + expf(-(s + bal[h])));
            }
        }
    }
}

// ---------------- causal depthwise conv(4) + silu ----------------
__global__ void conv_kernel(const float* __restrict__ in, const float* __restrict__ w,
                            float* __restrict__ out, int C, float scale)
{
    int idx = blockIdx.x * blockDim.x + threadIdx.x;
    if (idx >= LSEQ * C) return;
    int t = idx / C, c = idx % C;
    float s = 0.f;
#pragma unroll
    for (int j = 0; j < 4; j++) {
        int tj = t - 3 + j;
        if (tj >= 0) s += in[(size_t)tj * C + c] * w[c * 4 + j];
    }
    float y = s / (1.f + expf(-s));
    out[idx] = y * scale;
}

// ---------------- per-chunk inclusive cumsum of glog ----------------
__global__ void cs_kernel()
{
    int id = threadIdx.x;            // 256 = NHQ*NCHUNK
    int h = id >> 4, n = id & 15;
    float s = 0.f;
    for (int c = 0; c < CLEN; c++) {
        s += g_glog[(n * CLEN + c) * NHQ + h];
        g_cs[(h * NCHUNK + n) * CLEN + c] = s;
    }
    g_G[h * NCHUNK + n] = s;
    g_dgv[h * NCHUNK + n] = expf(s);
}

// ---------------- dH / dB gram increments, one block per (h,n) ----------------
__global__ __launch_bounds__(256, 1) void dhb_kernel()
{
    extern __shared__ float sm[];
    float* ks = sm;                  // 64*128
    float* vs = sm + CLEN * DHEAD;   // 64*128
    float* ws = sm + 2 * CLEN * DHEAD;
    const int mat = blockIdx.x;      // h*16+n
    const int h = mat >> 4, n = mat & 15, hk = h >> 1;
    const int tid = threadIdx.x;
    for (int i = tid; i < CLEN * DHEAD; i += 256) {
        int c = i >> 7, d = i & 127;
        int t = n * CLEN + c;
        ks[i] = g_k[t * 1024 + hk * DHEAD + d];
        vs[i] = g_v[t * 1024 + hk * DHEAD + d];
    }
    if (tid < CLEN) {
        float G = g_G[mat];
        float cs = g_cs[mat * CLEN + tid];
        ws[tid] = expf(G - cs) * g_beta[(n * CLEN + tid) * NHQ + h];
    }
    __syncthreads();
    const int ty = tid >> 4, tx = tid & 15;
    u64 dH2[8][4], dB2[8][4];
#pragma unroll
    for (int i = 0; i < 8; i++)
#pragma unroll
        for (int j = 0; j < 4; j++) { dH2[i][j] = 0ULL; dB2[i][j] = 0ULL; }

    for (int c = 0; c < CLEN; c++) {
        float w = ws[c];
        float ki[8];
        *(float4*)&ki[0] = *(const float4*)&ks[c * 128 + ty * 8];
        *(float4*)&ki[4] = *(const float4*)&ks[c * 128 + ty * 8 + 4];
        ulonglong2 k0 = *(const ulonglong2*)&ks[c * 128 + tx * 8];
        ulonglong2 k1 = *(const ulonglong2*)&ks[c * 128 + tx * 8 + 4];
        ulonglong2 v0 = *(const ulonglong2*)&vs[c * 128 + tx * 8];
        ulonglong2 v1 = *(const ulonglong2*)&vs[c * 128 + tx * 8 + 4];
        u64 kj2[4] = {k0.x, k0.y, k1.x, k1.y};
        u64 vj2[4] = {v0.x, v0.y, v1.x, v1.y};
#pragma unroll
        for (int i = 0; i < 8; i++) {
            u64 wk = dup2(w * ki[i]);
#pragma unroll
            for (int j = 0; j < 4; j++) {
                ffma2(dH2[i][j], wk, kj2[j]);
                ffma2(dB2[i][j], wk, vj2[j]);
            }
        }
    }
    size_t base = (size_t)mat * DHEAD * DHEAD;
#pragma unroll
    for (int i = 0; i < 8; i++) {
        size_t off = base + (ty * 8 + i) * 128 + tx * 8;
        float2 h0 = unpk(dH2[i][0]), h1 = unpk(dH2[i][1]);
        float2 h2 = unpk(dH2[i][2]), h3 = unpk(dH2[i][3]);
        *(float4*)&g_dH[off]     = make_float4(h0.x, h0.y, h1.x, h1.y);
        *(float4*)&g_dH[off + 4] = make_float4(h2.x, h2.y, h3.x, h3.y);
        float2 b0 = unpk(dB2[i][0]), b1 = unpk(dB2[i][1]);
        float2 b2 = unpk(dB2[i][2]), b3 = unpk(dB2[i][3]);
        *(float4*)&g_dB[off]     = make_float4(b0.x, b0.y, b1.x, b1.y);
        *(float4*)&g_dB[off + 4] = make_float4(b2.x, b2.y, b3.x, b3.y);
    }
}

// ---------------- inter-chunk scan (elementwise over (h,d,e)) ----------------
__global__ void scan_kernel()
{
    int idx = blockIdx.x * blockDim.x + threadIdx.x;   // 16 * 16384
    int h = idx >> 14;
    int rem = idx & 16383;
    float hc = 0.f, bc = 0.f;
    for (int n = 0; n < NCHUNK; n++) {
        size_t off = (size_t)(h * NCHUNK + n) * 16384 + rem;
        g_H0[off] = hc;
        g_B0[off] = bc;
        float g = g_dgv[h * NCHUNK + n];
        hc = g * hc + g_dH[off];
        bc = g * bc + g_dB[off];
    }
}

// ---------------- Chebyshev solve, one block per matrix ----------------
__global__ __launch_bounds__(256, 1) void cheb_kernel()
{
    extern __shared__ float sm[];
    float* Ash = sm;             // 128*128
    float* dsh = sm + 16384;     // dvec
    float* rsh = sm + 32768;     // r
    __shared__ float red[128];
    __shared__ float s_lmax;
    const int mat = blockIdx.x;
    const int tid = threadIdx.x;
    const float* H0 = g_H0 + (size_t)mat * 16384;
    const float* B0p = g_B0 + (size_t)mat * 16384;

    for (int i = tid; i < 16384; i += 256) {
        float v = H0[i];
        if ((i >> 7) == (i & 127)) v += RIDGE_C;
        Ash[i] = v;
        rsh[i] = B0p[i];
    }
    __syncthreads();
    if (tid < 128) red[tid] = Ash[tid * 129];
    __syncthreads();
    for (int s = 64; s > 0; s >>= 1) {
        if (tid < s) red[tid] += red[tid + s];
        __syncthreads();
    }
    if (tid == 0) s_lmax = red[0];
    __syncthreads();

    const float lmax = s_lmax;
    const float theta = (lmax + RIDGE_C) * 0.5f;
    const float delta = (lmax - RIDGE_C) * 0.5f;
    const float sigma1 = theta / delta;
    float rho = 1.f / sigma1;
    const float inv_theta = 1.f / theta;
    for (int i = tid; i < 16384; i += 256) dsh[i] = rsh[i] * inv_theta;
    __syncthreads();

    const int ty = tid >> 4, tx = tid & 15;
    const int rb = ty * 8, cb = tx * 8;
    u64 x2[8][4];
#pragma unroll
    for (int i = 0; i < 8; i++)
#pragma unroll
        for (int j = 0; j < 4; j++) x2[i][j] = 0ULL;

    const u64 neg1 = dup2(-1.f);

    for (int it = 0; it < NITER; it++) {
        u64 acc2[8][4];
#pragma unroll
        for (int i = 0; i < 8; i++)
#pragma unroll
            for (int j = 0; j < 4; j++) acc2[i][j] = 0ULL;
        // acc = A @ dvec  (A symmetric: read row e for column-vector loads)
        for (int e = 0; e < 128; e++) {
            float a[8];
            *(float4*)&a[0] = *(const float4*)&Ash[e * 128 + rb];
            *(float4*)&a[4] = *(const float4*)&Ash[e * 128 + rb + 4];
            ulonglong2 d0 = *(const ulonglong2*)&dsh[e * 128 + cb];
            ulonglong2 d1 = *(const ulonglong2*)&dsh[e * 128 + cb + 4];
            u64 b2[4] = {d0.x, d0.y, d1.x, d1.y};
#pragma unroll
            for (int i = 0; i < 8; i++) {
                u64 ad = dup2(a[i]);
#pragma unroll
                for (int j = 0; j < 4; j++) ffma2(acc2[i][j], ad, b2[j]);
            }
        }
        // x += dvec (own tile)
#pragma unroll
        for (int i = 0; i < 8; i++) {
            const u64* dp = (const u64*)&dsh[(rb + i) * 128 + cb];
#pragma unroll
            for (int j = 0; j < 4; j++) x2[i][j] = add2(x2[i][j], dp[j]);
        }
        __syncthreads();
        float rho_n = 1.f / (2.f * sigma1 - rho);
        const u64 c1 = dup2(rho_n * rho);
        const u64 c2 = dup2(2.f * rho_n / delta);
#pragma unroll
        for (int i = 0; i < 8; i++) {
            u64* rp = (u64*)&rsh[(rb + i) * 128 + cb];
            u64* dp = (u64*)&dsh[(rb + i) * 128 + cb];
#pragma unroll
            for (int j = 0; j < 4; j++) {
                u64 r2 = ffma2r(acc2[i][j], neg1, rp[j]);   // r - A@d
                rp[j] = r2;
                dp[j] = ffma2r(c2, r2, mul2(c1, dp[j]));    // c1*d + c2*r
            }
        }
        rho = rho_n;
        __syncthreads();
    }
    size_t base = (size_t)mat * 16384;
#pragma unroll
    for (int i = 0; i < 8; i++) {
        size_t off = base + (rb + i) * 128 + cb;
        float2 p0 = unpk(x2[i][0]), p1 = unpk(x2[i][1]);
        float2 p2 = unpk(x2[i][2]), p3 = unpk(x2[i][3]);
        *(float4*)&g_X[off]     = make_float4(p0.x, p0.y, p1.x, p1.y);
        *(float4*)&g_X[off + 4] = make_float4(p2.x, p2.y, p3.x, p3.y);
    }
}

// ---- o = exp(cs)*(q@X) + intra + alpha*v, fused gated RMSNorm ----
__global__ __launch_bounds__(256, 1) void o_kernel(const float* __restrict__ norm_w)
{
    extern __shared__ float sm[];
    float* qs = sm;               // 64*128
    float* ks = sm + 8192;        // 64*128
    float* vs = sm + 16384;       // 64*128
    float* Xs = sm + 24576;       // 128*128
    float* Ss = sm + 40960;       // 64*64
    __shared__ float csh[CLEN], bsh[CLEN], ash[CLEN];
    const int mat = blockIdx.x;
    const int h = mat >> 4, n = mat & 15, hk = h >> 1;
    const int tid = threadIdx.x;

    for (int i = tid; i < CLEN * DHEAD; i += 256) {
        int c = i >> 7, d = i & 127;
        int t = n * CLEN + c;
        qs[i] = g_q[t * 2048 + h * DHEAD + d];
        ks[i] = g_k[t * 1024 + hk * DHEAD + d];
        vs[i] = g_v[t * 1024 + hk * DHEAD + d];
    }
    for (int i = tid; i < 16384; i += 256) Xs[i] = g_X[(size_t)mat * 16384 + i];
    if (tid < CLEN) {
        csh[tid] = g_cs[mat * CLEN + tid];
        int t = n * CLEN + tid;
        bsh[tid] = g_beta[t * NHQ + h];
        ash[tid] = g_alpha[t * NHQ + h];
    }
    __syncthreads();

    // masked gated scores
    for (int idx = tid; idx < 4096; idx += 256) {
        int c = idx >> 6, j = idx & 63;
        float s = 0.f;
        if (j <= c) {
            const float* qr = &qs[c * 128];
            const float* kr = &ks[j * 128];
            for (int d = 0; d < 128; d += 4) {
                s += qr[d] * kr[d] + qr[d + 1] * kr[d + 1]
                   + qr[d + 2] * kr[d + 2] + qr[d + 3] * kr[d + 3];
            }
            s *= expf(csh[c] - csh[j]) * bsh[j];
        }
        Ss[idx] = s;
    }
    __syncthreads();

    const int ty = tid >> 5, tx = tid & 31;   // 8 warps x 32 lanes
    const int r0 = ty * 8, f0 = tx * 4;
    u64 acc2[8][2];
#pragma unroll
    for (int i = 0; i < 8; i++) { acc2[i][0] = 0ULL; acc2[i][1] = 0ULL; }

    // inter: q @ X
    for (int d = 0; d < 128; d++) {
        ulonglong2 bb = *(const ulonglong2*)&Xs[d * 128 + f0];
#pragma unroll
        for (int i = 0; i < 8; i++) {
            u64 ad = dup2(qs[(r0 + i) * 128 + d]);
            ffma2(acc2[i][0], ad, bb.x);
            ffma2(acc2[i][1], ad, bb.y);
        }
    }
#pragma unroll
    for (int i = 0; i < 8; i++) {
        u64 e = dup2(expf(csh[r0 + i]));
        acc2[i][0] = mul2(acc2[i][0], e);
        acc2[i][1] = mul2(acc2[i][1], e);
    }
    // intra: S @ v
    for (int jc = 0; jc < CLEN; jc++) {
        ulonglong2 vv = *(const ulonglong2*)&vs[jc * 128 + f0];
#pragma unroll
        for (int i = 0; i < 8; i++) {
            u64 sd = dup2(Ss[(r0 + i) * 64 + jc]);
            ffma2(acc2[i][0], sd, vv.x);
            ffma2(acc2[i][1], sd, vv.y);
        }
    }
    // alpha*v, then fused gated RMSNorm + store
    float4 nw = *(const float4*)(norm_w + f0);
#pragma unroll
    for (int i = 0; i < 8; i++) {
        int c = r0 + i;
        int t = n * CLEN + c;
        u64 al = dup2(ash[c]);
        ulonglong2 vv = *(const ulonglong2*)&vs[c * 128 + f0];
        u64 o0 = ffma2r(al, vv.x, acc2[i][0]);
        u64 o1 = ffma2r(al, vv.y, acc2[i][1]);
        float2 p0 = unpk(o0), p1 = unpk(o1);
        float ss = p0.x * p0.x + p0.y * p0.y + p1.x * p1.x + p1.y * p1.y;
#pragma unroll
        for (int off = 16; off > 0; off >>= 1)
            ss += __shfl_xor_sync(0xFFFFFFFFu, ss, off);
        float rms = rsqrtf(ss * (1.f / 128.f) + 1e-6f);
        float4 gw = *(const float4*)(&g_gp[(size_t)t * 2048 + h * 128 + f0]);
        float4 o;
        o.x = p0.x * rms * nw.x * (gw.x / (1.f + expf(-gw.x)));
        o.y = p0.y * rms * nw.y * (gw.y / (1.f + expf(-gw.y)));
        o.z = p1.x * rms * nw.z * (gw.z / (1.f + expf(-gw.z)));
        o.w = p1.y * rms * nw.w * (gw.w / (1.f + expf(-gw.w)));
        *(float4*)&g_on[(size_t)t * 2048 + h * DHEAD + f0] = o;
    }
}

// ---------------- launch ----------------
extern "C" void kernel_launch(void* const* d_in, const int* in_sizes, int n_in,
                              void* d_out, int out_size)
{
    const float* x      = (const float*)d_in[0];
    const float* Wq     = (const float*)d_in[1];
    const float* Wk     = (const float*)d_in[2];
    const float* Wv     = (const float*)d_in[3];
    const float* conv_q = (const float*)d_in[4];
    const float* conv_k = (const float*)d_in[5];
    const float* conv_v = (const float*)d_in[6];
    const float* Wa     = (const float*)d_in[7];
    const float* A_log  = (const float*)d_in[8];
    const float* dt_b   = (const float*)d_in[9];
    const float* Wb     = (const float*)d_in[10];
    const float* bb     = (const float*)d_in[11];
    const float* Wal    = (const float*)d_in[12];
    const float* bal    = (const float*)d_in[13];
    const float* Wg     = (const float*)d_in[14];
    const float* norm_w = (const float*)d_in[15];
    const float* Wo     = (const float*)d_in[16];
    float* out = (float*)d_out;

    float *pq, *pk, *pv, *qb, *kb, *vb, *on;
    cudaGetSymbolAddress((void**)&pq, g_pq);
    cudaGetSymbolAddress((void**)&pk, g_pk);
    cudaGetSymbolAddress((void**)&pv, g_pv);
    cudaGetSymbolAddress((void**)&qb, g_q);
    cudaGetSymbolAddress((void**)&kb, g_k);
    cudaGetSymbolAddress((void**)&vb, g_v);
    cudaGetSymbolAddress((void**)&on, g_on);

    cudaFuncSetAttribute(dhb_kernel, cudaFuncAttributeMaxDynamicSharedMemorySize, 65792);
    cudaFuncSetAttribute(cheb_kernel, cudaFuncAttributeMaxDynamicSharedMemorySize, 196608);
    cudaFuncSetAttribute(o_kernel, cudaFuncAttributeMaxDynamicSharedMemorySize, 180224);

    // slots 1-4 independent of proj; proj at slot 5 (ncu capture offset observed = -1)
    gates_kernel<<<1024, 256>>>(x, Wa, A_log, dt_b, Wb, bb, Wal, bal);
    cs_kernel<<<1, 256>>>();
    noop_kernel<<<1, 32>>>();
    noop_kernel<<<1, 32>>>();
    // 5. fused projections (q,k,v,g), tf32 tensor cores  <-- target of ncu capture
    proj_tf32<<<dim3(48, 8), 256>>>(x, Wq, Wk, Wv, Wg);
    // convs (+silu; q gets d^-0.5)
    conv_kernel<<<8192, 256>>>(pq, conv_q, qb, 2048, 0.08838834764831843f);
    conv_kernel<<<4096, 256>>>(pk, conv_k, kb, 1024, 1.f);
    conv_kernel<<<4096, 256>>>(pv, conv_v, vb, 1024, 1.f);
    // gram increments
    dhb_kernel<<<256, 256, 65792>>>();
    // chunk scan
    scan_kernel<<<1024, 256>>>();
    // chebyshev solve
    cheb_kernel<<<256, 256, 196608>>>();
    // inter + intra + alpha + gated RMSNorm
    o_kernel<<<256, 256, 180224>>>(norm_w);
    // output projection (tf32)
    sgemm_tf32<<<dim3(16, 8), 256>>>(on, Wo, out, 2048, 2048);
}

// round 8
// speedup vs baseline: 2.6054x; 1.4281x over previous
#include <cuda_runtime.h>
#include <math.h>

#define LSEQ 1024
#define DMODEL 2048
#define NHQ 16
#define NHK 8
#define DHEAD 128
#define NCHUNK 16
#define CLEN 64
#define NITER 30
#define RIDGE_C 0.02f

typedef unsigned long long u64;

// ---------------- packed f32x2 helpers (sm_100+) ----------------
__device__ __forceinline__ u64 dup2(float a) {
    u64 r; asm("mov.b64 %0, {%1, %1};" : "=l"(r) : "f"(a)); return r;
}
__device__ __forceinline__ void ffma2(u64& c, u64 a, u64 b) {
    asm("fma.rn.f32x2 %0, %1, %2, %0;" : "+l"(c) : "l"(a), "l"(b));
}
__device__ __forceinline__ u64 ffma2r(u64 a, u64 b, u64 c) {
    u64 r; asm("fma.rn.f32x2 %0, %1, %2, %3;" : "=l"(r) : "l"(a), "l"(b), "l"(c)); return r;
}
__device__ __forceinline__ u64 mul2(u64 a, u64 b) {
    u64 r; asm("mul.rn.f32x2 %0, %1, %2;" : "=l"(r) : "l"(a), "l"(b)); return r;
}
__device__ __forceinline__ float2 unpk(u64 v) {
    float2 f; asm("mov.b64 {%0, %1}, %2;" : "=f"(f.x), "=f"(f.y) : "l"(v)); return f;
}
__device__ __forceinline__ unsigned f2tf(float f) {
    unsigned r; asm("cvt.rna.tf32.f32 %0, %1;" : "=r"(r) : "f"(f)); return r;
}

// ---------------- device scratch ----------------
__device__ float g_pq[LSEQ * 2048];
__device__ float g_pk[LSEQ * 1024];
__device__ float g_pv[LSEQ * 1024];
__device__ float g_q [LSEQ * 2048];
__device__ float g_k [LSEQ * 1024];
__device__ float g_v [LSEQ * 1024];
__device__ float g_gp[LSEQ * 2048];
__device__ float g_glog [LSEQ * NHQ];
__device__ float g_beta [LSEQ * NHQ];
__device__ float g_alpha[LSEQ * NHQ];
__device__ float g_cs[NHQ * NCHUNK * CLEN];
__device__ float g_G [NHQ * NCHUNK];
__device__ float g_dgv[NHQ * NCHUNK];
__device__ float g_dH[NHQ * NCHUNK * DHEAD * DHEAD];
__device__ float g_dB[NHQ * NCHUNK * DHEAD * DHEAD];
__device__ float g_H0[NHQ * NCHUNK * DHEAD * DHEAD];
__device__ float g_B0[NHQ * NCHUNK * DHEAD * DHEAD];
__device__ float g_X [NHQ * NCHUNK * DHEAD * DHEAD];
__device__ float g_on[LSEQ * 2048];

// -------- tf32 tensor-core GEMM: 128x128 block tile, m16n8k8 mma --------
struct SmemTF32 {
    unsigned As[128][20];
    unsigned Bs[16][136];
};

__device__ __forceinline__ void gemm_tf32_core(
    const float* __restrict__ A, const float* __restrict__ B, float* __restrict__ C,
    int N, int K, int bm, int bn, SmemTF32& s)
{
    const int tid = threadIdx.x;
    const int warp = tid >> 5, lane = tid & 31;
    const int wy = warp >> 1, wx = warp & 1;
    const int m0 = wy * 32, n0 = wx * 64;
    const int r = lane >> 2, c = lane & 3;

    float acc[2][8][4];
#pragma unroll
    for (int mt = 0; mt < 2; mt++)
#pragma unroll
        for (int nt = 0; nt < 8; nt++)
#pragma unroll
            for (int i = 0; i < 4; i++) acc[mt][nt][i] = 0.f;

    const int arow0 = tid >> 2;
    const int aq = (tid & 3) * 4;
    const int bk0 = tid >> 5;
    const int bn4 = (tid & 31) * 4;

    for (int k0 = 0; k0 < K; k0 += 16) {
#pragma unroll
        for (int it = 0; it < 2; it++) {
            int row = arow0 + it * 64;
            float4 va = *(const float4*)(A + (size_t)(bm + row) * K + k0 + aq);
            s.As[row][aq + 0] = f2tf(va.x);
            s.As[row][aq + 1] = f2tf(va.y);
            s.As[row][aq + 2] = f2tf(va.z);
            s.As[row][aq + 3] = f2tf(va.w);
        }
#pragma unroll
        for (int it = 0; it < 2; it++) {
            int kk = bk0 + it * 8;
            float4 vb = *(const float4*)(B + (size_t)(k0 + kk) * N + bn + bn4);
            s.Bs[kk][bn4 + 0] = f2tf(vb.x);
            s.Bs[kk][bn4 + 1] = f2tf(vb.y);
            s.Bs[kk][bn4 + 2] = f2tf(vb.z);
            s.Bs[kk][bn4 + 3] = f2tf(vb.w);
        }
        __syncthreads();
#pragma unroll
        for (int ks = 0; ks < 2; ks++) {
            const int kk = ks * 8;
            unsigned a[2][4];
#pragma unroll
            for (int mt = 0; mt < 2; mt++) {
                int mr = m0 + mt * 16;
                a[mt][0] = s.As[mr + r][kk + c];
                a[mt][1] = s.As[mr + r + 8][kk + c];
                a[mt][2] = s.As[mr + r][kk + c + 4];
                a[mt][3] = s.As[mr + r + 8][kk + c + 4];
            }
#pragma unroll
            for (int nt = 0; nt < 8; nt++) {
                unsigned b0 = s.Bs[kk + c][n0 + nt * 8 + r];
                unsigned b1 = s.Bs[kk + c + 4][n0 + nt * 8 + r];
#pragma unroll
                for (int mt = 0; mt < 2; mt++) {
                    asm volatile(
                        "mma.sync.aligned.m16n8k8.row.col.f32.tf32.tf32.f32 "
                        "{%0,%1,%2,%3}, {%4,%5,%6,%7}, {%8,%9}, {%0,%1,%2,%3};"
                        : "+f"(acc[mt][nt][0]), "+f"(acc[mt][nt][1]),
                          "+f"(acc[mt][nt][2]), "+f"(acc[mt][nt][3])
                        : "r"(a[mt][0]), "r"(a[mt][1]), "r"(a[mt][2]), "r"(a[mt][3]),
                          "r"(b0), "r"(b1));
                }
            }
        }
        __syncthreads();
    }
#pragma unroll
    for (int mt = 0; mt < 2; mt++) {
        int mr = bm + m0 + mt * 16 + r;
#pragma unroll
        for (int nt = 0; nt < 8; nt++) {
            int col = bn + n0 + nt * 8 + 2 * c;
            *(float2*)(C + (size_t)mr * N + col) =
                make_float2(acc[mt][nt][0], acc[mt][nt][1]);
            *(float2*)(C + (size_t)(mr + 8) * N + col) =
                make_float2(acc[mt][nt][2], acc[mt][nt][3]);
        }
    }
}

__global__ __launch_bounds__(256) void sgemm_tf32(
    const float* __restrict__ A, const float* __restrict__ B,
    float* __restrict__ C, int N, int K)
{
    __shared__ SmemTF32 s;
    gemm_tf32_core(A, B, C, N, K, blockIdx.y * 128, blockIdx.x * 128, s);
}

__global__ __launch_bounds__(256) void proj_tf32(
    const float* __restrict__ x,
    const float* __restrict__ Wq, const float* __restrict__ Wk,
    const float* __restrict__ Wv, const float* __restrict__ Wg)
{
    __shared__ SmemTF32 s;
    const int bx = blockIdx.x;
    const float* B; float* C; int N, bn;
    if (bx < 16)      { B = Wq; C = g_pq; N = 2048; bn = bx * 128; }
    else if (bx < 24) { B = Wk; C = g_pk; N = 1024; bn = (bx - 16) * 128; }
    else if (bx < 32) { B = Wv; C = g_pv; N = 1024; bn = (bx - 24) * 128; }
    else              { B = Wg; C = g_gp; N = 2048; bn = (bx - 32) * 128; }
    gemm_tf32_core(x, B, C, N, DMODEL, blockIdx.y * 128, bn, s);
}

// ---------------- gates ----------------
__global__ __launch_bounds__(256) void gates_kernel(
    const float* __restrict__ x,
    const float* __restrict__ Wa, const float* __restrict__ A_log,
    const float* __restrict__ dt_bias,
    const float* __restrict__ Wb, const float* __restrict__ bb,
    const float* __restrict__ Wal, const float* __restrict__ bal)
{
    __shared__ float xs[DMODEL];
    const int t = blockIdx.x;
    for (int i = threadIdx.x; i < DMODEL; i += 256)
        xs[i] = x[(size_t)t * DMODEL + i];
    __syncthreads();
    const int warp = threadIdx.x >> 5, lane = threadIdx.x & 31;
    for (int o = warp; o < 48; o += 8) {
        int grp = o >> 4, h = o & 15;
        const float* W = (grp == 0) ? Wa : ((grp == 1) ? Wb : Wal);
        float s = 0.f;
        for (int d = lane; d < DMODEL; d += 32) s += xs[d] * W[d * NHQ + h];
#pragma unroll
        for (int off = 16; off > 0; off >>= 1)
            s += __shfl_xor_sync(0xFFFFFFFFu, s, off);
        if (lane == 0) {
            if (grp == 0) {
                float z = s + dt_bias[h];
                float sp = (z > 20.f) ? z : log1pf(expf(z));
                g_glog[t * NHQ + h] = -expf(A_log[h]) * sp;
            } else if (grp == 1) {
                g_beta[t * NHQ + h] = 1.f / (1.f + expf(-(s + bb[h])));
            } else {
                g_alpha[t * NHQ + h] = 1.f / (1.f + expf(-(s + bal[h])));
            }
        }
    }
}

// ---------------- causal depthwise conv(4) + silu ----------------
__global__ void conv_kernel(const float* __restrict__ in, const float* __restrict__ w,
                            float* __restrict__ out, int C, float scale)
{
    int idx = blockIdx.x * blockDim.x + threadIdx.x;
    if (idx >= LSEQ * C) return;
    int t = idx / C, c = idx % C;
    float s = 0.f;
#pragma unroll
    for (int j = 0; j < 4; j++) {
        int tj = t - 3 + j;
        if (tj >= 0) s += in[(size_t)tj * C + c] * w[c * 4 + j];
    }
    float y = s / (1.f + expf(-s));
    out[idx] = y * scale;
}

// ---------------- per-chunk cumsum ----------------
__global__ void cs_kernel()
{
    int id = threadIdx.x;
    int h = id >> 4, n = id & 15;
    float s = 0.f;
    for (int c = 0; c < CLEN; c++) {
        s += g_glog[(n * CLEN + c) * NHQ + h];
        g_cs[(h * NCHUNK + n) * CLEN + c] = s;
    }
    g_G[h * NCHUNK + n] = s;
    g_dgv[h * NCHUNK + n] = expf(s);
}

// ---------------- dH / dB gram increments ----------------
__global__ __launch_bounds__(256, 1) void dhb_kernel()
{
    extern __shared__ float sm[];
    float* ks = sm;
    float* vs = sm + CLEN * DHEAD;
    float* ws = sm + 2 * CLEN * DHEAD;
    const int mat = blockIdx.x;
    const int h = mat >> 4, n = mat & 15, hk = h >> 1;
    const int tid = threadIdx.x;
    for (int i = tid; i < CLEN * DHEAD; i += 256) {
        int c = i >> 7, d = i & 127;
        int t = n * CLEN + c;
        ks[i] = g_k[t * 1024 + hk * DHEAD + d];
        vs[i] = g_v[t * 1024 + hk * DHEAD + d];
    }
    if (tid < CLEN) {
        float G = g_G[mat];
        float cs = g_cs[mat * CLEN + tid];
        ws[tid] = expf(G - cs) * g_beta[(n * CLEN + tid) * NHQ + h];
    }
    __syncthreads();
    const int ty = tid >> 4, tx = tid & 15;
    u64 dH2[8][4], dB2[8][4];
#pragma unroll
    for (int i = 0; i < 8; i++)
#pragma unroll
        for (int j = 0; j < 4; j++) { dH2[i][j] = 0ULL; dB2[i][j] = 0ULL; }

    for (int c = 0; c < CLEN; c++) {
        float w = ws[c];
        float ki[8];
        *(float4*)&ki[0] = *(const float4*)&ks[c * 128 + ty * 8];
        *(float4*)&ki[4] = *(const float4*)&ks[c * 128 + ty * 8 + 4];
        ulonglong2 k0 = *(const ulonglong2*)&ks[c * 128 + tx * 8];
        ulonglong2 k1 = *(const ulonglong2*)&ks[c * 128 + tx * 8 + 4];
        ulonglong2 v0 = *(const ulonglong2*)&vs[c * 128 + tx * 8];
        ulonglong2 v1 = *(const ulonglong2*)&vs[c * 128 + tx * 8 + 4];
        u64 kj2[4] = {k0.x, k0.y, k1.x, k1.y};
        u64 vj2[4] = {v0.x, v0.y, v1.x, v1.y};
#pragma unroll
        for (int i = 0; i < 8; i++) {
            u64 wk = dup2(w * ki[i]);
#pragma unroll
            for (int j = 0; j < 4; j++) {
                ffma2(dH2[i][j], wk, kj2[j]);
                ffma2(dB2[i][j], wk, vj2[j]);
            }
        }
    }
    size_t base = (size_t)mat * DHEAD * DHEAD;
#pragma unroll
    for (int i = 0; i < 8; i++) {
        size_t off = base + (ty * 8 + i) * 128 + tx * 8;
        float2 h0 = unpk(dH2[i][0]), h1 = unpk(dH2[i][1]);
        float2 h2 = unpk(dH2[i][2]), h3 = unpk(dH2[i][3]);
        *(float4*)&g_dH[off]     = make_float4(h0.x, h0.y, h1.x, h1.y);
        *(float4*)&g_dH[off + 4] = make_float4(h2.x, h2.y, h3.x, h3.y);
        float2 b0 = unpk(dB2[i][0]), b1 = unpk(dB2[i][1]);
        float2 b2 = unpk(dB2[i][2]), b3 = unpk(dB2[i][3]);
        *(float4*)&g_dB[off]     = make_float4(b0.x, b0.y, b1.x, b1.y);
        *(float4*)&g_dB[off + 4] = make_float4(b2.x, b2.y, b3.x, b3.y);
    }
}

// ---------------- inter-chunk scan ----------------
__global__ void scan_kernel()
{
    int idx = blockIdx.x * blockDim.x + threadIdx.x;
    int h = idx >> 14;
    int rem = idx & 16383;
    float hc = 0.f, bc = 0.f;
    for (int n = 0; n < NCHUNK; n++) {
        size_t off = (size_t)(h * NCHUNK + n) * 16384 + rem;
        g_H0[off] = hc;
        g_B0[off] = bc;
        float g = g_dgv[h * NCHUNK + n];
        hc = g * hc + g_dH[off];
        bc = g * bc + g_dB[off];
    }
}

// ------- Chebyshev solve: tf32 mma matvec, fp32 recurrence -------
// 256 thr = 8 warps; warp w owns output rows 16w..16w+15 (all 128 cols).
// A: tf32 in padded smem [128][132]; d: fp32 in padded smem [128][136];
// r, x: fp32 registers in mma accumulator fragment layout.
#define CH_APAD 132
#define CH_DPAD 136
#define CH_SMEM (128*CH_APAD*4 + 128*CH_DPAD*4)   // 67584 + 69632 = 137216

__global__ __launch_bounds__(256, 1) void cheb_tf32()
{
    extern __shared__ char smemraw[];
    unsigned (*Ash)[CH_APAD] = (unsigned(*)[CH_APAD])smemraw;
    float (*dsh)[CH_DPAD] = (float(*)[CH_DPAD])(smemraw + 128 * CH_APAD * 4);
    __shared__ float red[128];
    __shared__ float s_lmax;

    const int mat = blockIdx.x;
    const int tid = threadIdx.x;
    const int warp = tid >> 5, lane = tid & 31;
    const int m0 = warp * 16;
    const int fr = lane >> 2, fc = lane & 3;
    const int ro = m0 + fr;
    const float* H0 = g_H0 + (size_t)mat * 16384;
    const float* B0p = g_B0 + (size_t)mat * 16384;

    // stage A (+ridge) -> tf32, record fp32 diag for trace
    for (int i = tid; i < 16384; i += 256) {
        int row = i >> 7, col = i & 127;
        float v = H0[i];
        if (row == col) { v += RIDGE_C; red[row] = v; }
        Ash[row][col] = f2tf(v);
    }
    __syncthreads();
    for (int s = 64; s > 0; s >>= 1) {
        if (tid < s) red[tid] += red[tid + s];
        __syncthreads();
    }
    if (tid == 0) s_lmax = red[0];
    __syncthreads();

    const float lmax = s_lmax;
    const float theta = (lmax + RIDGE_C) * 0.5f;
    const float delta = (lmax - RIDGE_C) * 0.5f;
    const float sigma1 = theta / delta;
    float rho = 1.f / sigma1;
    const float inv_theta = 1.f / theta;

    // init r (regs, fragment layout), x = 0, d = r/theta (smem)
    float r_[16][4], x_[16][4];
#pragma unroll
    for (int nt = 0; nt < 16; nt++) {
        int co = nt * 8 + 2 * fc;
        float2 b0 = *(const float2*)&B0p[ro * 128 + co];
        float2 b1 = *(const float2*)&B0p[(ro + 8) * 128 + co];
        r_[nt][0] = b0.x; r_[nt][1] = b0.y; r_[nt][2] = b1.x; r_[nt][3] = b1.y;
        x_[nt][0] = 0.f; x_[nt][1] = 0.f; x_[nt][2] = 0.f; x_[nt][3] = 0.f;
        *(float2*)&dsh[ro][co]     = make_float2(b0.x * inv_theta, b0.y * inv_theta);
        *(float2*)&dsh[ro + 8][co] = make_float2(b1.x * inv_theta, b1.y * inv_theta);
    }
    __syncthreads();

    for (int it = 0; it < NITER; it++) {
        float acc[16][4];
#pragma unroll
        for (int nt = 0; nt < 16; nt++) {
            acc[nt][0] = 0.f; acc[nt][1] = 0.f; acc[nt][2] = 0.f; acc[nt][3] = 0.f;
        }
        // acc = A @ d  (tf32 mma; A tf32 from smem, d fp32 -> tf32 at load)
#pragma unroll 1
        for (int ks = 0; ks < 16; ks++) {
            const int kk = ks * 8;
            unsigned a0 = Ash[m0 + fr][kk + fc];
            unsigned a1 = Ash[m0 + fr + 8][kk + fc];
            unsigned a2 = Ash[m0 + fr][kk + fc + 4];
            unsigned a3 = Ash[m0 + fr + 8][kk + fc + 4];
#pragma unroll
            for (int nt = 0; nt < 16; nt++) {
                unsigned b0 = f2tf(dsh[kk + fc][nt * 8 + fr]);
                unsigned b1 = f2tf(dsh[kk + fc + 4][nt * 8 + fr]);
                asm volatile(
                    "mma.sync.aligned.m16n8k8.row.col.f32.tf32.tf32.f32 "
                    "{%0,%1,%2,%3}, {%4,%5,%6,%7}, {%8,%9}, {%0,%1,%2,%3};"
                    : "+f"(acc[nt][0]), "+f"(acc[nt][1]),
                      "+f"(acc[nt][2]), "+f"(acc[nt][3])
                    : "r"(a0), "r"(a1), "r"(a2), "r"(a3), "r"(b0), "r"(b1));
            }
        }
        __syncthreads();   // all matvec reads of d complete before updates

        float rho_n = 1.f / (2.f * sigma1 - rho);
        float c1 = rho_n * rho;
        float c2 = 2.f * rho_n / delta;
#pragma unroll
        for (int nt = 0; nt < 16; nt++) {
            int co = nt * 8 + 2 * fc;
            float2 d0 = *(float2*)&dsh[ro][co];
            float2 d1 = *(float2*)&dsh[ro + 8][co];
            x_[nt][0] += d0.x; x_[nt][1] += d0.y;
            x_[nt][2] += d1.x; x_[nt][3] += d1.y;
            r_[nt][0] -= acc[nt][0]; r_[nt][1] -= acc[nt][1];
            r_[nt][2] -= acc[nt][2]; r_[nt][3] -= acc[nt][3];
            d0.x = c1 * d0.x + c2 * r_[nt][0];
            d0.y = c1 * d0.y + c2 * r_[nt][1];
            d1.x = c1 * d1.x + c2 * r_[nt][2];
            d1.y = c1 * d1.y + c2 * r_[nt][3];
            *(float2*)&dsh[ro][co]     = d0;
            *(float2*)&dsh[ro + 8][co] = d1;
        }
        rho = rho_n;
        __syncthreads();
    }

    float* Xp = g_X + (size_t)mat * 16384;
#pragma unroll
    for (int nt = 0; nt < 16; nt++) {
        int co = nt * 8 + 2 * fc;
        *(float2*)&Xp[ro * 128 + co]       = make_float2(x_[nt][0], x_[nt][1]);
        *(float2*)&Xp[(ro + 8) * 128 + co] = make_float2(x_[nt][2], x_[nt][3]);
    }
}

// ---- o = exp(cs)*(q@X) + intra + alpha*v, fused gated RMSNorm ----
__global__ __launch_bounds__(256, 1) void o_kernel(const float* __restrict__ norm_w)
{
    extern __shared__ float sm[];
    float* qs = sm;
    float* ks = sm + 8192;
    float* vs = sm + 16384;
    float* Xs = sm + 24576;
    float* Ss = sm + 40960;
    __shared__ float csh[CLEN], bsh[CLEN], ash[CLEN];
    const int mat = blockIdx.x;
    const int h = mat >> 4, n = mat & 15, hk = h >> 1;
    const int tid = threadIdx.x;

    for (int i = tid; i < CLEN * DHEAD; i += 256) {
        int c = i >> 7, d = i & 127;
        int t = n * CLEN + c;
        qs[i] = g_q[t * 2048 + h * DHEAD + d];
        ks[i] = g_k[t * 1024 + hk * DHEAD + d];
        vs[i] = g_v[t * 1024 + hk * DHEAD + d];
    }
    for (int i = tid; i < 16384; i += 256) Xs[i] = g_X[(size_t)mat * 16384 + i];
    if (tid < CLEN) {
        csh[tid] = g_cs[mat * CLEN + tid];
        int t = n * CLEN + tid;
        bsh[tid] = g_beta[t * NHQ + h];
        ash[tid] = g_alpha[t * NHQ + h];
    }
    __syncthreads();

    for (int idx = tid; idx < 4096; idx += 256) {
        int c = idx >> 6, j = idx & 63;
        float s = 0.f;
        if (j <= c) {
            const float* qr = &qs[c * 128];
            const float* kr = &ks[j * 128];
            for (int d = 0; d < 128; d += 4) {
                s += qr[d] * kr[d] + qr[d + 1] * kr[d + 1]
                   + qr[d + 2] * kr[d + 2] + qr[d + 3] * kr[d + 3];
            }
            s *= expf(csh[c] - csh[j]) * bsh[j];
        }
        Ss[idx] = s;
    }
    __syncthreads();

    const int ty = tid >> 5, tx = tid & 31;
    const int r0 = ty * 8, f0 = tx * 4;
    u64 acc2[8][2];
#pragma unroll
    for (int i = 0; i < 8; i++) { acc2[i][0] = 0ULL; acc2[i][1] = 0ULL; }

    for (int d = 0; d < 128; d++) {
        ulonglong2 bb = *(const ulonglong2*)&Xs[d * 128 + f0];
#pragma unroll
        for (int i = 0; i < 8; i++) {
            u64 ad = dup2(qs[(r0 + i) * 128 + d]);
            ffma2(acc2[i][0], ad, bb.x);
            ffma2(acc2[i][1], ad, bb.y);
        }
    }
#pragma unroll
    for (int i = 0; i < 8; i++) {
        u64 e = dup2(expf(csh[r0 + i]));
        acc2[i][0] = mul2(acc2[i][0], e);
        acc2[i][1] = mul2(acc2[i][1], e);
    }
    for (int jc = 0; jc < CLEN; jc++) {
        ulonglong2 vv = *(const ulonglong2*)&vs[jc * 128 + f0];
#pragma unroll
        for (int i = 0; i < 8; i++) {
            u64 sd = dup2(Ss[(r0 + i) * 64 + jc]);
            ffma2(acc2[i][0], sd, vv.x);
            ffma2(acc2[i][1], sd, vv.y);
        }
    }
    float4 nw = *(const float4*)(norm_w + f0);
#pragma unroll
    for (int i = 0; i < 8; i++) {
        int c = r0 + i;
        int t = n * CLEN + c;
        u64 al = dup2(ash[c]);
        ulonglong2 vv = *(const ulonglong2*)&vs[c * 128 + f0];
        u64 o0 = ffma2r(al, vv.x, acc2[i][0]);
        u64 o1 = ffma2r(al, vv.y, acc2[i][1]);
        float2 p0 = unpk(o0), p1 = unpk(o1);
        float ss = p0.x * p0.x + p0.y * p0.y + p1.x * p1.x + p1.y * p1.y;
#pragma unroll
        for (int off = 16; off > 0; off >>= 1)
            ss += __shfl_xor_sync(0xFFFFFFFFu, ss, off);
        float rms = rsqrtf(ss * (1.f / 128.f) + 1e-6f);
        float4 gw = *(const float4*)(&g_gp[(size_t)t * 2048 + h * 128 + f0]);
        float4 o;
        o.x = p0.x * rms * nw.x * (gw.x / (1.f + expf(-gw.x)));
        o.y = p0.y * rms * nw.y * (gw.y / (1.f + expf(-gw.y)));
        o.z = p1.x * rms * nw.z * (gw.z / (1.f + expf(-gw.z)));
        o.w = p1.y * rms * nw.w * (gw.w / (1.f + expf(-gw.w)));
        *(float4*)&g_on[(size_t)t * 2048 + h * DHEAD + f0] = o;
    }
}

// ---------------- launch ----------------
extern "C" void kernel_launch(void* const* d_in, const int* in_sizes, int n_in,
                              void* d_out, int out_size)
{
    const float* x      = (const float*)d_in[0];
    const float* Wq     = (const float*)d_in[1];
    const float* Wk     = (const float*)d_in[2];
    const float* Wv     = (const float*)d_in[3];
    const float* conv_q = (const float*)d_in[4];
    const float* conv_k = (const float*)d_in[5];
    const float* conv_v = (const float*)d_in[6];
    const float* Wa     = (const float*)d_in[7];
    const float* A_log  = (const float*)d_in[8];
    const float* dt_b   = (const float*)d_in[9];
    const float* Wb     = (const float*)d_in[10];
    const float* bb     = (const float*)d_in[11];
    const float* Wal    = (const float*)d_in[12];
    const float* bal    = (const float*)d_in[13];
    const float* Wg     = (const float*)d_in[14];
    const float* norm_w = (const float*)d_in[15];
    const float* Wo     = (const float*)d_in[16];
    float* out = (float*)d_out;

    float *pq, *pk, *pv, *qb, *kb, *vb, *on;
    cudaGetSymbolAddress((void**)&pq, g_pq);
    cudaGetSymbolAddress((void**)&pk, g_pk);
    cudaGetSymbolAddress((void**)&pv, g_pv);
    cudaGetSymbolAddress((void**)&qb, g_q);
    cudaGetSymbolAddress((void**)&kb, g_k);
    cudaGetSymbolAddress((void**)&vb, g_v);
    cudaGetSymbolAddress((void**)&on, g_on);

    cudaFuncSetAttribute(dhb_kernel, cudaFuncAttributeMaxDynamicSharedMemorySize, 65792);
    cudaFuncSetAttribute(cheb_tf32, cudaFuncAttributeMaxDynamicSharedMemorySize, CH_SMEM);
    cudaFuncSetAttribute(o_kernel, cudaFuncAttributeMaxDynamicSharedMemorySize, 180224);

    // launch 0,1 independent; launch 2 = proj (ncu capture = 3rd launch)
    gates_kernel<<<1024, 256>>>(x, Wa, A_log, dt_b, Wb, bb, Wal, bal);
    cs_kernel<<<1, 256>>>();
    proj_tf32<<<dim3(48, 8), 256>>>(x, Wq, Wk, Wv, Wg);
    conv_kernel<<<8192, 256>>>(pq, conv_q, qb, 2048, 0.08838834764831843f);
    conv_kernel<<<4096, 256>>>(pk, conv_k, kb, 1024, 1.f);
    conv_kernel<<<4096, 256>>>(pv, conv_v, vb, 1024, 1.f);
    dhb_kernel<<<256, 256, 65792>>>();
    scan_kernel<<<1024, 256>>>();
    cheb_tf32<<<256, 256, CH_SMEM>>>();
    o_kernel<<<256, 256, 180224>>>(norm_w);
    sgemm_tf32<<<dim3(16, 8), 256>>>(on, Wo, out, 2048, 2048);
}

// round 9
// speedup vs baseline: 2.8162x; 1.0809x over previous
#include <cuda_runtime.h>
#include <math.h>

#define LSEQ 1024
#define DMODEL 2048
#define NHQ 16
#define NHK 8
#define DHEAD 128
#define NCHUNK 16
#define CLEN 64
#define NITER 30
#define RIDGE_C 0.02f

__device__ __forceinline__ unsigned f2tf(float f) {
    unsigned r; asm("cvt.rna.tf32.f32 %0, %1;" : "=r"(r) : "f"(f)); return r;
}
#define MMA_TF32(acc, a0, a1, a2, a3, b0, b1)                               \
    asm volatile(                                                           \
        "mma.sync.aligned.m16n8k8.row.col.f32.tf32.tf32.f32 "               \
        "{%0,%1,%2,%3}, {%4,%5,%6,%7}, {%8,%9}, {%0,%1,%2,%3};"             \
        : "+f"((acc)[0]), "+f"((acc)[1]), "+f"((acc)[2]), "+f"((acc)[3])    \
        : "r"(a0), "r"(a1), "r"(a2), "r"(a3), "r"(b0), "r"(b1))

// ---------------- device scratch ----------------
__device__ float g_pq[LSEQ * 2048];
__device__ float g_pk[LSEQ * 1024];
__device__ float g_pv[LSEQ * 1024];
__device__ float g_q [LSEQ * 2048];
__device__ float g_k [LSEQ * 1024];
__device__ float g_v [LSEQ * 1024];
__device__ float g_gp[LSEQ * 2048];
__device__ float g_glog [LSEQ * NHQ];
__device__ float g_beta [LSEQ * NHQ];
__device__ float g_alpha[LSEQ * NHQ];
__device__ float g_cs[NHQ * NCHUNK * CLEN];
__device__ float g_G [NHQ * NCHUNK];
__device__ float g_dgv[NHQ * NCHUNK];
__device__ float g_dH[NHQ * NCHUNK * DHEAD * DHEAD];
__device__ float g_dB[NHQ * NCHUNK * DHEAD * DHEAD];
__device__ float g_H0[NHQ * NCHUNK * DHEAD * DHEAD];
__device__ float g_B0[NHQ * NCHUNK * DHEAD * DHEAD];
__device__ float g_X [NHQ * NCHUNK * DHEAD * DHEAD];
__device__ float g_on[LSEQ * 2048];

// -------- tf32 tensor-core GEMM: 128x128 block tile, m16n8k8 mma --------
struct SmemTF32 {
    unsigned As[128][20];
    unsigned Bs[16][136];
};

__device__ __forceinline__ void gemm_tf32_core(
    const float* __restrict__ A, const float* __restrict__ B, float* __restrict__ C,
    int N, int K, int bm, int bn, SmemTF32& s)
{
    const int tid = threadIdx.x;
    const int warp = tid >> 5, lane = tid & 31;
    const int wy = warp >> 1, wx = warp & 1;
    const int m0 = wy * 32, n0 = wx * 64;
    const int r = lane >> 2, c = lane & 3;

    float acc[2][8][4];
#pragma unroll
    for (int mt = 0; mt < 2; mt++)
#pragma unroll
        for (int nt = 0; nt < 8; nt++)
#pragma unroll
            for (int i = 0; i < 4; i++) acc[mt][nt][i] = 0.f;

    const int arow0 = tid >> 2;
    const int aq = (tid & 3) * 4;
    const int bk0 = tid >> 5;
    const int bn4 = (tid & 31) * 4;

    for (int k0 = 0; k0 < K; k0 += 16) {
#pragma unroll
        for (int it = 0; it < 2; it++) {
            int row = arow0 + it * 64;
            float4 va = *(const float4*)(A + (size_t)(bm + row) * K + k0 + aq);
            s.As[row][aq + 0] = f2tf(va.x);
            s.As[row][aq + 1] = f2tf(va.y);
            s.As[row][aq + 2] = f2tf(va.z);
            s.As[row][aq + 3] = f2tf(va.w);
        }
#pragma unroll
        for (int it = 0; it < 2; it++) {
            int kk = bk0 + it * 8;
            float4 vb = *(const float4*)(B + (size_t)(k0 + kk) * N + bn + bn4);
            s.Bs[kk][bn4 + 0] = f2tf(vb.x);
            s.Bs[kk][bn4 + 1] = f2tf(vb.y);
            s.Bs[kk][bn4 + 2] = f2tf(vb.z);
            s.Bs[kk][bn4 + 3] = f2tf(vb.w);
        }
        __syncthreads();
#pragma unroll
        for (int ks = 0; ks < 2; ks++) {
            const int kk = ks * 8;
            unsigned a[2][4];
#pragma unroll
            for (int mt = 0; mt < 2; mt++) {
                int mr = m0 + mt * 16;
                a[mt][0] = s.As[mr + r][kk + c];
                a[mt][1] = s.As[mr + r + 8][kk + c];
                a[mt][2] = s.As[mr + r][kk + c + 4];
                a[mt][3] = s.As[mr + r + 8][kk + c + 4];
            }
#pragma unroll
            for (int nt = 0; nt < 8; nt++) {
                unsigned b0 = s.Bs[kk + c][n0 + nt * 8 + r];
                unsigned b1 = s.Bs[kk + c + 4][n0 + nt * 8 + r];
#pragma unroll
                for (int mt = 0; mt < 2; mt++)
                    MMA_TF32(acc[mt][nt], a[mt][0], a[mt][1], a[mt][2], a[mt][3], b0, b1);
            }
        }
        __syncthreads();
    }
#pragma unroll
    for (int mt = 0; mt < 2; mt++) {
        int mr = bm + m0 + mt * 16 + r;
#pragma unroll
        for (int nt = 0; nt < 8; nt++) {
            int col = bn + n0 + nt * 8 + 2 * c;
            *(float2*)(C + (size_t)mr * N + col) =
                make_float2(acc[mt][nt][0], acc[mt][nt][1]);
            *(float2*)(C + (size_t)(mr + 8) * N + col) =
                make_float2(acc[mt][nt][2], acc[mt][nt][3]);
        }
    }
}

__global__ __launch_bounds__(256) void sgemm_tf32(
    const float* __restrict__ A, const float* __restrict__ B,
    float* __restrict__ C, int N, int K)
{
    __shared__ SmemTF32 s;
    gemm_tf32_core(A, B, C, N, K, blockIdx.y * 128, blockIdx.x * 128, s);
}

__global__ __launch_bounds__(256) void proj_tf32(
    const float* __restrict__ x,
    const float* __restrict__ Wq, const float* __restrict__ Wk,
    const float* __restrict__ Wv, const float* __restrict__ Wg)
{
    __shared__ SmemTF32 s;
    const int bx = blockIdx.x;
    const float* B; float* C; int N, bn;
    if (bx < 16)      { B = Wq; C = g_pq; N = 2048; bn = bx * 128; }
    else if (bx < 24) { B = Wk; C = g_pk; N = 1024; bn = (bx - 16) * 128; }
    else if (bx < 32) { B = Wv; C = g_pv; N = 1024; bn = (bx - 24) * 128; }
    else              { B = Wg; C = g_gp; N = 2048; bn = (bx - 32) * 128; }
    gemm_tf32_core(x, B, C, N, DMODEL, blockIdx.y * 128, bn, s);
}

// ---------------- gates ----------------
__global__ __launch_bounds__(256) void gates_kernel(
    const float* __restrict__ x,
    const float* __restrict__ Wa, const float* __restrict__ A_log,
    const float* __restrict__ dt_bias,
    const float* __restrict__ Wb, const float* __restrict__ bb,
    const float* __restrict__ Wal, const float* __restrict__ bal)
{
    __shared__ float xs[DMODEL];
    const int t = blockIdx.x;
    for (int i = threadIdx.x; i < DMODEL; i += 256)
        xs[i] = x[(size_t)t * DMODEL + i];
    __syncthreads();
    const int warp = threadIdx.x >> 5, lane = threadIdx.x & 31;
    for (int o = warp; o < 48; o += 8) {
        int grp = o >> 4, h = o & 15;
        const float* W = (grp == 0) ? Wa : ((grp == 1) ? Wb : Wal);
        float s = 0.f;
        for (int d = lane; d < DMODEL; d += 32) s += xs[d] * W[d * NHQ + h];
#pragma unroll
        for (int off = 16; off > 0; off >>= 1)
            s += __shfl_xor_sync(0xFFFFFFFFu, s, off);
        if (lane == 0) {
            if (grp == 0) {
                float z = s + dt_bias[h];
                float sp = (z > 20.f) ? z : log1pf(expf(z));
                g_glog[t * NHQ + h] = -expf(A_log[h]) * sp;
            } else if (grp == 1) {
                g_beta[t * NHQ + h] = 1.f / (1.f + expf(-(s + bb[h])));
            } else {
                g_alpha[t * NHQ + h] = 1.f / (1.f + expf(-(s + bal[h])));
            }
        }
    }
}

// ---------------- causal depthwise conv(4) + silu ----------------
__global__ void conv_kernel(const float* __restrict__ in, const float* __restrict__ w,
                            float* __restrict__ out, int C, float scale)
{
    int idx = blockIdx.x * blockDim.x + threadIdx.x;
    if (idx >= LSEQ * C) return;
    int t = idx / C, c = idx % C;
    float s = 0.f;
#pragma unroll
    for (int j = 0; j < 4; j++) {
        int tj = t - 3 + j;
        if (tj >= 0) s += in[(size_t)tj * C + c] * w[c * 4 + j];
    }
    float y = s / (1.f + expf(-s));
    out[idx] = y * scale;
}

// ---------------- per-chunk cumsum ----------------
__global__ void cs_kernel()
{
    int id = threadIdx.x;
    int h = id >> 4, n = id & 15;
    float s = 0.f;
    for (int c = 0; c < CLEN; c++) {
        s += g_glog[(n * CLEN + c) * NHQ + h];
        g_cs[(h * NCHUNK + n) * CLEN + c] = s;
    }
    g_G[h * NCHUNK + n] = s;
    g_dgv[h * NCHUNK + n] = expf(s);
}

// -------- dH / dB gram increments via tf32 mma, one block per (h,n) --------
// dH[d][e] = sum_c w[c] K[c][d] K[c][e]; dB likewise with V.
// A[m=d][k=c] = w[c]K[c][d]; B[k=c][n] = K[c][n] (or V).
#define DB_PAD 132
#define DB_SMEM ((2 * 64 * DB_PAD + 64) * 4)

__global__ __launch_bounds__(256, 1) void dhb_tf32()
{
    extern __shared__ float sm[];
    float* ksf = sm;                       // [64][132]
    float* vsf = sm + 64 * DB_PAD;         // [64][132]
    float* ws  = sm + 2 * 64 * DB_PAD;     // [64]
    const int mat = blockIdx.x;
    const int h = mat >> 4, n = mat & 15, hk = h >> 1;
    const int tid = threadIdx.x;
    for (int i = tid; i < CLEN * DHEAD; i += 256) {
        int c = i >> 7, d = i & 127;
        int t = n * CLEN + c;
        ksf[c * DB_PAD + d] = g_k[t * 1024 + hk * DHEAD + d];
        vsf[c * DB_PAD + d] = g_v[t * 1024 + hk * DHEAD + d];
    }
    if (tid < CLEN) {
        float G = g_G[mat];
        float cs = g_cs[mat * CLEN + tid];
        ws[tid] = expf(G - cs) * g_beta[(n * CLEN + tid) * NHQ + h];
    }
    __syncthreads();

    const int warp = tid >> 5, lane = tid & 31;
    const int m0 = warp * 16;
    const int fr = lane >> 2, fc = lane & 3;

    float accH[16][4], accB[16][4];
#pragma unroll
    for (int nt = 0; nt < 16; nt++)
#pragma unroll
        for (int i = 0; i < 4; i++) { accH[nt][i] = 0.f; accB[nt][i] = 0.f; }

#pragma unroll 1
    for (int ks8 = 0; ks8 < 8; ks8++) {
        const int kk = ks8 * 8;
        float w0 = ws[kk + fc], w1 = ws[kk + fc + 4];
        unsigned a0 = f2tf(w0 * ksf[(kk + fc) * DB_PAD + m0 + fr]);
        unsigned a1 = f2tf(w0 * ksf[(kk + fc) * DB_PAD + m0 + fr + 8]);
        unsigned a2 = f2tf(w1 * ksf[(kk + fc + 4) * DB_PAD + m0 + fr]);
        unsigned a3 = f2tf(w1 * ksf[(kk + fc + 4) * DB_PAD + m0 + fr + 8]);
#pragma unroll
        for (int nt = 0; nt < 16; nt++) {
            int cn = nt * 8 + fr;
            unsigned bh0 = f2tf(ksf[(kk + fc) * DB_PAD + cn]);
            unsigned bh1 = f2tf(ksf[(kk + fc + 4) * DB_PAD + cn]);
            MMA_TF32(accH[nt], a0, a1, a2, a3, bh0, bh1);
            unsigned bv0 = f2tf(vsf[(kk + fc) * DB_PAD + cn]);
            unsigned bv1 = f2tf(vsf[(kk + fc + 4) * DB_PAD + cn]);
            MMA_TF32(accB[nt], a0, a1, a2, a3, bv0, bv1);
        }
    }
    size_t base = (size_t)mat * DHEAD * DHEAD;
#pragma unroll
    for (int nt = 0; nt < 16; nt++) {
        int col = nt * 8 + 2 * fc;
        size_t r0 = base + (size_t)(m0 + fr) * 128 + col;
        size_t r1 = base + (size_t)(m0 + fr + 8) * 128 + col;
        *(float2*)&g_dH[r0] = make_float2(accH[nt][0], accH[nt][1]);
        *(float2*)&g_dH[r1] = make_float2(accH[nt][2], accH[nt][3]);
        *(float2*)&g_dB[r0] = make_float2(accB[nt][0], accB[nt][1]);
        *(float2*)&g_dB[r1] = make_float2(accB[nt][2], accB[nt][3]);
    }
}

// ---------------- inter-chunk scan ----------------
__global__ void scan_kernel()
{
    int idx = blockIdx.x * blockDim.x + threadIdx.x;
    int h = idx >> 14;
    int rem = idx & 16383;
    float hc = 0.f, bc = 0.f;
    for (int n = 0; n < NCHUNK; n++) {
        size_t off = (size_t)(h * NCHUNK + n) * 16384 + rem;
        g_H0[off] = hc;
        g_B0[off] = bc;
        float g = g_dgv[h * NCHUNK + n];
        hc = g * hc + g_dH[off];
        bc = g * bc + g_dB[off];
    }
}

// ------- Chebyshev solve: tf32 mma matvec, fp32 recurrence -------
#define CH_APAD 132
#define CH_DPAD 136
#define CH_SMEM (128*CH_APAD*4 + 128*CH_DPAD*4)

__global__ __launch_bounds__(256, 1) void cheb_tf32()
{
    extern __shared__ char smemraw[];
    unsigned (*Ash)[CH_APAD] = (unsigned(*)[CH_APAD])smemraw;
    float (*dsh)[CH_DPAD] = (float(*)[CH_DPAD])(smemraw + 128 * CH_APAD * 4);
    __shared__ float red[128];
    __shared__ float s_lmax;

    const int mat = blockIdx.x;
    const int tid = threadIdx.x;
    const int warp = tid >> 5, lane = tid & 31;
    const int m0 = warp * 16;
    const int fr = lane >> 2, fc = lane & 3;
    const int ro = m0 + fr;
    const float* H0 = g_H0 + (size_t)mat * 16384;
    const float* B0p = g_B0 + (size_t)mat * 16384;

    for (int i = tid; i < 16384; i += 256) {
        int row = i >> 7, col = i & 127;
        float v = H0[i];
        if (row == col) { v += RIDGE_C; red[row] = v; }
        Ash[row][col] = f2tf(v);
    }
    __syncthreads();
    for (int s = 64; s > 0; s >>= 1) {
        if (tid < s) red[tid] += red[tid + s];
        __syncthreads();
    }
    if (tid == 0) s_lmax = red[0];
    __syncthreads();

    const float lmax = s_lmax;
    const float theta = (lmax + RIDGE_C) * 0.5f;
    const float delta = (lmax - RIDGE_C) * 0.5f;
    const float sigma1 = theta / delta;
    float rho = 1.f / sigma1;
    const float inv_theta = 1.f / theta;

    float r_[16][4], x_[16][4];
#pragma unroll
    for (int nt = 0; nt < 16; nt++) {
        int co = nt * 8 + 2 * fc;
        float2 b0 = *(const float2*)&B0p[ro * 128 + co];
        float2 b1 = *(const float2*)&B0p[(ro + 8) * 128 + co];
        r_[nt][0] = b0.x; r_[nt][1] = b0.y; r_[nt][2] = b1.x; r_[nt][3] = b1.y;
        x_[nt][0] = 0.f; x_[nt][1] = 0.f; x_[nt][2] = 0.f; x_[nt][3] = 0.f;
        *(float2*)&dsh[ro][co]     = make_float2(b0.x * inv_theta, b0.y * inv_theta);
        *(float2*)&dsh[ro + 8][co] = make_float2(b1.x * inv_theta, b1.y * inv_theta);
    }
    __syncthreads();

    for (int it = 0; it < NITER; it++) {
        float acc[16][4];
#pragma unroll
        for (int nt = 0; nt < 16; nt++) {
            acc[nt][0] = 0.f; acc[nt][1] = 0.f; acc[nt][2] = 0.f; acc[nt][3] = 0.f;
        }
#pragma unroll 1
        for (int ks = 0; ks < 16; ks++) {
            const int kk = ks * 8;
            unsigned a0 = Ash[m0 + fr][kk + fc];
            unsigned a1 = Ash[m0 + fr + 8][kk + fc];
            unsigned a2 = Ash[m0 + fr][kk + fc + 4];
            unsigned a3 = Ash[m0 + fr + 8][kk + fc + 4];
#pragma unroll
            for (int nt = 0; nt < 16; nt++) {
                unsigned b0 = f2tf(dsh[kk + fc][nt * 8 + fr]);
                unsigned b1 = f2tf(dsh[kk + fc + 4][nt * 8 + fr]);
                MMA_TF32(acc[nt], a0, a1, a2, a3, b0, b1);
            }
        }
        __syncthreads();

        float rho_n = 1.f / (2.f * sigma1 - rho);
        float c1 = rho_n * rho;
        float c2 = 2.f * rho_n / delta;
#pragma unroll
        for (int nt = 0; nt < 16; nt++) {
            int co = nt * 8 + 2 * fc;
            float2 d0 = *(float2*)&dsh[ro][co];
            float2 d1 = *(float2*)&dsh[ro + 8][co];
            x_[nt][0] += d0.x; x_[nt][1] += d0.y;
            x_[nt][2] += d1.x; x_[nt][3] += d1.y;
            r_[nt][0] -= acc[nt][0]; r_[nt][1] -= acc[nt][1];
            r_[nt][2] -= acc[nt][2]; r_[nt][3] -= acc[nt][3];
            d0.x = c1 * d0.x + c2 * r_[nt][0];
            d0.y = c1 * d0.y + c2 * r_[nt][1];
            d1.x = c1 * d1.x + c2 * r_[nt][2];
            d1.y = c1 * d1.y + c2 * r_[nt][3];
            *(float2*)&dsh[ro][co]     = d0;
            *(float2*)&dsh[ro + 8][co] = d1;
        }
        rho = rho_n;
        __syncthreads();
    }

    float* Xp = g_X + (size_t)mat * 16384;
#pragma unroll
    for (int nt = 0; nt < 16; nt++) {
        int co = nt * 8 + 2 * fc;
        *(float2*)&Xp[ro * 128 + co]       = make_float2(x_[nt][0], x_[nt][1]);
        *(float2*)&Xp[(ro + 8) * 128 + co] = make_float2(x_[nt][2], x_[nt][3]);
    }
}

// ---- o: scores + inter + intra via tf32 mma, alpha*v, gated RMSNorm ----
#define OP 132
#define O_SMEM ((3 * 64 * OP + 128 * OP + 64 * OP) * 4)   // 202752

__global__ __launch_bounds__(256, 1) void o_tf32(const float* __restrict__ norm_w)
{
    extern __shared__ float sm[];
    float* qs = sm;                    // [64][132]
    float* ks = sm + 64 * OP;          // [64][132]
    float* vs = sm + 2 * 64 * OP;      // [64][132]
    float* Xs = sm + 3 * 64 * OP;      // [128][132]
    float* Os = sm + 3 * 64 * OP + 128 * OP;  // [64][132]: S, then o
    __shared__ float csh[CLEN], bsh[CLEN], ash[CLEN], expc[CLEN];
    const int mat = blockIdx.x;
    const int h = mat >> 4, n = mat & 15, hk = h >> 1;
    const int tid = threadIdx.x;
    const int warp = tid >> 5, lane = tid & 31;
    const int fr = lane >> 2, fc = lane & 3;

    for (int i = tid; i < CLEN * DHEAD; i += 256) {
        int c = i >> 7, d = i & 127;
        int t = n * CLEN + c;
        qs[c * OP + d] = g_q[t * 2048 + h * DHEAD + d];
        ks[c * OP + d] = g_k[t * 1024 + hk * DHEAD + d];
        vs[c * OP + d] = g_v[t * 1024 + hk * DHEAD + d];
    }
    for (int i = tid; i < 16384; i += 256) {
        int row = i >> 7, col = i & 127;
        Xs[row * OP + col] = g_X[(size_t)mat * 16384 + i];
    }
    if (tid < CLEN) {
        float cv = g_cs[mat * CLEN + tid];
        csh[tid] = cv;
        expc[tid] = expf(cv);
        int t = n * CLEN + tid;
        bsh[tid] = g_beta[t * NHQ + h];
        ash[tid] = g_alpha[t * NHQ + h];
    }
    __syncthreads();

    // Phase B: scores S[c][j] = (q@k^T) * exp(cs_c - cs_j) * beta_j, masked j<=c
    {
        const int m0 = (warp & 3) * 16, n0 = (warp >> 2) * 32;
        float sc[4][4];
#pragma unroll
        for (int nt = 0; nt < 4; nt++)
#pragma unroll
            for (int i = 0; i < 4; i++) sc[nt][i] = 0.f;
#pragma unroll 1
        for (int ks8 = 0; ks8 < 16; ks8++) {
            const int kk = ks8 * 8;
            unsigned a0 = f2tf(qs[(m0 + fr) * OP + kk + fc]);
            unsigned a1 = f2tf(qs[(m0 + fr + 8) * OP + kk + fc]);
            unsigned a2 = f2tf(qs[(m0 + fr) * OP + kk + fc + 4]);
            unsigned a3 = f2tf(qs[(m0 + fr + 8) * OP + kk + fc + 4]);
#pragma unroll
            for (int nt = 0; nt < 4; nt++) {
                int j = n0 + nt * 8 + fr;
                unsigned b0 = f2tf(ks[j * OP + kk + fc]);
                unsigned b1 = f2tf(ks[j * OP + kk + fc + 4]);
                MMA_TF32(sc[nt], a0, a1, a2, a3, b0, b1);
            }
        }
#pragma unroll
        for (int nt = 0; nt < 4; nt++) {
            int j0 = n0 + nt * 8 + 2 * fc;
            int c0 = m0 + fr, c1 = m0 + fr + 8;
#pragma unroll
            for (int e = 0; e < 4; e++) {
                int c = (e < 2) ? c0 : c1;
                int j = j0 + (e & 1);
                float v = 0.f;
                if (j <= c) v = sc[nt][e] * expf(csh[c] - csh[j]) * bsh[j];
                Os[c * OP + j] = v;
            }
        }
    }
    __syncthreads();

    // Phase C: o = (exp(cs)*q) @ X + S @ v
    {
        const int m0 = (warp & 3) * 16, n0 = (warp >> 2) * 64;
        float oa[8][4];
#pragma unroll
        for (int nt = 0; nt < 8; nt++)
#pragma unroll
            for (int i = 0; i < 4; i++) oa[nt][i] = 0.f;
        float e0 = expc[m0 + fr], e1 = expc[m0 + fr + 8];
#pragma unroll 1
        for (int ks8 = 0; ks8 < 16; ks8++) {
            const int kk = ks8 * 8;
            unsigned a0 = f2tf(qs[(m0 + fr) * OP + kk + fc] * e0);
            unsigned a1 = f2tf(qs[(m0 + fr + 8) * OP + kk + fc] * e1);
            unsigned a2 = f2tf(qs[(m0 + fr) * OP + kk + fc + 4] * e0);
            unsigned a3 = f2tf(qs[(m0 + fr + 8) * OP + kk + fc + 4] * e1);
#pragma unroll
            for (int nt = 0; nt < 8; nt++) {
                int cn = n0 + nt * 8 + fr;
                unsigned b0 = f2tf(Xs[(kk + fc) * OP + cn]);
                unsigned b1 = f2tf(Xs[(kk + fc + 4) * OP + cn]);
                MMA_TF32(oa[nt], a0, a1, a2, a3, b0, b1);
            }
        }
#pragma unroll 1
        for (int ks8 = 0; ks8 < 8; ks8++) {
            const int kk = ks8 * 8;
            unsigned a0 = f2tf(Os[(m0 + fr) * OP + kk + fc]);
            unsigned a1 = f2tf(Os[(m0 + fr + 8) * OP + kk + fc]);
            unsigned a2 = f2tf(Os[(m0 + fr) * OP + kk + fc + 4]);
            unsigned a3 = f2tf(Os[(m0 + fr + 8) * OP + kk + fc + 4]);
#pragma unroll
            for (int nt = 0; nt < 8; nt++) {
                int cn = n0 + nt * 8 + fr;
                unsigned b0 = f2tf(vs[(kk + fc) * OP + cn]);
                unsigned b1 = f2tf(vs[(kk + fc + 4) * OP + cn]);
                MMA_TF32(oa[nt], a0, a1, a2, a3, b0, b1);
            }
        }
        __syncthreads();   // all S reads complete before overwrite
        int c0 = m0 + fr, c1 = m0 + fr + 8;
        float al0 = ash[c0], al1 = ash[c1];
#pragma unroll
        for (int nt = 0; nt < 8; nt++) {
            int col = n0 + nt * 8 + 2 * fc;
            Os[c0 * OP + col]     = oa[nt][0] + al0 * vs[c0 * OP + col];
            Os[c0 * OP + col + 1] = oa[nt][1] + al0 * vs[c0 * OP + col + 1];
            Os[c1 * OP + col]     = oa[nt][2] + al1 * vs[c1 * OP + col];
            Os[c1 * OP + col + 1] = oa[nt][3] + al1 * vs[c1 * OP + col + 1];
        }
    }
    __syncthreads();

    // epilogue: gated RMSNorm per row; warp ty owns rows ty*8..+8
    {
        const int ty = warp, tx = lane;
        const int f0 = tx * 4;
        float4 nw = *(const float4*)(norm_w + f0);
#pragma unroll
        for (int i = 0; i < 8; i++) {
            int c = ty * 8 + i;
            int t = n * CLEN + c;
            float4 ov = *(const float4*)&Os[c * OP + f0];
            float ss = ov.x * ov.x + ov.y * ov.y + ov.z * ov.z + ov.w * ov.w;
#pragma unroll
            for (int off = 16; off > 0; off >>= 1)
                ss += __shfl_xor_sync(0xFFFFFFFFu, ss, off);
            float rms = rsqrtf(ss * (1.f / 128.f) + 1e-6f);
            float4 gw = *(const float4*)(&g_gp[(size_t)t * 2048 + h * 128 + f0]);
            float4 o;
            o.x = ov.x * rms * nw.x * (gw.x / (1.f + expf(-gw.x)));
            o.y = ov.y * rms * nw.y * (gw.y / (1.f + expf(-gw.y)));
            o.z = ov.z * rms * nw.z * (gw.z / (1.f + expf(-gw.z)));
            o.w = ov.w * rms * nw.w * (gw.w / (1.f + expf(-gw.w)));
            *(float4*)&g_on[(size_t)t * 2048 + h * DHEAD + f0] = o;
        }
    }
}

// ---------------- launch ----------------
extern "C" void kernel_launch(void* const* d_in, const int* in_sizes, int n_in,
                              void* d_out, int out_size)
{
    const float* x      = (const float*)d_in[0];
    const float* Wq     = (const float*)d_in[1];
    const float* Wk     = (const float*)d_in[2];
    const float* Wv     = (const float*)d_in[3];
    const float* conv_q = (const float*)d_in[4];
    const float* conv_k = (const float*)d_in[5];
    const float* conv_v = (const float*)d_in[6];
    const float* Wa     = (const float*)d_in[7];
    const float* A_log  = (const float*)d_in[8];
    const float* dt_b   = (const float*)d_in[9];
    const float* Wb     = (const float*)d_in[10];
    const float* bb     = (const float*)d_in[11];
    const float* Wal    = (const float*)d_in[12];
    const float* bal    = (const float*)d_in[13];
    const float* Wg     = (const float*)d_in[14];
    const float* norm_w = (const float*)d_in[15];
    const float* Wo     = (const float*)d_in[16];
    float* out = (float*)d_out;

    float *pq, *pk, *pv, *qb, *kb, *vb, *on;
    cudaGetSymbolAddress((void**)&pq, g_pq);
    cudaGetSymbolAddress((void**)&pk, g_pk);
    cudaGetSymbolAddress((void**)&pv, g_pv);
    cudaGetSymbolAddress((void**)&qb, g_q);
    cudaGetSymbolAddress((void**)&kb, g_k);
    cudaGetSymbolAddress((void**)&vb, g_v);
    cudaGetSymbolAddress((void**)&on, g_on);

    cudaFuncSetAttribute(dhb_tf32, cudaFuncAttributeMaxDynamicSharedMemorySize, DB_SMEM);
    cudaFuncSetAttribute(cheb_tf32, cudaFuncAttributeMaxDynamicSharedMemorySize, CH_SMEM);
    cudaFuncSetAttribute(o_tf32, cudaFuncAttributeMaxDynamicSharedMemorySize, O_SMEM);

    gates_kernel<<<1024, 256>>>(x, Wa, A_log, dt_b, Wb, bb, Wal, bal);
    cs_kernel<<<1, 256>>>();
    proj_tf32<<<dim3(48, 8), 256>>>(x, Wq, Wk, Wv, Wg);
    conv_kernel<<<8192, 256>>>(pq, conv_q, qb, 2048, 0.08838834764831843f);
    conv_kernel<<<4096, 256>>>(pk, conv_k, kb, 1024, 1.f);
    conv_kernel<<<4096, 256>>>(pv, conv_v, vb, 1024, 1.f);
    dhb_tf32<<<256, 256, DB_SMEM>>>();
    scan_kernel<<<1024, 256>>>();
    cheb_tf32<<<256, 256, CH_SMEM>>>();
    o_tf32<<<256, 256, O_SMEM>>>(norm_w);
    sgemm_tf32<<<dim3(16, 8), 256>>>(on, Wo, out, 2048, 2048);
}

// round 10
// speedup vs baseline: 3.4804x; 1.2358x over previous
#include <cuda_runtime.h>
#include <math.h>

#define LSEQ 1024
#define DMODEL 2048
#define NHQ 16
#define NHK 8
#define DHEAD 128
#define NCHUNK 16
#define CLEN 64
#define NITER 30
#define RIDGE_C 0.02f

__device__ __forceinline__ unsigned f2tf(float f) {
    unsigned r; asm("cvt.rna.tf32.f32 %0, %1;" : "=r"(r) : "f"(f)); return r;
}
#define MMA_TF32(acc, a0, a1, a2, a3, b0, b1)                               \
    asm volatile(                                                           \
        "mma.sync.aligned.m16n8k8.row.col.f32.tf32.tf32.f32 "               \
        "{%0,%1,%2,%3}, {%4,%5,%6,%7}, {%8,%9}, {%0,%1,%2,%3};"             \
        : "+f"((acc)[0]), "+f"((acc)[1]), "+f"((acc)[2]), "+f"((acc)[3])    \
        : "r"(a0), "r"(a1), "r"(a2), "r"(a3), "r"(b0), "r"(b1))

// ---------------- device scratch ----------------
__device__ float g_pq[LSEQ * 2048];
__device__ float g_pk[LSEQ * 1024];
__device__ float g_pv[LSEQ * 1024];
__device__ float g_q [LSEQ * 2048];
__device__ float g_k [LSEQ * 1024];
__device__ float g_v [LSEQ * 1024];
__device__ float g_gp[LSEQ * 2048];
__device__ float g_gpart[4][LSEQ][48];
__device__ float g_glog [LSEQ * NHQ];
__device__ float g_beta [LSEQ * NHQ];
__device__ float g_alpha[LSEQ * NHQ];
__device__ float g_cs[NHQ * NCHUNK * CLEN];
__device__ float g_G [NHQ * NCHUNK];
__device__ float g_dgv[NHQ * NCHUNK];
__device__ float g_dH[NHQ * NCHUNK * DHEAD * DHEAD];
__device__ float g_dB[NHQ * NCHUNK * DHEAD * DHEAD];
__device__ float g_H0[NHQ * NCHUNK * DHEAD * DHEAD];
__device__ float g_B0[NHQ * NCHUNK * DHEAD * DHEAD];
__device__ float g_X [NHQ * NCHUNK * DHEAD * DHEAD];
__device__ float g_on[LSEQ * 2048];

// -------- tf32 tensor-core GEMM: 128x128 block tile, m16n8k8 mma --------
struct SmemTF32 {
    unsigned As[128][20];
    unsigned Bs[16][136];
};

__device__ __forceinline__ void gemm_tf32_core(
    const float* __restrict__ A, const float* __restrict__ B, float* __restrict__ C,
    int N, int K, int bm, int bn, SmemTF32& s)
{
    const int tid = threadIdx.x;
    const int warp = tid >> 5, lane = tid & 31;
    const int wy = warp >> 1, wx = warp & 1;
    const int m0 = wy * 32, n0 = wx * 64;
    const int r = lane >> 2, c = lane & 3;

    float acc[2][8][4];
#pragma unroll
    for (int mt = 0; mt < 2; mt++)
#pragma unroll
        for (int nt = 0; nt < 8; nt++)
#pragma unroll
            for (int i = 0; i < 4; i++) acc[mt][nt][i] = 0.f;

    const int arow0 = tid >> 2;
    const int aq = (tid & 3) * 4;
    const int bk0 = tid >> 5;
    const int bn4 = (tid & 31) * 4;

    for (int k0 = 0; k0 < K; k0 += 16) {
#pragma unroll
        for (int it = 0; it < 2; it++) {
            int row = arow0 + it * 64;
            float4 va = *(const float4*)(A + (size_t)(bm + row) * K + k0 + aq);
            s.As[row][aq + 0] = f2tf(va.x);
            s.As[row][aq + 1] = f2tf(va.y);
            s.As[row][aq + 2] = f2tf(va.z);
            s.As[row][aq + 3] = f2tf(va.w);
        }
#pragma unroll
        for (int it = 0; it < 2; it++) {
            int kk = bk0 + it * 8;
            float4 vb = *(const float4*)(B + (size_t)(k0 + kk) * N + bn + bn4);
            s.Bs[kk][bn4 + 0] = f2tf(vb.x);
            s.Bs[kk][bn4 + 1] = f2tf(vb.y);
            s.Bs[kk][bn4 + 2] = f2tf(vb.z);
            s.Bs[kk][bn4 + 3] = f2tf(vb.w);
        }
        __syncthreads();
#pragma unroll
        for (int ks = 0; ks < 2; ks++) {
            const int kk = ks * 8;
            unsigned a[2][4];
#pragma unroll
            for (int mt = 0; mt < 2; mt++) {
                int mr = m0 + mt * 16;
                a[mt][0] = s.As[mr + r][kk + c];
                a[mt][1] = s.As[mr + r + 8][kk + c];
                a[mt][2] = s.As[mr + r][kk + c + 4];
                a[mt][3] = s.As[mr + r + 8][kk + c + 4];
            }
#pragma unroll
            for (int nt = 0; nt < 8; nt++) {
                unsigned b0 = s.Bs[kk + c][n0 + nt * 8 + r];
                unsigned b1 = s.Bs[kk + c + 4][n0 + nt * 8 + r];
#pragma unroll
                for (int mt = 0; mt < 2; mt++)
                    MMA_TF32(acc[mt][nt], a[mt][0], a[mt][1], a[mt][2], a[mt][3], b0, b1);
            }
        }
        __syncthreads();
    }
#pragma unroll
    for (int mt = 0; mt < 2; mt++) {
        int mr = bm + m0 + mt * 16 + r;
#pragma unroll
        for (int nt = 0; nt < 8; nt++) {
            int col = bn + n0 + nt * 8 + 2 * c;
            *(float2*)(C + (size_t)mr * N + col) =
                make_float2(acc[mt][nt][0], acc[mt][nt][1]);
            *(float2*)(C + (size_t)(mr + 8) * N + col) =
                make_float2(acc[mt][nt][2], acc[mt][nt][3]);
        }
    }
}

__global__ __launch_bounds__(256) void sgemm_tf32(
    const float* __restrict__ A, const float* __restrict__ B,
    float* __restrict__ C, int N, int K)
{
    __shared__ SmemTF32 s;
    gemm_tf32_core(A, B, C, N, K, blockIdx.y * 128, blockIdx.x * 128, s);
}

__global__ __launch_bounds__(256) void proj_tf32(
    const float* __restrict__ x,
    const float* __restrict__ Wq, const float* __restrict__ Wk,
    const float* __restrict__ Wv, const float* __restrict__ Wg)
{
    __shared__ SmemTF32 s;
    const int bx = blockIdx.x;
    const float* B; float* C; int N, bn;
    if (bx < 16)      { B = Wq; C = g_pq; N = 2048; bn = bx * 128; }
    else if (bx < 24) { B = Wk; C = g_pk; N = 1024; bn = (bx - 16) * 128; }
    else if (bx < 32) { B = Wv; C = g_pv; N = 1024; bn = (bx - 24) * 128; }
    else              { B = Wg; C = g_gp; N = 2048; bn = (bx - 32) * 128; }
    gemm_tf32_core(x, B, C, N, DMODEL, blockIdx.y * 128, bn, s);
}

// ------- gates as GEMM: x[1024,2048] @ [Wa|Wb|Wal][2048,48], K split 4 -------
__global__ __launch_bounds__(256) void gates_mm(
    const float* __restrict__ x, const float* __restrict__ Wa,
    const float* __restrict__ Wb, const float* __restrict__ Wal)
{
    __shared__ float xs[16][132];   // [kk][row]
    __shared__ float Ws[16][52];    // [kk][48 cols]
    const int bm = blockIdx.x * 128;
    const int k0 = blockIdx.y * 512;
    const int tid = threadIdx.x;
    const int row = tid >> 1, kq = (tid & 1) * 8;
    const int wk = tid >> 4, wh = tid & 15;
    const int ty = tid >> 3, tx = tid & 7;   // rows ty*4..+4, cols tx*6..+6

    float acc[4][6];
#pragma unroll
    for (int i = 0; i < 4; i++)
#pragma unroll
        for (int j = 0; j < 6; j++) acc[i][j] = 0.f;

    for (int kt = 0; kt < 512; kt += 16) {
        const int kb = k0 + kt;
        float4 v0 = *(const float4*)(x + (size_t)(bm + row) * DMODEL + kb + kq);
        float4 v1 = *(const float4*)(x + (size_t)(bm + row) * DMODEL + kb + kq + 4);
        xs[kq + 0][row] = v0.x; xs[kq + 1][row] = v0.y;
        xs[kq + 2][row] = v0.z; xs[kq + 3][row] = v0.w;
        xs[kq + 4][row] = v1.x; xs[kq + 5][row] = v1.y;
        xs[kq + 6][row] = v1.z; xs[kq + 7][row] = v1.w;
        Ws[wk][wh]      = Wa[(size_t)(kb + wk) * NHQ + wh];
        Ws[wk][16 + wh] = Wb[(size_t)(kb + wk) * NHQ + wh];
        Ws[wk][32 + wh] = Wal[(size_t)(kb + wk) * NHQ + wh];
        __syncthreads();
#pragma unroll
        for (int kk = 0; kk < 16; kk++) {
            float a[4], b[6];
#pragma unroll
            for (int i = 0; i < 4; i++) a[i] = xs[kk][ty * 4 + i];
#pragma unroll
            for (int j = 0; j < 6; j++) b[j] = Ws[kk][tx * 6 + j];
#pragma unroll
            for (int i = 0; i < 4; i++)
#pragma unroll
                for (int j = 0; j < 6; j++) acc[i][j] += a[i] * b[j];
        }
        __syncthreads();
    }
#pragma unroll
    for (int i = 0; i < 4; i++)
#pragma unroll
        for (int j = 0; j < 6; j++)
            g_gpart[blockIdx.y][bm + ty * 4 + i][tx * 6 + j] = acc[i][j];
}

__global__ void gates_ep(
    const float* __restrict__ A_log, const float* __restrict__ dt_bias,
    const float* __restrict__ bb, const float* __restrict__ bal)
{
    int idx = blockIdx.x * 256 + threadIdx.x;   // 1024*48
    if (idx >= LSEQ * 48) return;
    int t = idx / 48, j = idx % 48;
    float s = g_gpart[0][t][j] + g_gpart[1][t][j]
            + g_gpart[2][t][j] + g_gpart[3][t][j];
    if (j < 16) {
        float z = s + dt_bias[j];
        float sp = (z > 20.f) ? z : log1pf(expf(z));
        g_glog[t * NHQ + j] = -expf(A_log[j]) * sp;
    } else if (j < 32) {
        int h = j - 16;
        g_beta[t * NHQ + h] = 1.f / (1.f + expf(-(s + bb[h])));
    } else {
        int h = j - 32;
        g_alpha[t * NHQ + h] = 1.f / (1.f + expf(-(s + bal[h])));
    }
}

// ---------------- causal depthwise conv(4) + silu ----------------
__global__ void conv_kernel(const float* __restrict__ in, const float* __restrict__ w,
                            float* __restrict__ out, int C, float scale)
{
    int idx = blockIdx.x * blockDim.x + threadIdx.x;
    if (idx >= LSEQ * C) return;
    int t = idx / C, c = idx % C;
    float s = 0.f;
#pragma unroll
    for (int j = 0; j < 4; j++) {
        int tj = t - 3 + j;
        if (tj >= 0) s += in[(size_t)tj * C + c] * w[c * 4 + j];
    }
    float y = s / (1.f + expf(-s));
    out[idx] = y * scale;
}

// fused k+v conv (both C=1024, scale 1)
__global__ void convkv_kernel(const float* __restrict__ wk, const float* __restrict__ wv)
{
    int idx = blockIdx.x * 256 + threadIdx.x;    // 2*1024*1024
    const float* in; const float* w; float* out;
    int id2 = idx;
    if (idx >= LSEQ * 1024) { in = g_pv; w = wv; out = g_v; id2 -= LSEQ * 1024; }
    else                    { in = g_pk; w = wk; out = g_k; }
    int t = id2 >> 10, c = id2 & 1023;
    float s = 0.f;
#pragma unroll
    for (int j = 0; j < 4; j++) {
        int tj = t - 3 + j;
        if (tj >= 0) s += in[(size_t)tj * 1024 + c] * w[c * 4 + j];
    }
    out[id2] = s / (1.f + expf(-s));
}

// ---------------- per-chunk cumsum ----------------
__global__ void cs_kernel()
{
    int id = threadIdx.x;
    int h = id >> 4, n = id & 15;
    float s = 0.f;
    for (int c = 0; c < CLEN; c++) {
        s += g_glog[(n * CLEN + c) * NHQ + h];
        g_cs[(h * NCHUNK + n) * CLEN + c] = s;
    }
    g_G[h * NCHUNK + n] = s;
    g_dgv[h * NCHUNK + n] = expf(s);
}

// -------- dH / dB gram increments via tf32 mma --------
#define DB_PAD 132
#define DB_SMEM ((2 * 64 * DB_PAD + 64) * 4)

__global__ __launch_bounds__(256, 1) void dhb_tf32()
{
    extern __shared__ float sm[];
    float* ksf = sm;
    float* vsf = sm + 64 * DB_PAD;
    float* ws  = sm + 2 * 64 * DB_PAD;
    const int mat = blockIdx.x;
    const int h = mat >> 4, n = mat & 15, hk = h >> 1;
    const int tid = threadIdx.x;
    for (int i = tid; i < CLEN * DHEAD; i += 256) {
        int c = i >> 7, d = i & 127;
        int t = n * CLEN + c;
        ksf[c * DB_PAD + d] = g_k[t * 1024 + hk * DHEAD + d];
        vsf[c * DB_PAD + d] = g_v[t * 1024 + hk * DHEAD + d];
    }
    if (tid < CLEN) {
        float G = g_G[mat];
        float cs = g_cs[mat * CLEN + tid];
        ws[tid] = expf(G - cs) * g_beta[(n * CLEN + tid) * NHQ + h];
    }
    __syncthreads();

    const int warp = tid >> 5, lane = tid & 31;
    const int m0 = warp * 16;
    const int fr = lane >> 2, fc = lane & 3;

    float accH[16][4], accB[16][4];
#pragma unroll
    for (int nt = 0; nt < 16; nt++)
#pragma unroll
        for (int i = 0; i < 4; i++) { accH[nt][i] = 0.f; accB[nt][i] = 0.f; }

#pragma unroll 1
    for (int ks8 = 0; ks8 < 8; ks8++) {
        const int kk = ks8 * 8;
        float w0 = ws[kk + fc], w1 = ws[kk + fc + 4];
        unsigned a0 = f2tf(w0 * ksf[(kk + fc) * DB_PAD + m0 + fr]);
        unsigned a1 = f2tf(w0 * ksf[(kk + fc) * DB_PAD + m0 + fr + 8]);
        unsigned a2 = f2tf(w1 * ksf[(kk + fc + 4) * DB_PAD + m0 + fr]);
        unsigned a3 = f2tf(w1 * ksf[(kk + fc + 4) * DB_PAD + m0 + fr + 8]);
#pragma unroll
        for (int nt = 0; nt < 16; nt++) {
            int cn = nt * 8 + fr;
            unsigned bh0 = f2tf(ksf[(kk + fc) * DB_PAD + cn]);
            unsigned bh1 = f2tf(ksf[(kk + fc + 4) * DB_PAD + cn]);
            MMA_TF32(accH[nt], a0, a1, a2, a3, bh0, bh1);
            unsigned bv0 = f2tf(vsf[(kk + fc) * DB_PAD + cn]);
            unsigned bv1 = f2tf(vsf[(kk + fc + 4) * DB_PAD + cn]);
            MMA_TF32(accB[nt], a0, a1, a2, a3, bv0, bv1);
        }
    }
    size_t base = (size_t)mat * DHEAD * DHEAD;
#pragma unroll
    for (int nt = 0; nt < 16; nt++) {
        int col = nt * 8 + 2 * fc;
        size_t r0 = base + (size_t)(m0 + fr) * 128 + col;
        size_t r1 = base + (size_t)(m0 + fr + 8) * 128 + col;
        *(float2*)&g_dH[r0] = make_float2(accH[nt][0], accH[nt][1]);
        *(float2*)&g_dH[r1] = make_float2(accH[nt][2], accH[nt][3]);
        *(float2*)&g_dB[r0] = make_float2(accB[nt][0], accB[nt][1]);
        *(float2*)&g_dB[r1] = make_float2(accB[nt][2], accB[nt][3]);
    }
}

// ---------------- inter-chunk scan ----------------
__global__ void scan_kernel()
{
    int idx = blockIdx.x * blockDim.x + threadIdx.x;
    int h = idx >> 14;
    int rem = idx & 16383;
    float hc = 0.f, bc = 0.f;
    for (int n = 0; n < NCHUNK; n++) {
        size_t off = (size_t)(h * NCHUNK + n) * 16384 + rem;
        g_H0[off] = hc;
        g_B0[off] = bc;
        float g = g_dgv[h * NCHUNK + n];
        hc = g * hc + g_dH[off];
        bc = g * bc + g_dB[off];
    }
}

// ------- Chebyshev solve: tf32 mma matvec, d stored tf32-rounded -------
#define CH_APAD 132
#define CH_DPAD 136
#define CH_SMEM (128*CH_APAD*4 + 128*CH_DPAD*4)

__global__ __launch_bounds__(256, 1) void cheb_tf32()
{
    extern __shared__ char smemraw[];
    unsigned (*Ash)[CH_APAD] = (unsigned(*)[CH_APAD])smemraw;
    float (*dsh)[CH_DPAD] = (float(*)[CH_DPAD])(smemraw + 128 * CH_APAD * 4);
    __shared__ float red[128];
    __shared__ float s_lmax;

    const int mat = blockIdx.x;
    const int tid = threadIdx.x;
    const int warp = tid >> 5, lane = tid & 31;
    const int m0 = warp * 16;
    const int fr = lane >> 2, fc = lane & 3;
    const int ro = m0 + fr;
    const float* H0 = g_H0 + (size_t)mat * 16384;
    const float* B0p = g_B0 + (size_t)mat * 16384;

    for (int i = tid; i < 16384; i += 256) {
        int row = i >> 7, col = i & 127;
        float v = H0[i];
        if (row == col) { v += RIDGE_C; red[row] = v; }
        Ash[row][col] = f2tf(v);
    }
    __syncthreads();
    for (int s = 64; s > 0; s >>= 1) {
        if (tid < s) red[tid] += red[tid + s];
        __syncthreads();
    }
    if (tid == 0) s_lmax = red[0];
    __syncthreads();

    const float lmax = s_lmax;
    const float theta = (lmax + RIDGE_C) * 0.5f;
    const float delta = (lmax - RIDGE_C) * 0.5f;
    const float sigma1 = theta / delta;
    float rho = 1.f / sigma1;
    const float inv_theta = 1.f / theta;

    float r_[16][4], x_[16][4];
#pragma unroll
    for (int nt = 0; nt < 16; nt++) {
        int co = nt * 8 + 2 * fc;
        float2 b0 = *(const float2*)&B0p[ro * 128 + co];
        float2 b1 = *(const float2*)&B0p[(ro + 8) * 128 + co];
        r_[nt][0] = b0.x; r_[nt][1] = b0.y; r_[nt][2] = b1.x; r_[nt][3] = b1.y;
        x_[nt][0] = 0.f; x_[nt][1] = 0.f; x_[nt][2] = 0.f; x_[nt][3] = 0.f;
        *(float2*)&dsh[ro][co] = make_float2(
            __uint_as_float(f2tf(b0.x * inv_theta)),
            __uint_as_float(f2tf(b0.y * inv_theta)));
        *(float2*)&dsh[ro + 8][co] = make_float2(
            __uint_as_float(f2tf(b1.x * inv_theta)),
            __uint_as_float(f2tf(b1.y * inv_theta)));
    }
    __syncthreads();

    for (int it = 0; it < NITER; it++) {
        float acc[16][4];
#pragma unroll
        for (int nt = 0; nt < 16; nt++) {
            acc[nt][0] = 0.f; acc[nt][1] = 0.f; acc[nt][2] = 0.f; acc[nt][3] = 0.f;
        }
#pragma unroll 1
        for (int ks = 0; ks < 16; ks++) {
            const int kk = ks * 8;
            unsigned a0 = Ash[m0 + fr][kk + fc];
            unsigned a1 = Ash[m0 + fr + 8][kk + fc];
            unsigned a2 = Ash[m0 + fr][kk + fc + 4];
            unsigned a3 = Ash[m0 + fr + 8][kk + fc + 4];
#pragma unroll
            for (int nt = 0; nt < 16; nt++) {
                unsigned b0 = __float_as_uint(dsh[kk + fc][nt * 8 + fr]);
                unsigned b1 = __float_as_uint(dsh[kk + fc + 4][nt * 8 + fr]);
                MMA_TF32(acc[nt], a0, a1, a2, a3, b0, b1);
            }
        }
        __syncthreads();

        float rho_n = 1.f / (2.f * sigma1 - rho);
        float c1 = rho_n * rho;
        float c2 = 2.f * rho_n / delta;
#pragma unroll
        for (int nt = 0; nt < 16; nt++) {
            int co = nt * 8 + 2 * fc;
            float2 d0 = *(float2*)&dsh[ro][co];
            float2 d1 = *(float2*)&dsh[ro + 8][co];
            x_[nt][0] += d0.x; x_[nt][1] += d0.y;
            x_[nt][2] += d1.x; x_[nt][3] += d1.y;
            r_[nt][0] -= acc[nt][0]; r_[nt][1] -= acc[nt][1];
            r_[nt][2] -= acc[nt][2]; r_[nt][3] -= acc[nt][3];
            d0.x = __uint_as_float(f2tf(c1 * d0.x + c2 * r_[nt][0]));
            d0.y = __uint_as_float(f2tf(c1 * d0.y + c2 * r_[nt][1]));
            d1.x = __uint_as_float(f2tf(c1 * d1.x + c2 * r_[nt][2]));
            d1.y = __uint_as_float(f2tf(c1 * d1.y + c2 * r_[nt][3]));
            *(float2*)&dsh[ro][co]     = d0;
            *(float2*)&dsh[ro + 8][co] = d1;
        }
        rho = rho_n;
        __syncthreads();
    }

    float* Xp = g_X + (size_t)mat * 16384;
#pragma unroll
    for (int nt = 0; nt < 16; nt++) {
        int co = nt * 8 + 2 * fc;
        *(float2*)&Xp[ro * 128 + co]       = make_float2(x_[nt][0], x_[nt][1]);
        *(float2*)&Xp[(ro + 8) * 128 + co] = make_float2(x_[nt][2], x_[nt][3]);
    }
}

// ---- o: scores + inter + intra via tf32 mma, alpha*v, gated RMSNorm ----
#define OP 132
#define O_SMEM ((3 * 64 * OP + 128 * OP + 64 * OP) * 4)

__global__ __launch_bounds__(256, 1) void o_tf32(const float* __restrict__ norm_w)
{
    extern __shared__ float sm[];
    float* qs = sm;
    float* ks = sm + 64 * OP;
    float* vs = sm + 2 * 64 * OP;
    float* Xs = sm + 3 * 64 * OP;
    float* Os = sm + 3 * 64 * OP + 128 * OP;
    __shared__ float csh[CLEN], bsh[CLEN], ash[CLEN], expc[CLEN];
    const int mat = blockIdx.x;
    const int h = mat >> 4, n = mat & 15, hk = h >> 1;
    const int tid = threadIdx.x;
    const int warp = tid >> 5, lane = tid & 31;
    const int fr = lane >> 2, fc = lane & 3;

    for (int i = tid; i < CLEN * DHEAD; i += 256) {
        int c = i >> 7, d = i & 127;
        int t = n * CLEN + c;
        qs[c * OP + d] = g_q[t * 2048 + h * DHEAD + d];
        ks[c * OP + d] = g_k[t * 1024 + hk * DHEAD + d];
        vs[c * OP + d] = g_v[t * 1024 + hk * DHEAD + d];
    }
    for (int i = tid; i < 16384; i += 256) {
        int row = i >> 7, col = i & 127;
        Xs[row * OP + col] = g_X[(size_t)mat * 16384 + i];
    }
    if (tid < CLEN) {
        float cv = g_cs[mat * CLEN + tid];
        csh[tid] = cv;
        expc[tid] = expf(cv);
        int t = n * CLEN + tid;
        bsh[tid] = g_beta[t * NHQ + h];
        ash[tid] = g_alpha[t * NHQ + h];
    }
    __syncthreads();

    {
        const int m0 = (warp & 3) * 16, n0 = (warp >> 2) * 32;
        float sc[4][4];
#pragma unroll
        for (int nt = 0; nt < 4; nt++)
#pragma unroll
            for (int i = 0; i < 4; i++) sc[nt][i] = 0.f;
#pragma unroll 1
        for (int ks8 = 0; ks8 < 16; ks8++) {
            const int kk = ks8 * 8;
            unsigned a0 = f2tf(qs[(m0 + fr) * OP + kk + fc]);
            unsigned a1 = f2tf(qs[(m0 + fr + 8) * OP + kk + fc]);
            unsigned a2 = f2tf(qs[(m0 + fr) * OP + kk + fc + 4]);
            unsigned a3 = f2tf(qs[(m0 + fr + 8) * OP + kk + fc + 4]);
#pragma unroll
            for (int nt = 0; nt < 4; nt++) {
                int j = n0 + nt * 8 + fr;
                unsigned b0 = f2tf(ks[j * OP + kk + fc]);
                unsigned b1 = f2tf(ks[j * OP + kk + fc + 4]);
                MMA_TF32(sc[nt], a0, a1, a2, a3, b0, b1);
            }
        }
#pragma unroll
        for (int nt = 0; nt < 4; nt++) {
            int j0 = n0 + nt * 8 + 2 * fc;
            int c0 = m0 + fr, c1 = m0 + fr + 8;
#pragma unroll
            for (int e = 0; e < 4; e++) {
                int c = (e < 2) ? c0 : c1;
                int j = j0 + (e & 1);
                float v = 0.f;
                if (j <= c) v = sc[nt][e] * expf(csh[c] - csh[j]) * bsh[j];
                Os[c * OP + j] = v;
            }
        }
    }
    __syncthreads();

    {
        const int m0 = (warp & 3) * 16, n0 = (warp >> 2) * 64;
        float oa[8][4];
#pragma unroll
        for (int nt = 0; nt < 8; nt++)
#pragma unroll
            for (int i = 0; i < 4; i++) oa[nt][i] = 0.f;
        float e0 = expc[m0 + fr], e1 = expc[m0 + fr + 8];
#pragma unroll 1
        for (int ks8 = 0; ks8 < 16; ks8++) {
            const int kk = ks8 * 8;
            unsigned a0 = f2tf(qs[(m0 + fr) * OP + kk + fc] * e0);
            unsigned a1 = f2tf(qs[(m0 + fr + 8) * OP + kk + fc] * e1);
            unsigned a2 = f2tf(qs[(m0 + fr) * OP + kk + fc + 4] * e0);
            unsigned a3 = f2tf(qs[(m0 + fr + 8) * OP + kk + fc + 4] * e1);
#pragma unroll
            for (int nt = 0; nt < 8; nt++) {
                int cn = n0 + nt * 8 + fr;
                unsigned b0 = f2tf(Xs[(kk + fc) * OP + cn]);
                unsigned b1 = f2tf(Xs[(kk + fc + 4) * OP + cn]);
                MMA_TF32(oa[nt], a0, a1, a2, a3, b0, b1);
            }
        }
#pragma unroll 1
        for (int ks8 = 0; ks8 < 8; ks8++) {
            const int kk = ks8 * 8;
            unsigned a0 = f2tf(Os[(m0 + fr) * OP + kk + fc]);
            unsigned a1 = f2tf(Os[(m0 + fr + 8) * OP + kk + fc]);
            unsigned a2 = f2tf(Os[(m0 + fr) * OP + kk + fc + 4]);
            unsigned a3 = f2tf(Os[(m0 + fr + 8) * OP + kk + fc + 4]);
#pragma unroll
            for (int nt = 0; nt < 8; nt++) {
                int cn = n0 + nt * 8 + fr;
                unsigned b0 = f2tf(vs[(kk + fc) * OP + cn]);
                unsigned b1 = f2tf(vs[(kk + fc + 4) * OP + cn]);
                MMA_TF32(oa[nt], a0, a1, a2, a3, b0, b1);
            }
        }
        __syncthreads();
        int c0 = m0 + fr, c1 = m0 + fr + 8;
        float al0 = ash[c0], al1 = ash[c1];
#pragma unroll
        for (int nt = 0; nt < 8; nt++) {
            int col = n0 + nt * 8 + 2 * fc;
            Os[c0 * OP + col]     = oa[nt][0] + al0 * vs[c0 * OP + col];
            Os[c0 * OP + col + 1] = oa[nt][1] + al0 * vs[c0 * OP + col + 1];
            Os[c1 * OP + col]     = oa[nt][2] + al1 * vs[c1 * OP + col];
            Os[c1 * OP + col + 1] = oa[nt][3] + al1 * vs[c1 * OP + col + 1];
        }
    }
    __syncthreads();

    {
        const int ty = warp, tx = lane;
        const int f0 = tx * 4;
        float4 nw = *(const float4*)(norm_w + f0);
#pragma unroll
        for (int i = 0; i < 8; i++) {
            int c = ty * 8 + i;
            int t = n * CLEN + c;
            float4 ov = *(const float4*)&Os[c * OP + f0];
            float ss = ov.x * ov.x + ov.y * ov.y + ov.z * ov.z + ov.w * ov.w;
#pragma unroll
            for (int off = 16; off > 0; off >>= 1)
                ss += __shfl_xor_sync(0xFFFFFFFFu, ss, off);
            float rms = rsqrtf(ss * (1.f / 128.f) + 1e-6f);
            float4 gw = *(const float4*)(&g_gp[(size_t)t * 2048 + h * 128 + f0]);
            float4 o;
            o.x = ov.x * rms * nw.x * (gw.x / (1.f + expf(-gw.x)));
            o.y = ov.y * rms * nw.y * (gw.y / (1.f + expf(-gw.y)));
            o.z = ov.z * rms * nw.z * (gw.z / (1.f + expf(-gw.z)));
            o.w = ov.w * rms * nw.w * (gw.w / (1.f + expf(-gw.w)));
            *(float4*)&g_on[(size_t)t * 2048 + h * DHEAD + f0] = o;
        }
    }
}

// ---------------- launch ----------------
extern "C" void kernel_launch(void* const* d_in, const int* in_sizes, int n_in,
                              void* d_out, int out_size)
{
    const float* x      = (const float*)d_in[0];
    const float* Wq     = (const float*)d_in[1];
    const float* Wk     = (const float*)d_in[2];
    const float* Wv     = (const float*)d_in[3];
    const float* conv_q = (const float*)d_in[4];
    const float* conv_k = (const float*)d_in[5];
    const float* conv_v = (const float*)d_in[6];
    const float* Wa     = (const float*)d_in[7];
    const float* A_log  = (const float*)d_in[8];
    const float* dt_b   = (const float*)d_in[9];
    const float* Wb     = (const float*)d_in[10];
    const float* bb     = (const float*)d_in[11];
    const float* Wal    = (const float*)d_in[12];
    const float* bal    = (const float*)d_in[13];
    const float* Wg     = (const float*)d_in[14];
    const float* norm_w = (const float*)d_in[15];
    const float* Wo     = (const float*)d_in[16];
    float* out = (float*)d_out;

    float *pq, *qb, *on;
    cudaGetSymbolAddress((void**)&pq, g_pq);
    cudaGetSymbolAddress((void**)&qb, g_q);
    cudaGetSymbolAddress((void**)&on, g_on);

    cudaFuncSetAttribute(dhb_tf32, cudaFuncAttributeMaxDynamicSharedMemorySize, DB_SMEM);
    cudaFuncSetAttribute(cheb_tf32, cudaFuncAttributeMaxDynamicSharedMemorySize, CH_SMEM);
    cudaFuncSetAttribute(o_tf32, cudaFuncAttributeMaxDynamicSharedMemorySize, O_SMEM);

    gates_mm<<<dim3(8, 4), 256>>>(x, Wa, Wb, Wal);            // 0
    gates_ep<<<192, 256>>>(A_log, dt_b, bb, bal);             // 1
    cs_kernel<<<1, 256>>>();                                  // 2
    proj_tf32<<<dim3(48, 8), 256>>>(x, Wq, Wk, Wv, Wg);       // 3
    convkv_kernel<<<8192, 256>>>(conv_k, conv_v);             // 4
    dhb_tf32<<<256, 256, DB_SMEM>>>();                        // 5  <- ncu capture
    conv_kernel<<<8192, 256>>>(pq, conv_q, qb, 2048, 0.08838834764831843f); // 6
    scan_kernel<<<1024, 256>>>();                             // 7
    cheb_tf32<<<256, 256, CH_SMEM>>>();                       // 8
    o_tf32<<<256, 256, O_SMEM>>>(norm_w);                     // 9
    sgemm_tf32<<<dim3(16, 8), 256>>>(on, Wo, out, 2048, 2048);// 10
}

// round 11
// speedup vs baseline: 4.3200x; 1.2412x over previous
#include <cuda_runtime.h>
#include <math.h>

#define LSEQ 1024
#define DMODEL 2048
#define NHQ 16
#define NHK 8
#define DHEAD 128
#define NCHUNK 16
#define CLEN 64
#define NITER 30
#define RIDGE_C 0.02f

__device__ __forceinline__ unsigned f2tf(float f) {
    unsigned r; asm("cvt.rna.tf32.f32 %0, %1;" : "=r"(r) : "f"(f)); return r;
}
#define MMA_TF32(acc, a0, a1, a2, a3, b0, b1)                               \
    asm volatile(                                                           \
        "mma.sync.aligned.m16n8k8.row.col.f32.tf32.tf32.f32 "               \
        "{%0,%1,%2,%3}, {%4,%5,%6,%7}, {%8,%9}, {%0,%1,%2,%3};"             \
        : "+f"((acc)[0]), "+f"((acc)[1]), "+f"((acc)[2]), "+f"((acc)[3])    \
        : "r"(a0), "r"(a1), "r"(a2), "r"(a3), "r"(b0), "r"(b1))

__device__ __forceinline__ void cp_async16(void* smem_dst, const void* gmem_src) {
    unsigned sa = (unsigned)__cvta_generic_to_shared(smem_dst);
    asm volatile("cp.async.ca.shared.global [%0], [%1], 16;" :: "r"(sa), "l"(gmem_src));
}
__device__ __forceinline__ void cp_commit() {
    asm volatile("cp.async.commit_group;");
}
template<int NWAIT>
__device__ __forceinline__ void cp_wait() {
    asm volatile("cp.async.wait_group %0;" :: "n"(NWAIT));
}

// ---------------- device scratch ----------------
__device__ float g_pq[LSEQ * 2048];
__device__ float g_pk[LSEQ * 1024];
__device__ float g_pv[LSEQ * 1024];
__device__ float g_q [LSEQ * 2048];
__device__ float g_k [LSEQ * 1024];
__device__ float g_v [LSEQ * 1024];
__device__ float g_gp[LSEQ * 2048];
__device__ float g_gpart[4][LSEQ][48];
__device__ float g_glog [LSEQ * NHQ];
__device__ float g_beta [LSEQ * NHQ];
__device__ float g_alpha[LSEQ * NHQ];
__device__ float g_cs[NHQ * NCHUNK * CLEN];
__device__ float g_G [NHQ * NCHUNK];
__device__ float g_dgv[NHQ * NCHUNK];
__device__ float g_dH[NHQ * NCHUNK * DHEAD * DHEAD];
__device__ float g_dB[NHQ * NCHUNK * DHEAD * DHEAD];
__device__ float g_H0[NHQ * NCHUNK * DHEAD * DHEAD];
__device__ float g_B0[NHQ * NCHUNK * DHEAD * DHEAD];
__device__ float g_X [NHQ * NCHUNK * DHEAD * DHEAD];
__device__ float g_on[LSEQ * 2048];

// -- tf32 GEMM: 128x128 tile, m16n8k8, cp.async double-buffered fp32 stage --
struct SmemTF32 {
    float As[2][128][20];   // [buf][m][k] pad 20 -> conflict-free frags
    float Bs[2][16][136];   // [buf][k][n] pad 136
};

__device__ __forceinline__ void gemm_tf32_core(
    const float* __restrict__ A, const float* __restrict__ B, float* __restrict__ C,
    int N, int K, int bm, int bn, SmemTF32& s)
{
    const int tid = threadIdx.x;
    const int warp = tid >> 5, lane = tid & 31;
    const int wy = warp >> 1, wx = warp & 1;
    const int m0 = wy * 32, n0 = wx * 64;
    const int r = lane >> 2, c = lane & 3;

    float acc[2][8][4];
#pragma unroll
    for (int mt = 0; mt < 2; mt++)
#pragma unroll
        for (int nt = 0; nt < 8; nt++)
#pragma unroll
            for (int i = 0; i < 4; i++) acc[mt][nt][i] = 0.f;

    const int arow0 = tid >> 2;        // 0..63 (rows +0 and +64)
    const int aq = (tid & 3) * 4;      // 0,4,8,12
    const int bk0 = tid >> 5;          // 0..7 (kk +0 and +8)
    const int bn4 = (tid & 31) * 4;    // 0..124

    const float* Ap0 = A + (size_t)(bm + arow0) * K + aq;
    const float* Ap1 = A + (size_t)(bm + arow0 + 64) * K + aq;
    const float* Bp0 = B + (size_t)bk0 * N + bn + bn4;
    const float* Bp1 = B + (size_t)(bk0 + 8) * N + bn + bn4;

    // stage tile 0
    cp_async16(&s.As[0][arow0][aq], Ap0);
    cp_async16(&s.As[0][arow0 + 64][aq], Ap1);
    cp_async16(&s.Bs[0][bk0][bn4], Bp0);
    cp_async16(&s.Bs[0][bk0 + 8][bn4], Bp1);
    cp_commit();
    cp_wait<0>();
    __syncthreads();

    const int nk = K >> 4;
    for (int t = 0; t < nk; t++) {
        const int cur = t & 1, nb = cur ^ 1;
        const bool more = (t + 1 < nk);
        if (more) {
            int k0 = (t + 1) << 4;
            cp_async16(&s.As[nb][arow0][aq], Ap0 + k0);
            cp_async16(&s.As[nb][arow0 + 64][aq], Ap1 + k0);
            cp_async16(&s.Bs[nb][bk0][bn4], Bp0 + (size_t)k0 * N);
            cp_async16(&s.Bs[nb][bk0 + 8][bn4], Bp1 + (size_t)k0 * N);
            cp_commit();
        }
#pragma unroll
        for (int ks = 0; ks < 2; ks++) {
            const int kk = ks * 8;
            unsigned a[2][4];
#pragma unroll
            for (int mt = 0; mt < 2; mt++) {
                int mr = m0 + mt * 16;
                a[mt][0] = f2tf(s.As[cur][mr + r][kk + c]);
                a[mt][1] = f2tf(s.As[cur][mr + r + 8][kk + c]);
                a[mt][2] = f2tf(s.As[cur][mr + r][kk + c + 4]);
                a[mt][3] = f2tf(s.As[cur][mr + r + 8][kk + c + 4]);
            }
#pragma unroll
            for (int nt = 0; nt < 8; nt++) {
                unsigned b0 = f2tf(s.Bs[cur][kk + c][n0 + nt * 8 + r]);
                unsigned b1 = f2tf(s.Bs[cur][kk + c + 4][n0 + nt * 8 + r]);
#pragma unroll
                for (int mt = 0; mt < 2; mt++)
                    MMA_TF32(acc[mt][nt], a[mt][0], a[mt][1], a[mt][2], a[mt][3], b0, b1);
            }
        }
        if (more) cp_wait<0>();
        __syncthreads();
    }
#pragma unroll
    for (int mt = 0; mt < 2; mt++) {
        int mr = bm + m0 + mt * 16 + r;
#pragma unroll
        for (int nt = 0; nt < 8; nt++) {
            int col = bn + n0 + nt * 8 + 2 * c;
            *(float2*)(C + (size_t)mr * N + col) =
                make_float2(acc[mt][nt][0], acc[mt][nt][1]);
            *(float2*)(C + (size_t)(mr + 8) * N + col) =
                make_float2(acc[mt][nt][2], acc[mt][nt][3]);
        }
    }
}

__global__ __launch_bounds__(256) void sgemm_tf32(
    const float* __restrict__ A, const float* __restrict__ B,
    float* __restrict__ C, int N, int K)
{
    __shared__ SmemTF32 s;
    gemm_tf32_core(A, B, C, N, K, blockIdx.y * 128, blockIdx.x * 128, s);
}

__global__ __launch_bounds__(256) void proj_tf32(
    const float* __restrict__ x,
    const float* __restrict__ Wq, const float* __restrict__ Wk,
    const float* __restrict__ Wv, const float* __restrict__ Wg)
{
    __shared__ SmemTF32 s;
    const int bx = blockIdx.x;
    const float* B; float* C; int N, bn;
    if (bx < 16)      { B = Wq; C = g_pq; N = 2048; bn = bx * 128; }
    else if (bx < 24) { B = Wk; C = g_pk; N = 1024; bn = (bx - 16) * 128; }
    else if (bx < 32) { B = Wv; C = g_pv; N = 1024; bn = (bx - 24) * 128; }
    else              { B = Wg; C = g_gp; N = 2048; bn = (bx - 32) * 128; }
    gemm_tf32_core(x, B, C, N, DMODEL, blockIdx.y * 128, bn, s);
}

// ------- gates as GEMM: x[1024,2048] @ [Wa|Wb|Wal][2048,48], K split 4 -------
__global__ __launch_bounds__(256) void gates_mm(
    const float* __restrict__ x, const float* __restrict__ Wa,
    const float* __restrict__ Wb, const float* __restrict__ Wal)
{
    __shared__ float xs[16][132];
    __shared__ float Ws[16][52];
    const int bm = blockIdx.x * 128;
    const int k0 = blockIdx.y * 512;
    const int tid = threadIdx.x;
    const int row = tid >> 1, kq = (tid & 1) * 8;
    const int wk = tid >> 4, wh = tid & 15;
    const int ty = tid >> 3, tx = tid & 7;

    float acc[4][6];
#pragma unroll
    for (int i = 0; i < 4; i++)
#pragma unroll
        for (int j = 0; j < 6; j++) acc[i][j] = 0.f;

    for (int kt = 0; kt < 512; kt += 16) {
        const int kb = k0 + kt;
        float4 v0 = *(const float4*)(x + (size_t)(bm + row) * DMODEL + kb + kq);
        float4 v1 = *(const float4*)(x + (size_t)(bm + row) * DMODEL + kb + kq + 4);
        xs[kq + 0][row] = v0.x; xs[kq + 1][row] = v0.y;
        xs[kq + 2][row] = v0.z; xs[kq + 3][row] = v0.w;
        xs[kq + 4][row] = v1.x; xs[kq + 5][row] = v1.y;
        xs[kq + 6][row] = v1.z; xs[kq + 7][row] = v1.w;
        Ws[wk][wh]      = Wa[(size_t)(kb + wk) * NHQ + wh];
        Ws[wk][16 + wh] = Wb[(size_t)(kb + wk) * NHQ + wh];
        Ws[wk][32 + wh] = Wal[(size_t)(kb + wk) * NHQ + wh];
        __syncthreads();
#pragma unroll
        for (int kk = 0; kk < 16; kk++) {
            float a[4], b[6];
#pragma unroll
            for (int i = 0; i < 4; i++) a[i] = xs[kk][ty * 4 + i];
#pragma unroll
            for (int j = 0; j < 6; j++) b[j] = Ws[kk][tx * 6 + j];
#pragma unroll
            for (int i = 0; i < 4; i++)
#pragma unroll
                for (int j = 0; j < 6; j++) acc[i][j] += a[i] * b[j];
        }
        __syncthreads();
    }
#pragma unroll
    for (int i = 0; i < 4; i++)
#pragma unroll
        for (int j = 0; j < 6; j++)
            g_gpart[blockIdx.y][bm + ty * 4 + i][tx * 6 + j] = acc[i][j];
}

__global__ void gates_ep(
    const float* __restrict__ A_log, const float* __restrict__ dt_bias,
    const float* __restrict__ bb, const float* __restrict__ bal)
{
    int idx = blockIdx.x * 256 + threadIdx.x;
    if (idx >= LSEQ * 48) return;
    int t = idx / 48, j = idx % 48;
    float s = g_gpart[0][t][j] + g_gpart[1][t][j]
            + g_gpart[2][t][j] + g_gpart[3][t][j];
    if (j < 16) {
        float z = s + dt_bias[j];
        float sp = (z > 20.f) ? z : log1pf(expf(z));
        g_glog[t * NHQ + j] = -expf(A_log[j]) * sp;
    } else if (j < 32) {
        int h = j - 16;
        g_beta[t * NHQ + h] = 1.f / (1.f + expf(-(s + bb[h])));
    } else {
        int h = j - 32;
        g_alpha[t * NHQ + h] = 1.f / (1.f + expf(-(s + bal[h])));
    }
}

// ---------------- causal depthwise conv(4) + silu ----------------
__global__ void conv_kernel(const float* __restrict__ in, const float* __restrict__ w,
                            float* __restrict__ out, int C, float scale)
{
    int idx = blockIdx.x * blockDim.x + threadIdx.x;
    if (idx >= LSEQ * C) return;
    int t = idx / C, c = idx % C;
    float s = 0.f;
#pragma unroll
    for (int j = 0; j < 4; j++) {
        int tj = t - 3 + j;
        if (tj >= 0) s += in[(size_t)tj * C + c] * w[c * 4 + j];
    }
    float y = s / (1.f + expf(-s));
    out[idx] = y * scale;
}

__global__ void convkv_kernel(const float* __restrict__ wk, const float* __restrict__ wv)
{
    int idx = blockIdx.x * 256 + threadIdx.x;
    const float* in; const float* w; float* out;
    int id2 = idx;
    if (idx >= LSEQ * 1024) { in = g_pv; w = wv; out = g_v; id2 -= LSEQ * 1024; }
    else                    { in = g_pk; w = wk; out = g_k; }
    int t = id2 >> 10, c = id2 & 1023;
    float s = 0.f;
#pragma unroll
    for (int j = 0; j < 4; j++) {
        int tj = t - 3 + j;
        if (tj >= 0) s += in[(size_t)tj * 1024 + c] * w[c * 4 + j];
    }
    out[id2] = s / (1.f + expf(-s));
}

// ---------------- per-chunk cumsum ----------------
__global__ void cs_kernel()
{
    int id = threadIdx.x;
    int h = id >> 4, n = id & 15;
    float s = 0.f;
    for (int c = 0; c < CLEN; c++) {
        s += g_glog[(n * CLEN + c) * NHQ + h];
        g_cs[(h * NCHUNK + n) * CLEN + c] = s;
    }
    g_G[h * NCHUNK + n] = s;
    g_dgv[h * NCHUNK + n] = expf(s);
}

// -------- dH / dB gram increments via tf32 mma --------
#define DB_PAD 132
#define DB_SMEM ((2 * 64 * DB_PAD + 64) * 4)

__global__ __launch_bounds__(256, 1) void dhb_tf32()
{
    extern __shared__ float sm[];
    float* ksf = sm;
    float* vsf = sm + 64 * DB_PAD;
    float* ws  = sm + 2 * 64 * DB_PAD;
    const int mat = blockIdx.x;
    const int h = mat >> 4, n = mat & 15, hk = h >> 1;
    const int tid = threadIdx.x;
    for (int i = tid; i < CLEN * DHEAD; i += 256) {
        int c = i >> 7, d = i & 127;
        int t = n * CLEN + c;
        ksf[c * DB_PAD + d] = g_k[t * 1024 + hk * DHEAD + d];
        vsf[c * DB_PAD + d] = g_v[t * 1024 + hk * DHEAD + d];
    }
    if (tid < CLEN) {
        float G = g_G[mat];
        float cs = g_cs[mat * CLEN + tid];
        ws[tid] = expf(G - cs) * g_beta[(n * CLEN + tid) * NHQ + h];
    }
    __syncthreads();

    const int warp = tid >> 5, lane = tid & 31;
    const int m0 = warp * 16;
    const int fr = lane >> 2, fc = lane & 3;

    float accH[16][4], accB[16][4];
#pragma unroll
    for (int nt = 0; nt < 16; nt++)
#pragma unroll
        for (int i = 0; i < 4; i++) { accH[nt][i] = 0.f; accB[nt][i] = 0.f; }

#pragma unroll 1
    for (int ks8 = 0; ks8 < 8; ks8++) {
        const int kk = ks8 * 8;
        float w0 = ws[kk + fc], w1 = ws[kk + fc + 4];
        unsigned a0 = f2tf(w0 * ksf[(kk + fc) * DB_PAD + m0 + fr]);
        unsigned a1 = f2tf(w0 * ksf[(kk + fc) * DB_PAD + m0 + fr + 8]);
        unsigned a2 = f2tf(w1 * ksf[(kk + fc + 4) * DB_PAD + m0 + fr]);
        unsigned a3 = f2tf(w1 * ksf[(kk + fc + 4) * DB_PAD + m0 + fr + 8]);
#pragma unroll
        for (int nt = 0; nt < 16; nt++) {
            int cn = nt * 8 + fr;
            unsigned bh0 = f2tf(ksf[(kk + fc) * DB_PAD + cn]);
            unsigned bh1 = f2tf(ksf[(kk + fc + 4) * DB_PAD + cn]);
            MMA_TF32(accH[nt], a0, a1, a2, a3, bh0, bh1);
            unsigned bv0 = f2tf(vsf[(kk + fc) * DB_PAD + cn]);
            unsigned bv1 = f2tf(vsf[(kk + fc + 4) * DB_PAD + cn]);
            MMA_TF32(accB[nt], a0, a1, a2, a3, bv0, bv1);
        }
    }
    size_t base = (size_t)mat * DHEAD * DHEAD;
#pragma unroll
    for (int nt = 0; nt < 16; nt++) {
        int col = nt * 8 + 2 * fc;
        size_t r0 = base + (size_t)(m0 + fr) * 128 + col;
        size_t r1 = base + (size_t)(m0 + fr + 8) * 128 + col;
        *(float2*)&g_dH[r0] = make_float2(accH[nt][0], accH[nt][1]);
        *(float2*)&g_dH[r1] = make_float2(accH[nt][2], accH[nt][3]);
        *(float2*)&g_dB[r0] = make_float2(accB[nt][0], accB[nt][1]);
        *(float2*)&g_dB[r1] = make_float2(accB[nt][2], accB[nt][3]);
    }
}

// ---------------- inter-chunk scan ----------------
__global__ void scan_kernel()
{
    int idx = blockIdx.x * blockDim.x + threadIdx.x;
    int h = idx >> 14;
    int rem = idx & 16383;
    float hc = 0.f, bc = 0.f;
    for (int n = 0; n < NCHUNK; n++) {
        size_t off = (size_t)(h * NCHUNK + n) * 16384 + rem;
        g_H0[off] = hc;
        g_B0[off] = bc;
        float g = g_dgv[h * NCHUNK + n];
        hc = g * hc + g_dH[off];
        bc = g * bc + g_dB[off];
    }
}

// ------- Chebyshev solve: tf32 mma matvec, d stored tf32-rounded -------
#define CH_APAD 132
#define CH_DPAD 136
#define CH_SMEM (128*CH_APAD*4 + 128*CH_DPAD*4)

__global__ __launch_bounds__(256, 1) void cheb_tf32()
{
    extern __shared__ char smemraw[];
    unsigned (*Ash)[CH_APAD] = (unsigned(*)[CH_APAD])smemraw;
    float (*dsh)[CH_DPAD] = (float(*)[CH_DPAD])(smemraw + 128 * CH_APAD * 4);
    __shared__ float red[128];
    __shared__ float s_lmax;

    const int mat = blockIdx.x;
    const int tid = threadIdx.x;
    const int warp = tid >> 5, lane = tid & 31;
    const int m0 = warp * 16;
    const int fr = lane >> 2, fc = lane & 3;
    const int ro = m0 + fr;
    const float* H0 = g_H0 + (size_t)mat * 16384;
    const float* B0p = g_B0 + (size_t)mat * 16384;

    for (int i = tid; i < 16384; i += 256) {
        int row = i >> 7, col = i & 127;
        float v = H0[i];
        if (row == col) { v += RIDGE_C; red[row] = v; }
        Ash[row][col] = f2tf(v);
    }
    __syncthreads();
    for (int s = 64; s > 0; s >>= 1) {
        if (tid < s) red[tid] += red[tid + s];
        __syncthreads();
    }
    if (tid == 0) s_lmax = red[0];
    __syncthreads();

    const float lmax = s_lmax;
    const float theta = (lmax + RIDGE_C) * 0.5f;
    const float delta = (lmax - RIDGE_C) * 0.5f;
    const float sigma1 = theta / delta;
    float rho = 1.f / sigma1;
    const float inv_theta = 1.f / theta;

    float r_[16][4], x_[16][4];
#pragma unroll
    for (int nt = 0; nt < 16; nt++) {
        int co = nt * 8 + 2 * fc;
        float2 b0 = *(const float2*)&B0p[ro * 128 + co];
        float2 b1 = *(const float2*)&B0p[(ro + 8) * 128 + co];
        r_[nt][0] = b0.x; r_[nt][1] = b0.y; r_[nt][2] = b1.x; r_[nt][3] = b1.y;
        x_[nt][0] = 0.f; x_[nt][1] = 0.f; x_[nt][2] = 0.f; x_[nt][3] = 0.f;
        *(float2*)&dsh[ro][co] = make_float2(
            __uint_as_float(f2tf(b0.x * inv_theta)),
            __uint_as_float(f2tf(b0.y * inv_theta)));
        *(float2*)&dsh[ro + 8][co] = make_float2(
            __uint_as_float(f2tf(b1.x * inv_theta)),
            __uint_as_float(f2tf(b1.y * inv_theta)));
    }
    __syncthreads();

    for (int it = 0; it < NITER; it++) {
        float acc[16][4];
#pragma unroll
        for (int nt = 0; nt < 16; nt++) {
            acc[nt][0] = 0.f; acc[nt][1] = 0.f; acc[nt][2] = 0.f; acc[nt][3] = 0.f;
        }
#pragma unroll 1
        for (int ks = 0; ks < 16; ks++) {
            const int kk = ks * 8;
            unsigned a0 = Ash[m0 + fr][kk + fc];
            unsigned a1 = Ash[m0 + fr + 8][kk + fc];
            unsigned a2 = Ash[m0 + fr][kk + fc + 4];
            unsigned a3 = Ash[m0 + fr + 8][kk + fc + 4];
#pragma unroll
            for (int nt = 0; nt < 16; nt++) {
                unsigned b0 = __float_as_uint(dsh[kk + fc][nt * 8 + fr]);
                unsigned b1 = __float_as_uint(dsh[kk + fc + 4][nt * 8 + fr]);
                MMA_TF32(acc[nt], a0, a1, a2, a3, b0, b1);
            }
        }
        __syncthreads();

        float rho_n = 1.f / (2.f * sigma1 - rho);
        float c1 = rho_n * rho;
        float c2 = 2.f * rho_n / delta;
#pragma unroll
        for (int nt = 0; nt < 16; nt++) {
            int co = nt * 8 + 2 * fc;
            float2 d0 = *(float2*)&dsh[ro][co];
            float2 d1 = *(float2*)&dsh[ro + 8][co];
            x_[nt][0] += d0.x; x_[nt][1] += d0.y;
            x_[nt][2] += d1.x; x_[nt][3] += d1.y;
            r_[nt][0] -= acc[nt][0]; r_[nt][1] -= acc[nt][1];
            r_[nt][2] -= acc[nt][2]; r_[nt][3] -= acc[nt][3];
            d0.x = __uint_as_float(f2tf(c1 * d0.x + c2 * r_[nt][0]));
            d0.y = __uint_as_float(f2tf(c1 * d0.y + c2 * r_[nt][1]));
            d1.x = __uint_as_float(f2tf(c1 * d1.x + c2 * r_[nt][2]));
            d1.y = __uint_as_float(f2tf(c1 * d1.y + c2 * r_[nt][3]));
            *(float2*)&dsh[ro][co]     = d0;
            *(float2*)&dsh[ro + 8][co] = d1;
        }
        rho = rho_n;
        __syncthreads();
    }

    float* Xp = g_X + (size_t)mat * 16384;
#pragma unroll
    for (int nt = 0; nt < 16; nt++) {
        int co = nt * 8 + 2 * fc;
        *(float2*)&Xp[ro * 128 + co]       = make_float2(x_[nt][0], x_[nt][1]);
        *(float2*)&Xp[(ro + 8) * 128 + co] = make_float2(x_[nt][2], x_[nt][3]);
    }
}

// ---- o: scores + inter + intra via tf32 mma, alpha*v, gated RMSNorm ----
#define OP 132
#define O_SMEM ((3 * 64 * OP + 128 * OP + 64 * OP) * 4)

__global__ __launch_bounds__(256, 1) void o_tf32(const float* __restrict__ norm_w)
{
    extern __shared__ float sm[];
    float* qs = sm;
    float* ks = sm + 64 * OP;
    float* vs = sm + 2 * 64 * OP;
    float* Xs = sm + 3 * 64 * OP;
    float* Os = sm + 3 * 64 * OP + 128 * OP;
    __shared__ float csh[CLEN], bsh[CLEN], ash[CLEN], expc[CLEN];
    const int mat = blockIdx.x;
    const int h = mat >> 4, n = mat & 15, hk = h >> 1;
    const int tid = threadIdx.x;
    const int warp = tid >> 5, lane = tid & 31;
    const int fr = lane >> 2, fc = lane & 3;

    for (int i = tid; i < CLEN * DHEAD; i += 256) {
        int c = i >> 7, d = i & 127;
        int t = n * CLEN + c;
        qs[c * OP + d] = g_q[t * 2048 + h * DHEAD + d];
        ks[c * OP + d] = g_k[t * 1024 + hk * DHEAD + d];
        vs[c * OP + d] = g_v[t * 1024 + hk * DHEAD + d];
    }
    for (int i = tid; i < 16384; i += 256) {
        int row = i >> 7, col = i & 127;
        Xs[row * OP + col] = g_X[(size_t)mat * 16384 + i];
    }
    if (tid < CLEN) {
        float cv = g_cs[mat * CLEN + tid];
        csh[tid] = cv;
        expc[tid] = expf(cv);
        int t = n * CLEN + tid;
        bsh[tid] = g_beta[t * NHQ + h];
        ash[tid] = g_alpha[t * NHQ + h];
    }
    __syncthreads();

    {
        const int m0 = (warp & 3) * 16, n0 = (warp >> 2) * 32;
        float sc[4][4];
#pragma unroll
        for (int nt = 0; nt < 4; nt++)
#pragma unroll
            for (int i = 0; i < 4; i++) sc[nt][i] = 0.f;
#pragma unroll 1
        for (int ks8 = 0; ks8 < 16; ks8++) {
            const int kk = ks8 * 8;
            unsigned a0 = f2tf(qs[(m0 + fr) * OP + kk + fc]);
            unsigned a1 = f2tf(qs[(m0 + fr + 8) * OP + kk + fc]);
            unsigned a2 = f2tf(qs[(m0 + fr) * OP + kk + fc + 4]);
            unsigned a3 = f2tf(qs[(m0 + fr + 8) * OP + kk + fc + 4]);
#pragma unroll
            for (int nt = 0; nt < 4; nt++) {
                int j = n0 + nt * 8 + fr;
                unsigned b0 = f2tf(ks[j * OP + kk + fc]);
                unsigned b1 = f2tf(ks[j * OP + kk + fc + 4]);
                MMA_TF32(sc[nt], a0, a1, a2, a3, b0, b1);
            }
        }
#pragma unroll
        for (int nt = 0; nt < 4; nt++) {
            int j0 = n0 + nt * 8 + 2 * fc;
            int c0 = m0 + fr, c1 = m0 + fr + 8;
#pragma unroll
            for (int e = 0; e < 4; e++) {
                int c = (e < 2) ? c0 : c1;
                int j = j0 + (e & 1);
                float v = 0.f;
                if (j <= c) v = sc[nt][e] * expf(csh[c] - csh[j]) * bsh[j];
                Os[c * OP + j] = v;
            }
        }
    }
    __syncthreads();

    {
        const int m0 = (warp & 3) * 16, n0 = (warp >> 2) * 64;
        float oa[8][4];
#pragma unroll
        for (int nt = 0; nt < 8; nt++)
#pragma unroll
            for (int i = 0; i < 4; i++) oa[nt][i] = 0.f;
        float e0 = expc[m0 + fr], e1 = expc[m0 + fr + 8];
#pragma unroll 1
        for (int ks8 = 0; ks8 < 16; ks8++) {
            const int kk = ks8 * 8;
            unsigned a0 = f2tf(qs[(m0 + fr) * OP + kk + fc] * e0);
            unsigned a1 = f2tf(qs[(m0 + fr + 8) * OP + kk + fc] * e1);
            unsigned a2 = f2tf(qs[(m0 + fr) * OP + kk + fc + 4] * e0);
            unsigned a3 = f2tf(qs[(m0 + fr + 8) * OP + kk + fc + 4] * e1);
#pragma unroll
            for (int nt = 0; nt < 8; nt++) {
                int cn = n0 + nt * 8 + fr;
                unsigned b0 = f2tf(Xs[(kk + fc) * OP + cn]);
                unsigned b1 = f2tf(Xs[(kk + fc + 4) * OP + cn]);
                MMA_TF32(oa[nt], a0, a1, a2, a3, b0, b1);
            }
        }
#pragma unroll 1
        for (int ks8 = 0; ks8 < 8; ks8++) {
            const int kk = ks8 * 8;
            unsigned a0 = f2tf(Os[(m0 + fr) * OP + kk + fc]);
            unsigned a1 = f2tf(Os[(m0 + fr + 8) * OP + kk + fc]);
            unsigned a2 = f2tf(Os[(m0 + fr) * OP + kk + fc + 4]);
            unsigned a3 = f2tf(Os[(m0 + fr + 8) * OP + kk + fc + 4]);
#pragma unroll
            for (int nt = 0; nt < 8; nt++) {
                int cn = n0 + nt * 8 + fr;
                unsigned b0 = f2tf(vs[(kk + fc) * OP + cn]);
                unsigned b1 = f2tf(vs[(kk + fc + 4) * OP + cn]);
                MMA_TF32(oa[nt], a0, a1, a2, a3, b0, b1);
            }
        }
        __syncthreads();
        int c0 = m0 + fr, c1 = m0 + fr + 8;
        float al0 = ash[c0], al1 = ash[c1];
#pragma unroll
        for (int nt = 0; nt < 8; nt++) {
            int col = n0 + nt * 8 + 2 * fc;
            Os[c0 * OP + col]     = oa[nt][0] + al0 * vs[c0 * OP + col];
            Os[c0 * OP + col + 1] = oa[nt][1] + al0 * vs[c0 * OP + col + 1];
            Os[c1 * OP + col]     = oa[nt][2] + al1 * vs[c1 * OP + col];
            Os[c1 * OP + col + 1] = oa[nt][3] + al1 * vs[c1 * OP + col + 1];
        }
    }
    __syncthreads();

    {
        const int ty = warp, tx = lane;
        const int f0 = tx * 4;
        float4 nw = *(const float4*)(norm_w + f0);
#pragma unroll
        for (int i = 0; i < 8; i++) {
            int c = ty * 8 + i;
            int t = n * CLEN + c;
            float4 ov = *(const float4*)&Os[c * OP + f0];
            float ss = ov.x * ov.x + ov.y * ov.y + ov.z * ov.z + ov.w * ov.w;
#pragma unroll
            for (int off = 16; off > 0; off >>= 1)
                ss += __shfl_xor_sync(0xFFFFFFFFu, ss, off);
            float rms = rsqrtf(ss * (1.f / 128.f) + 1e-6f);
            float4 gw = *(const float4*)(&g_gp[(size_t)t * 2048 + h * 128 + f0]);
            float4 o;
            o.x = ov.x * rms * nw.x * (gw.x / (1.f + expf(-gw.x)));
            o.y = ov.y * rms * nw.y * (gw.y / (1.f + expf(-gw.y)));
            o.z = ov.z * rms * nw.z * (gw.z / (1.f + expf(-gw.z)));
            o.w = ov.w * rms * nw.w * (gw.w / (1.f + expf(-gw.w)));
            *(float4*)&g_on[(size_t)t * 2048 + h * DHEAD + f0] = o;
        }
    }
}

// ---------------- launch ----------------
extern "C" void kernel_launch(void* const* d_in, const int* in_sizes, int n_in,
                              void* d_out, int out_size)
{
    const float* x      = (const float*)d_in[0];
    const float* Wq     = (const float*)d_in[1];
    const float* Wk     = (const float*)d_in[2];
    const float* Wv     = (const float*)d_in[3];
    const float* conv_q = (const float*)d_in[4];
    const float* conv_k = (const float*)d_in[5];
    const float* conv_v = (const float*)d_in[6];
    const float* Wa     = (const float*)d_in[7];
    const float* A_log  = (const float*)d_in[8];
    const float* dt_b   = (const float*)d_in[9];
    const float* Wb     = (const float*)d_in[10];
    const float* bb     = (const float*)d_in[11];
    const float* Wal    = (const float*)d_in[12];
    const float* bal    = (const float*)d_in[13];
    const float* Wg     = (const float*)d_in[14];
    const float* norm_w = (const float*)d_in[15];
    const float* Wo     = (const float*)d_in[16];
    float* out = (float*)d_out;

    float *pq, *qb, *on;
    cudaGetSymbolAddress((void**)&pq, g_pq);
    cudaGetSymbolAddress((void**)&qb, g_q);
    cudaGetSymbolAddress((void**)&on, g_on);

    cudaFuncSetAttribute(dhb_tf32, cudaFuncAttributeMaxDynamicSharedMemorySize, DB_SMEM);
    cudaFuncSetAttribute(cheb_tf32, cudaFuncAttributeMaxDynamicSharedMemorySize, CH_SMEM);
    cudaFuncSetAttribute(o_tf32, cudaFuncAttributeMaxDynamicSharedMemorySize, O_SMEM);

    gates_mm<<<dim3(8, 4), 256>>>(x, Wa, Wb, Wal);            // 0
    gates_ep<<<192, 256>>>(A_log, dt_b, bb, bal);             // 1
    cs_kernel<<<1, 256>>>();                                  // 2
    proj_tf32<<<dim3(48, 8), 256>>>(x, Wq, Wk, Wv, Wg);       // 3  <- ncu capture (idx 3 observed last round)
    convkv_kernel<<<8192, 256>>>(conv_k, conv_v);             // 4
    dhb_tf32<<<256, 256, DB_SMEM>>>();                        // 5
    conv_kernel<<<8192, 256>>>(pq, conv_q, qb, 2048, 0.08838834764831843f); // 6
    scan_kernel<<<1024, 256>>>();                             // 7
    cheb_tf32<<<256, 256, CH_SMEM>>>();                       // 8
    o_tf32<<<256, 256, O_SMEM>>>(norm_w);                     // 9
    sgemm_tf32<<<dim3(16, 8), 256>>>(on, Wo, out, 2048, 2048);// 10
}